// round 4
// baseline (speedup 1.0000x reference)
#include <cuda_runtime.h>
#include <math.h>

// Problem constants
#define Bc   8
#define Hh   8
#define NT   1024    // N*T query rows per batch
#define NKT  2048    // (N+NC)*T key rows per batch
#define Cdim 512
#define Dh   64

// ---------------- scratch (device globals; no allocation allowed) ----------
__device__ float g_q[(size_t)Bc * Hh * NT  * Dh];   // [B,H,NT,Dh]
__device__ float g_k[(size_t)Bc * Hh * NKT * Dh];   // [B,H,NKT,Dh]
__device__ float g_v[(size_t)Bc * Hh * NKT * Dh];   // [B,H,NKT,Dh]
__device__ float g_y[(size_t)Bc * NT * Cdim];       // [B,NT,C] attention output
__device__ int   g_maskmode;                        // 0=uint8, 1=int32, 2=float32

// ---------------- mask dtype detection -------------------------------------
// Serialized bool masks may arrive as uint8 (1B), int32, or float32. Detect by
// byte pattern over the first 8KB:
//  - float32 1.0f has byte3 == 0x3f        -> mode 2
//  - else any nonzero byte at idx%4 != 0   -> mode 0 (uint8 random 0/1)
//  - else                                  -> mode 1 (int32 0/1, little-endian)
__global__ void detect_mask_mode(const unsigned char* __restrict__ m) {
    bool hi = false, f3 = false;
    for (int i = threadIdx.x; i < 8192; i += blockDim.x) {
        unsigned char v = m[i];
        int p = i & 3;
        if (p == 3 && v == 0x3f) f3 = true;
        if (p != 0 && v != 0)    hi = true;
    }
    int a3 = __syncthreads_or(f3 ? 1 : 0);
    int ah = __syncthreads_or(hi ? 1 : 0);
    if (threadIdx.x == 0)
        g_maskmode = a3 ? 2 : (ah ? 0 : 1);
}

__device__ __forceinline__ int mask_at(const void* mp, size_t idx, int mode) {
    if (mode == 0) return ((const unsigned char*)mp)[idx] != 0;
    if (mode == 1) return ((const int*)mp)[idx] != 0;
    return ((const float*)mp)[idx] != 0.0f;
}

// ---------------- GEMM: Y = A @ W^T ----------------------------------------
// A rows gathered from x (modeIn=0) or concat(x,c) (modeIn=1).
// Output: modeOut=0 -> head-split [B,H,Mrows,Dh]; modeOut=1 -> flat [rows, C].
#define GBM 128
#define GBN 128
#define GBK 16
#define GPAD 132   // padded row stride (floats) -> <=2-way STS conflicts, 16B aligned

__global__ __launch_bounds__(256) void gemm_kernel(
    const float* __restrict__ A0, const float* __restrict__ A1,
    const float* __restrict__ W, float* __restrict__ outp,
    int MrowsPerB, int modeIn, int modeOut)
{
    __shared__ float As[GBK][GPAD];
    __shared__ float Bs[GBK][GPAD];

    const int tid = threadIdx.x;
    const int m0  = blockIdx.y * GBM;
    const int n0  = blockIdx.x * GBN;
    const int lr  = tid >> 2;          // 0..63
    const int lc  = (tid & 3) << 2;    // 0,4,8,12

    const float* arow[2];
    const float* brow[2];
#pragma unroll
    for (int p = 0; p < 2; p++) {
        int gm = m0 + lr + p * 64;
        int b  = gm / MrowsPerB;
        int m  = gm - b * MrowsPerB;
        if (modeIn == 0 || m < NT)
            arow[p] = A0 + ((size_t)b * NT + m) * Cdim;
        else
            arow[p] = A1 + ((size_t)b * NT + (m - NT)) * Cdim;
        brow[p] = W + (size_t)(n0 + lr + p * 64) * Cdim;
    }

    float acc[8][8];
#pragma unroll
    for (int i = 0; i < 8; i++)
#pragma unroll
        for (int j = 0; j < 8; j++) acc[i][j] = 0.f;

    const int ty = tid >> 4;     // 0..15
    const int tx = tid & 15;     // 0..15

    for (int k0 = 0; k0 < Cdim; k0 += GBK) {
#pragma unroll
        for (int p = 0; p < 2; p++) {
            float4 a  = *(const float4*)(arow[p] + k0 + lc);
            As[lc + 0][lr + p * 64] = a.x;
            As[lc + 1][lr + p * 64] = a.y;
            As[lc + 2][lr + p * 64] = a.z;
            As[lc + 3][lr + p * 64] = a.w;
            float4 bv = *(const float4*)(brow[p] + k0 + lc);
            Bs[lc + 0][lr + p * 64] = bv.x;
            Bs[lc + 1][lr + p * 64] = bv.y;
            Bs[lc + 2][lr + p * 64] = bv.z;
            Bs[lc + 3][lr + p * 64] = bv.w;
        }
        __syncthreads();
#pragma unroll
        for (int kk = 0; kk < GBK; kk++) {
            float4 ta0 = *(const float4*)&As[kk][ty * 8];
            float4 ta1 = *(const float4*)&As[kk][ty * 8 + 4];
            float4 tb0 = *(const float4*)&Bs[kk][tx * 8];
            float4 tb1 = *(const float4*)&Bs[kk][tx * 8 + 4];
            float a[8]  = {ta0.x, ta0.y, ta0.z, ta0.w, ta1.x, ta1.y, ta1.z, ta1.w};
            float bb[8] = {tb0.x, tb0.y, tb0.z, tb0.w, tb1.x, tb1.y, tb1.z, tb1.w};
#pragma unroll
            for (int i = 0; i < 8; i++)
#pragma unroll
                for (int j = 0; j < 8; j++)
                    acc[i][j] = fmaf(a[i], bb[j], acc[i][j]);
        }
        __syncthreads();
    }

    const int gn0 = n0 + tx * 8;
#pragma unroll
    for (int i = 0; i < 8; i++) {
        int gm = m0 + ty * 8 + i;
        float* op;
        if (modeOut == 0) {
            int b  = gm / MrowsPerB;
            int m  = gm - b * MrowsPerB;
            int h  = gn0 >> 6;
            int d0 = gn0 & 63;
            op = outp + (((size_t)(b * Hh + h)) * MrowsPerB + m) * Dh + d0;
        } else {
            op = outp + (size_t)gm * Cdim + gn0;
        }
        *(float4*)op       = make_float4(acc[i][0], acc[i][1], acc[i][2], acc[i][3]);
        *(float4*)(op + 4) = make_float4(acc[i][4], acc[i][5], acc[i][6], acc[i][7]);
    }
}

// ---------------- Flash attention ------------------------------------------
// grid (NT/64, H, B), 256 threads. 64 query rows per block, Dh=64.
// Online softmax; masked scores = -1e30 (NaN-free recurrence).
#define TPAD 68
#define ATT_SMEM_FLOATS (4 * 64 * TPAD + 128)
#define ATT_SMEM_BYTES  (ATT_SMEM_FLOATS * 4)

__global__ __launch_bounds__(256) void attn_kernel(
    const float* __restrict__ qg, const float* __restrict__ kg,
    const float* __restrict__ vg, const void* __restrict__ maskp,
    float* __restrict__ yg)
{
    extern __shared__ float sm[];
    float* Qs   = sm;                 // [64][TPAD]
    float* Ks   = Qs + 64 * TPAD;
    float* Vs   = Ks + 64 * TPAD;
    float* Ps   = Vs + 64 * TPAD;
    float* mrow = Ps + 64 * TPAD;     // [64]
    float* lrow = mrow + 64;          // [64]

    const int tid = threadIdx.x;
    const int b = blockIdx.z, h = blockIdx.y, qt = blockIdx.x;
    const int ty = tid >> 4, tx = tid & 15;
    const int rq = ty * 4, ck = tx * 4;
    const int mode = g_maskmode;

    // load Q tile (coalesced float4)
    const float* qbase = qg + (((size_t)(b * Hh + h)) * NT + qt * 64) * Dh;
#pragma unroll
    for (int i = 0; i < 4; i++) {
        int e = tid + i * 256;
        int r = e >> 4, c4 = (e & 15) << 2;
        *(float4*)&Qs[r * TPAD + c4] = *(const float4*)(qbase + r * Dh + c4);
    }
    if (tid < 64) { mrow[tid] = -1e30f; lrow[tid] = 0.f; }

    float acc[4][4];
#pragma unroll
    for (int i = 0; i < 4; i++)
#pragma unroll
        for (int j = 0; j < 4; j++) acc[i][j] = 0.f;

    const float* kbase = kg + ((size_t)(b * Hh + h)) * NKT * Dh;
    const float* vbase = vg + ((size_t)(b * Hh + h)) * NKT * Dh;
    const size_t mbase0 = ((size_t)b * NT + (size_t)qt * 64) * NKT;

    for (int kt = 0; kt < NKT / 64; kt++) {
        __syncthreads();   // previous iteration done with Ks/Vs/Ps
#pragma unroll
        for (int i = 0; i < 4; i++) {
            int e = tid + i * 256;
            int r = e >> 4, c4 = (e & 15) << 2;
            *(float4*)&Ks[r * TPAD + c4] = *(const float4*)(kbase + (size_t)(kt * 64 + r) * Dh + c4);
            *(float4*)&Vs[r * TPAD + c4] = *(const float4*)(vbase + (size_t)(kt * 64 + r) * Dh + c4);
        }
        __syncthreads();

        // S = Q K^T tile (4x4 per thread, vectorized over d)
        float s[4][4];
#pragma unroll
        for (int i = 0; i < 4; i++)
#pragma unroll
            for (int j = 0; j < 4; j++) s[i][j] = 0.f;

#pragma unroll
        for (int d4 = 0; d4 < Dh; d4 += 4) {
            float4 qv[4], kv[4];
#pragma unroll
            for (int i = 0; i < 4; i++) qv[i] = *(const float4*)&Qs[(rq + i) * TPAD + d4];
#pragma unroll
            for (int j = 0; j < 4; j++) kv[j] = *(const float4*)&Ks[(ck + j) * TPAD + d4];
#pragma unroll
            for (int i = 0; i < 4; i++)
#pragma unroll
                for (int j = 0; j < 4; j++)
                    s[i][j] += qv[i].x * kv[j].x + qv[i].y * kv[j].y +
                               qv[i].z * kv[j].z + qv[i].w * kv[j].w;
        }

        // mask + scale + online softmax update
#pragma unroll
        for (int i = 0; i < 4; i++) {
            size_t moff = mbase0 + (size_t)(rq + i) * NKT + (size_t)kt * 64 + ck;
            float sv[4];
#pragma unroll
            for (int j = 0; j < 4; j++)
                sv[j] = mask_at(maskp, moff + j, mode) ? -1e30f : s[i][j] * 0.125f;

            float rm = fmaxf(fmaxf(sv[0], sv[1]), fmaxf(sv[2], sv[3]));
            rm = fmaxf(rm, __shfl_xor_sync(0xffffffffu, rm, 1));
            rm = fmaxf(rm, __shfl_xor_sync(0xffffffffu, rm, 2));
            rm = fmaxf(rm, __shfl_xor_sync(0xffffffffu, rm, 4));
            rm = fmaxf(rm, __shfl_xor_sync(0xffffffffu, rm, 8));

            float mold = mrow[rq + i];
            float mnew = fmaxf(mold, rm);
            float corr = __expf(mold - mnew);

            float p0 = __expf(sv[0] - mnew);
            float p1 = __expf(sv[1] - mnew);
            float p2 = __expf(sv[2] - mnew);
            float p3 = __expf(sv[3] - mnew);
            *(float4*)&Ps[(rq + i) * TPAD + ck] = make_float4(p0, p1, p2, p3);
            float rs = p0 + p1 + p2 + p3;
            rs += __shfl_xor_sync(0xffffffffu, rs, 1);
            rs += __shfl_xor_sync(0xffffffffu, rs, 2);
            rs += __shfl_xor_sync(0xffffffffu, rs, 4);
            rs += __shfl_xor_sync(0xffffffffu, rs, 8);

#pragma unroll
            for (int j = 0; j < 4; j++) acc[i][j] *= corr;
            if (tx == 0) {
                mrow[rq + i] = mnew;
                lrow[rq + i] = lrow[rq + i] * corr + rs;
            }
        }
        __syncthreads();   // Ps complete, mrow/lrow updated

        // acc += P V (vectorized over kc)
#pragma unroll
        for (int kc0 = 0; kc0 < 64; kc0 += 4) {
            float4 vv[4];
#pragma unroll
            for (int u = 0; u < 4; u++) vv[u] = *(const float4*)&Vs[(kc0 + u) * TPAD + ck];
#pragma unroll
            for (int i = 0; i < 4; i++) {
                float4 pv = *(const float4*)&Ps[(rq + i) * TPAD + kc0];
                acc[i][0] += pv.x * vv[0].x + pv.y * vv[1].x + pv.z * vv[2].x + pv.w * vv[3].x;
                acc[i][1] += pv.x * vv[0].y + pv.y * vv[1].y + pv.z * vv[2].y + pv.w * vv[3].y;
                acc[i][2] += pv.x * vv[0].z + pv.y * vv[1].z + pv.z * vv[2].z + pv.w * vv[3].z;
                acc[i][3] += pv.x * vv[0].w + pv.y * vv[1].w + pv.z * vv[2].w + pv.w * vv[3].w;
            }
        }
    }

    // epilogue: normalize and write y in [B, NT, C] layout (C = h*Dh + d)
#pragma unroll
    for (int i = 0; i < 4; i++) {
        float l = lrow[rq + i];
        float linv = (l > 0.f) ? 1.f / l : 0.f;
        float* yo = yg + ((size_t)b * NT + (size_t)qt * 64 + rq + i) * Cdim + h * Dh + ck;
        *(float4*)yo = make_float4(acc[i][0] * linv, acc[i][1] * linv,
                                   acc[i][2] * linv, acc[i][3] * linv);
    }
}

// ---------------- launch ----------------------------------------------------
extern "C" void kernel_launch(void* const* d_in, const int* in_sizes, int n_in,
                              void* d_out, int out_size)
{
    const float* x  = (const float*)d_in[0];
    const float* c  = (const float*)d_in[1];
    const void*  mk = d_in[2];
    const float* Wq = (const float*)d_in[3];
    const float* Wk = (const float*)d_in[4];
    const float* Wv = (const float*)d_in[5];
    const float* Wp = (const float*)d_in[6];
    float* out = (float*)d_out;

    float *qp, *kp, *vp, *yp;
    cudaGetSymbolAddress((void**)&qp, g_q);
    cudaGetSymbolAddress((void**)&kp, g_k);
    cudaGetSymbolAddress((void**)&vp, g_v);
    cudaGetSymbolAddress((void**)&yp, g_y);

    cudaFuncSetAttribute(attn_kernel, cudaFuncAttributeMaxDynamicSharedMemorySize,
                         ATT_SMEM_BYTES);

    detect_mask_mode<<<1, 256>>>((const unsigned char*)mk);

    // Q = x @ Wq^T  -> [B,H,NT,Dh]
    gemm_kernel<<<dim3(Cdim / GBN, Bc * NT / GBM), 256>>>(x, nullptr, Wq, qp, NT, 0, 0);
    // K,V = concat(x,c) @ W^T -> [B,H,NKT,Dh]
    gemm_kernel<<<dim3(Cdim / GBN, Bc * NKT / GBM), 256>>>(x, c, Wk, kp, NKT, 1, 0);
    gemm_kernel<<<dim3(Cdim / GBN, Bc * NKT / GBM), 256>>>(x, c, Wv, vp, NKT, 1, 0);

    // attention -> g_y [B,NT,C]
    attn_kernel<<<dim3(NT / 64, Hh, Bc), 256, ATT_SMEM_BYTES>>>(qp, kp, vp, mk, yp);

    // out = y @ Wp^T -> [B,NT,C] (== [B,N,T,C])
    gemm_kernel<<<dim3(Cdim / GBN, Bc * NT / GBM), 256>>>(yp, nullptr, Wp, out, NT, 0, 1);
}

// round 5
// speedup vs baseline: 2.9093x; 2.9093x over previous
#include <cuda_runtime.h>
#include <cuda_fp16.h>
#include <stdint.h>

#define Bc   8
#define Hh   8
#define NT   1024
#define NKT  2048
#define Cdim 512
#define Dh   64

// ---------------- scratch ----------------------------------------------------
__device__ float g_q[(size_t)Bc * Hh * NT  * Dh];   // [B,H,NT,Dh]
__device__ float g_k[(size_t)Bc * Hh * NKT * Dh];   // [B,H,NKT,Dh]
__device__ float g_v[(size_t)Bc * Hh * NKT * Dh];   // [B,H,NKT,Dh]
__device__ float g_y[(size_t)Bc * NT * Cdim];       // [B,NT,C]
__device__ int   g_maskmode;                        // 0=uint8, 1=int32, 2=float32

// ---------------- mask dtype detection --------------------------------------
__global__ void detect_mask_mode(const unsigned char* __restrict__ m) {
    bool hi = false, f3 = false;
    for (int i = threadIdx.x; i < 8192; i += blockDim.x) {
        unsigned char v = m[i];
        int p = i & 3;
        if (p == 3 && v == 0x3f) f3 = true;
        if (p != 0 && v != 0)    hi = true;
    }
    int a3 = __syncthreads_or(f3 ? 1 : 0);
    int ah = __syncthreads_or(hi ? 1 : 0);
    if (threadIdx.x == 0) g_maskmode = a3 ? 2 : (ah ? 0 : 1);
}

// ---------------- mma / ldmatrix helpers -------------------------------------
__device__ __forceinline__ uint32_t smaddr(const void* p) {
    return (uint32_t)__cvta_generic_to_shared(p);
}
__device__ __forceinline__ void ldmx4(uint32_t a, uint32_t* r) {
    asm volatile("ldmatrix.sync.aligned.m8n8.x4.shared.b16 {%0,%1,%2,%3}, [%4];"
                 : "=r"(r[0]), "=r"(r[1]), "=r"(r[2]), "=r"(r[3]) : "r"(a));
}
__device__ __forceinline__ void ldmx2(uint32_t a, uint32_t* r) {
    asm volatile("ldmatrix.sync.aligned.m8n8.x2.shared.b16 {%0,%1}, [%2];"
                 : "=r"(r[0]), "=r"(r[1]) : "r"(a));
}
__device__ __forceinline__ void ldmx2t(uint32_t a, uint32_t* r) {
    asm volatile("ldmatrix.sync.aligned.m8n8.x2.trans.shared.b16 {%0,%1}, [%2];"
                 : "=r"(r[0]), "=r"(r[1]) : "r"(a));
}
__device__ __forceinline__ void mma16816(float* c, const uint32_t* a, const uint32_t* b) {
    asm volatile("mma.sync.aligned.m16n8k16.row.col.f32.f16.f16.f32 "
                 "{%0,%1,%2,%3},{%4,%5,%6,%7},{%8,%9},{%0,%1,%2,%3};"
                 : "+f"(c[0]), "+f"(c[1]), "+f"(c[2]), "+f"(c[3])
                 : "r"(a[0]), "r"(a[1]), "r"(a[2]), "r"(a[3]), "r"(b[0]), "r"(b[1]));
}

// split a float4 into hi/lo fp16 pairs, store 4 contiguous halves in each buffer
__device__ __forceinline__ void split_store(__half* hb, __half* lb, int idx, float4 v) {
    __half hx = __float2half_rn(v.x), hy = __float2half_rn(v.y);
    __half hz = __float2half_rn(v.z), hw = __float2half_rn(v.w);
    *(__half2*)(hb + idx)     = __halves2half2(hx, hy);
    *(__half2*)(hb + idx + 2) = __halves2half2(hz, hw);
    *(__half2*)(lb + idx)     = __halves2half2(__float2half_rn(v.x - __half2float(hx)),
                                               __float2half_rn(v.y - __half2float(hy)));
    *(__half2*)(lb + idx + 2) = __halves2half2(__float2half_rn(v.z - __half2float(hz)),
                                               __float2half_rn(v.w - __half2float(hw)));
}

// ---------------- GEMM: Y = A @ W^T (split-fp16, 3x mma) ---------------------
// block 128x128, K-tile 32, 8 warps (2x4), warp tile 64x32.
// modeIn: 0 -> rows from A0; 1 -> rows from concat(A0,A1) per batch.
// modeOut: 0 -> head-split [B,H,M,Dh]; 1 -> flat [rows,C].
#define GKT 32
#define GSH 40   // smem stride in halves (80B: conflict-free ldmatrix, 2-way STS max)

__global__ __launch_bounds__(256) void gemm_mma(
    const float* __restrict__ A0, const float* __restrict__ A1,
    const float* __restrict__ W,  float* __restrict__ outp,
    int MrowsPerB, int modeIn, int modeOut)
{
    __shared__ __half Ash[128 * GSH], Asl[128 * GSH];
    __shared__ __half Bsh[128 * GSH], Bsl[128 * GSH];

    const int tid = threadIdx.x, lane = tid & 31, w = tid >> 5;
    const int wm = w >> 2, wn = w & 3;
    const int m0 = blockIdx.y * 128, n0 = blockIdx.x * 128;
    const int rb = tid >> 3, c4 = (tid & 7) * 4;

    const float* ar[4]; const float* br[4];
#pragma unroll
    for (int i = 0; i < 4; i++) {
        int r  = rb + i * 32;
        int gm = m0 + r;
        int bb = gm / MrowsPerB, mm = gm - bb * MrowsPerB;
        ar[i] = (modeIn == 0 || mm < NT)
              ? (A0 + ((size_t)bb * NT + mm) * Cdim)
              : (A1 + ((size_t)bb * NT + (mm - NT)) * Cdim);
        br[i] = W + (size_t)(n0 + r) * Cdim;
    }

    float acc[4][4][4];
#pragma unroll
    for (int a = 0; a < 4; a++)
#pragma unroll
        for (int b2 = 0; b2 < 4; b2++)
#pragma unroll
            for (int q = 0; q < 4; q++) acc[a][b2][q] = 0.f;

    const int arl = wm * 64 + (lane & 15);     // A ldmatrix row
    const int acs = (lane >> 4) * 8;           // A col select (halves)
    const int brl = wn * 32 + (lane & 7);      // B ldmatrix row
    const int bcs = ((lane >> 3) & 1) * 8;

    for (int k0 = 0; k0 < Cdim; k0 += GKT) {
        __syncthreads();
#pragma unroll
        for (int i = 0; i < 4; i++) {
            int r = rb + i * 32;
            split_store(Ash, Asl, r * GSH + c4, *(const float4*)(ar[i] + k0 + c4));
            split_store(Bsh, Bsl, r * GSH + c4, *(const float4*)(br[i] + k0 + c4));
        }
        __syncthreads();
#pragma unroll
        for (int ks = 0; ks < 2; ks++) {
            const int kcA = ks * 16 + acs, kcB = ks * 16 + bcs;
            uint32_t ah[4][4], al[4][4];
#pragma unroll
            for (int mt = 0; mt < 4; mt++) {
                ldmx4(smaddr(&Ash[(arl + mt * 16) * GSH + kcA]), ah[mt]);
                ldmx4(smaddr(&Asl[(arl + mt * 16) * GSH + kcA]), al[mt]);
            }
#pragma unroll
            for (int nt = 0; nt < 4; nt++) {
                uint32_t bh[2], bl[2];
                ldmx2(smaddr(&Bsh[(brl + nt * 8) * GSH + kcB]), bh);
                ldmx2(smaddr(&Bsl[(brl + nt * 8) * GSH + kcB]), bl);
#pragma unroll
                for (int mt = 0; mt < 4; mt++) {
                    mma16816(acc[mt][nt], ah[mt], bh);
                    mma16816(acc[mt][nt], al[mt], bh);
                    mma16816(acc[mt][nt], ah[mt], bl);
                }
            }
        }
    }

    const int er = m0 + wm * 64 + (lane >> 2);
    const int ec = n0 + wn * 32 + 2 * (lane & 3);
#pragma unroll
    for (int mt = 0; mt < 4; mt++)
#pragma unroll
        for (int nt = 0; nt < 4; nt++) {
            int col = ec + nt * 8;
#pragma unroll
            for (int hf = 0; hf < 2; hf++) {
                int   row = er + mt * 16 + hf * 8;
                float v0 = acc[mt][nt][hf * 2], v1 = acc[mt][nt][hf * 2 + 1];
                if (modeOut == 0) {
                    int bb = row / MrowsPerB, mm = row - bb * MrowsPerB;
                    int hh = col >> 6, dd = col & 63;
                    float* p = outp + (((size_t)(bb * Hh + hh)) * MrowsPerB + mm) * Dh + dd;
                    *(float2*)p = make_float2(v0, v1);
                } else {
                    float* p = outp + (size_t)row * Cdim + col;
                    *(float2*)p = make_float2(v0, v1);
                }
            }
        }
}

// ---------------- Flash attention (split-fp16, 3x mma) -----------------------
// grid (16, H, B), 256 threads (8 warps). 64 q-rows x 64 kv per tile.
// warp grid 4(q) x 2(col of 32) for both S and O.
#define ASTR 72                     // half stride (144B: conflict-free ldmatrix)
#define SSTR 68                     // float stride for S buffer
#define ATT_SMEM_BYTES (8 * 64 * ASTR * 2 + 64 * SSTR * 4 + 3 * 64 * 4)

__global__ __launch_bounds__(256) void attn_mma(
    const float* __restrict__ qg, const float* __restrict__ kg,
    const float* __restrict__ vg, const void* __restrict__ maskp,
    float* __restrict__ yg)
{
    extern __shared__ __half sh[];
    __half* Qh = sh;
    __half* Ql = Qh + 64 * ASTR;
    __half* Kh = Ql + 64 * ASTR;
    __half* Kl = Kh + 64 * ASTR;
    __half* Vh = Kl + 64 * ASTR;
    __half* Vl = Vh + 64 * ASTR;
    __half* Ph = Vl + 64 * ASTR;
    __half* Pl = Ph + 64 * ASTR;
    float*  Sf   = (float*)(Pl + 64 * ASTR);
    float*  mrow = Sf + 64 * SSTR;
    float*  lrow = mrow + 64;
    float*  crow = lrow + 64;

    const int tid = threadIdx.x, lane = tid & 31, w = tid >> 5;
    const int wq = w >> 1, wk = w & 1;
    const int b = blockIdx.z, h = blockIdx.y, qt = blockIdx.x;
    const int mode = g_maskmode;

    // --- load Q tile, init stats ---
    const float* qbase = qg + (((size_t)(b * Hh + h)) * NT + qt * 64) * Dh;
#pragma unroll
    for (int i = 0; i < 4; i++) {
        int e = tid + i * 256;
        int r = e >> 4, cc = (e & 15) * 4;
        split_store(Qh, Ql, r * ASTR + cc, *(const float4*)(qbase + r * Dh + cc));
    }
    if (tid < 64) { mrow[tid] = -1e30f; lrow[tid] = 0.f; }
    __syncthreads();

    // --- preload Q fragments (4 k-chunks, hi/lo) ---
    uint32_t qf[4][2][4];
    {
        const int rl = wq * 16 + (lane & 15);
        const int cs = (lane >> 4) * 8;
#pragma unroll
        for (int kc = 0; kc < 4; kc++) {
            ldmx4(smaddr(&Qh[rl * ASTR + kc * 16 + cs]), qf[kc][0]);
            ldmx4(smaddr(&Ql[rl * ASTR + kc * 16 + cs]), qf[kc][1]);
        }
    }

    float oacc[4][4];
#pragma unroll
    for (int nt = 0; nt < 4; nt++)
#pragma unroll
        for (int q = 0; q < 4; q++) oacc[nt][q] = 0.f;

    const float* kbase = kg + ((size_t)(b * Hh + h)) * NKT * Dh;
    const float* vbase = vg + ((size_t)(b * Hh + h)) * NKT * Dh;
    const size_t mbase0 = ((size_t)b * NT + (size_t)qt * 64) * NKT;

    for (int kt = 0; kt < NKT / 64; kt++) {
        __syncthreads();  // guard K/V/P reuse
#pragma unroll
        for (int i = 0; i < 4; i++) {
            int e = tid + i * 256;
            int r = e >> 4, cc = (e & 15) * 4;
            const float* kp = kbase + (size_t)(kt * 64 + r) * Dh + cc;
            const float* vp = vbase + (size_t)(kt * 64 + r) * Dh + cc;
            split_store(Kh, Kl, r * ASTR + cc, *(const float4*)kp);
            split_store(Vh, Vl, r * ASTR + cc, *(const float4*)vp);
        }
        __syncthreads();

        // --- S = Q K^T (warp strip 16q x 32key) ---
        float sacc[4][4];
#pragma unroll
        for (int nt = 0; nt < 4; nt++)
#pragma unroll
            for (int q = 0; q < 4; q++) sacc[nt][q] = 0.f;

        {
            const int brl = wk * 32 + (lane & 7);
            const int bcs = ((lane >> 3) & 1) * 8;
#pragma unroll
            for (int kc = 0; kc < 4; kc++) {
#pragma unroll
                for (int nt = 0; nt < 4; nt++) {
                    uint32_t bh[2], bl[2];
                    ldmx2(smaddr(&Kh[(brl + nt * 8) * ASTR + kc * 16 + bcs]), bh);
                    ldmx2(smaddr(&Kl[(brl + nt * 8) * ASTR + kc * 16 + bcs]), bl);
                    mma16816(sacc[nt], qf[kc][0], bh);
                    mma16816(sacc[nt], qf[kc][1], bh);
                    mma16816(sacc[nt], qf[kc][0], bl);
                }
            }
        }
        // write S tile
        {
            const int r0 = wq * 16 + (lane >> 2);
            const int c0 = wk * 32 + 2 * (lane & 3);
#pragma unroll
            for (int nt = 0; nt < 4; nt++) {
                *(float2*)&Sf[r0 * SSTR + c0 + nt * 8]       = make_float2(sacc[nt][0], sacc[nt][1]);
                *(float2*)&Sf[(r0 + 8) * SSTR + c0 + nt * 8] = make_float2(sacc[nt][2], sacc[nt][3]);
            }
        }
        __syncthreads();

        // --- softmax pass: 4 threads per row, 16 cols each ---
        {
            const int row = tid >> 2, sub = tid & 3;
            const size_t mb = mbase0 + (size_t)row * NKT + (size_t)kt * 64 + sub * 16;
            bool bm[16];
            if (mode == 0) {
                uint4 u = *(const uint4*)((const unsigned char*)maskp + mb);
                uint32_t ww[4] = {u.x, u.y, u.z, u.w};
#pragma unroll
                for (int q = 0; q < 4; q++)
#pragma unroll
                    for (int j = 0; j < 4; j++)
                        bm[q * 4 + j] = ((ww[q] >> (8 * j)) & 0xff) != 0;
            } else if (mode == 1) {
                const int* ip = (const int*)maskp + mb;
#pragma unroll
                for (int q = 0; q < 4; q++) {
                    int4 v = *(const int4*)(ip + q * 4);
                    bm[q * 4 + 0] = v.x != 0; bm[q * 4 + 1] = v.y != 0;
                    bm[q * 4 + 2] = v.z != 0; bm[q * 4 + 3] = v.w != 0;
                }
            } else {
                const float* fp = (const float*)maskp + mb;
#pragma unroll
                for (int q = 0; q < 4; q++) {
                    float4 v = *(const float4*)(fp + q * 4);
                    bm[q * 4 + 0] = v.x != 0.f; bm[q * 4 + 1] = v.y != 0.f;
                    bm[q * 4 + 2] = v.z != 0.f; bm[q * 4 + 3] = v.w != 0.f;
                }
            }
            const float* srow = &Sf[row * SSTR + sub * 16];
            float sv[16], rm = -1e30f;
#pragma unroll
            for (int j = 0; j < 16; j++) {
                sv[j] = bm[j] ? -1e30f : srow[j] * 0.125f;
                rm = fmaxf(rm, sv[j]);
            }
            rm = fmaxf(rm, __shfl_xor_sync(0xffffffffu, rm, 1));
            rm = fmaxf(rm, __shfl_xor_sync(0xffffffffu, rm, 2));
            float mold = mrow[row];
            float mnew = fmaxf(mold, rm);
            float cf   = __expf(mold - mnew);
            float rs   = 0.f, pv[16];
#pragma unroll
            for (int j = 0; j < 16; j++) { pv[j] = __expf(sv[j] - mnew); rs += pv[j]; }
            __half* php = &Ph[row * ASTR + sub * 16];
            __half* plp = &Pl[row * ASTR + sub * 16];
#pragma unroll
            for (int j = 0; j < 16; j += 2) {
                __half h0 = __float2half_rn(pv[j]), h1 = __float2half_rn(pv[j + 1]);
                *(__half2*)(php + j) = __halves2half2(h0, h1);
                *(__half2*)(plp + j) = __halves2half2(
                    __float2half_rn(pv[j] - __half2float(h0)),
                    __float2half_rn(pv[j + 1] - __half2float(h1)));
            }
            rs += __shfl_xor_sync(0xffffffffu, rs, 1);
            rs += __shfl_xor_sync(0xffffffffu, rs, 2);
            if (sub == 0) {
                mrow[row] = mnew;
                lrow[row] = lrow[row] * cf + rs;
                crow[row] = cf;
            }
        }
        __syncthreads();

        // --- rescale O, then O += P V ---
        {
            float c0 = crow[wq * 16 + (lane >> 2)];
            float c1 = crow[wq * 16 + (lane >> 2) + 8];
#pragma unroll
            for (int nt = 0; nt < 4; nt++) {
                oacc[nt][0] *= c0; oacc[nt][1] *= c0;
                oacc[nt][2] *= c1; oacc[nt][3] *= c1;
            }
            const int prl = wq * 16 + (lane & 15);
            const int pcs = (lane >> 4) * 8;
            const int vrl = lane & 15;
#pragma unroll
            for (int kc = 0; kc < 4; kc++) {
                uint32_t pfh[4], pfl[4];
                ldmx4(smaddr(&Ph[prl * ASTR + kc * 16 + pcs]), pfh);
                ldmx4(smaddr(&Pl[prl * ASTR + kc * 16 + pcs]), pfl);
#pragma unroll
                for (int nt = 0; nt < 4; nt++) {
                    uint32_t vh[2], vl[2];
                    ldmx2t(smaddr(&Vh[(kc * 16 + vrl) * ASTR + wk * 32 + nt * 8]), vh);
                    ldmx2t(smaddr(&Vl[(kc * 16 + vrl) * ASTR + wk * 32 + nt * 8]), vl);
                    mma16816(oacc[nt], pfh, vh);
                    mma16816(oacc[nt], pfl, vh);
                    mma16816(oacc[nt], pfh, vl);
                }
            }
        }
    }

    // --- epilogue: normalize, write y [B,NT,C] (col = h*64 + d) ---
    {
        const int r0 = wq * 16 + (lane >> 2);
        float l0 = lrow[r0], l1 = lrow[r0 + 8];
        float i0 = (l0 > 0.f) ? 1.f / l0 : 0.f;
        float i1 = (l1 > 0.f) ? 1.f / l1 : 0.f;
        const int c0 = h * 64 + wk * 32 + 2 * (lane & 3);
        float* y0 = yg + ((size_t)b * NT + qt * 64 + r0) * Cdim;
        float* y1 = yg + ((size_t)b * NT + qt * 64 + r0 + 8) * Cdim;
#pragma unroll
        for (int nt = 0; nt < 4; nt++) {
            *(float2*)(y0 + c0 + nt * 8) = make_float2(oacc[nt][0] * i0, oacc[nt][1] * i0);
            *(float2*)(y1 + c0 + nt * 8) = make_float2(oacc[nt][2] * i1, oacc[nt][3] * i1);
        }
    }
}

// ---------------- launch ------------------------------------------------------
extern "C" void kernel_launch(void* const* d_in, const int* in_sizes, int n_in,
                              void* d_out, int out_size)
{
    const float* x  = (const float*)d_in[0];
    const float* c  = (const float*)d_in[1];
    const void*  mk = d_in[2];
    const float* Wq = (const float*)d_in[3];
    const float* Wk = (const float*)d_in[4];
    const float* Wv = (const float*)d_in[5];
    const float* Wp = (const float*)d_in[6];
    float* out = (float*)d_out;

    float *qp, *kp, *vp, *yp;
    cudaGetSymbolAddress((void**)&qp, g_q);
    cudaGetSymbolAddress((void**)&kp, g_k);
    cudaGetSymbolAddress((void**)&vp, g_v);
    cudaGetSymbolAddress((void**)&yp, g_y);

    cudaFuncSetAttribute(attn_mma, cudaFuncAttributeMaxDynamicSharedMemorySize,
                         ATT_SMEM_BYTES);

    detect_mask_mode<<<1, 256>>>((const unsigned char*)mk);

    gemm_mma<<<dim3(Cdim / 128, Bc * NT  / 128), 256>>>(x, nullptr, Wq, qp, NT,  0, 0);
    gemm_mma<<<dim3(Cdim / 128, Bc * NKT / 128), 256>>>(x, c,       Wk, kp, NKT, 1, 0);
    gemm_mma<<<dim3(Cdim / 128, Bc * NKT / 128), 256>>>(x, c,       Wv, vp, NKT, 1, 0);

    attn_mma<<<dim3(NT / 64, Hh, Bc), 256, ATT_SMEM_BYTES>>>(qp, kp, vp, mk, yp);

    gemm_mma<<<dim3(Cdim / 128, Bc * NT / 128), 256>>>(yp, nullptr, Wp, out, NT, 0, 1);
}

// round 6
// speedup vs baseline: 3.1168x; 1.0713x over previous
#include <cuda_runtime.h>
#include <cuda_fp16.h>
#include <stdint.h>

#define Bc   8
#define Hh   8
#define NT   1024
#define NKT  2048
#define Cdim 512
#define Dh   64

// ---------------- scratch (fp16 hi/lo pairs; no allocation allowed) ----------
__device__ __half g_xh[(size_t)Bc * NT * Cdim],  g_xl[(size_t)Bc * NT * Cdim];
__device__ __half g_ch[(size_t)Bc * NT * Cdim],  g_cl[(size_t)Bc * NT * Cdim];
__device__ __half g_wqh[Cdim * Cdim], g_wql[Cdim * Cdim];
__device__ __half g_wkh[Cdim * Cdim], g_wkl[Cdim * Cdim];
__device__ __half g_wvh[Cdim * Cdim], g_wvl[Cdim * Cdim];
__device__ __half g_wph[Cdim * Cdim], g_wpl[Cdim * Cdim];
__device__ __half g_qh[(size_t)Bc * Hh * NT  * Dh], g_ql[(size_t)Bc * Hh * NT  * Dh];
__device__ __half g_kh[(size_t)Bc * Hh * NKT * Dh], g_kl[(size_t)Bc * Hh * NKT * Dh];
__device__ __half g_vh[(size_t)Bc * Hh * NKT * Dh], g_vl[(size_t)Bc * Hh * NKT * Dh];
__device__ __half g_yh[(size_t)Bc * NT * Cdim],     g_yl[(size_t)Bc * NT * Cdim];
__device__ int    g_maskmode;

// ---------------- helpers -----------------------------------------------------
__device__ __forceinline__ uint32_t smaddr(const void* p) {
    return (uint32_t)__cvta_generic_to_shared(p);
}
__device__ __forceinline__ void cpa16(uint32_t d, const void* s) {
    asm volatile("cp.async.ca.shared.global [%0], [%1], 16;" :: "r"(d), "l"(s));
}
__device__ __forceinline__ void cpcommit() { asm volatile("cp.async.commit_group;"); }
__device__ __forceinline__ void cpwait0()  { asm volatile("cp.async.wait_group 0;"); }

__device__ __forceinline__ void ldmx4(uint32_t a, uint32_t* r) {
    asm volatile("ldmatrix.sync.aligned.m8n8.x4.shared.b16 {%0,%1,%2,%3}, [%4];"
                 : "=r"(r[0]), "=r"(r[1]), "=r"(r[2]), "=r"(r[3]) : "r"(a));
}
__device__ __forceinline__ void ldmx2(uint32_t a, uint32_t* r) {
    asm volatile("ldmatrix.sync.aligned.m8n8.x2.shared.b16 {%0,%1}, [%2];"
                 : "=r"(r[0]), "=r"(r[1]) : "r"(a));
}
__device__ __forceinline__ void ldmx2t(uint32_t a, uint32_t* r) {
    asm volatile("ldmatrix.sync.aligned.m8n8.x2.trans.shared.b16 {%0,%1}, [%2];"
                 : "=r"(r[0]), "=r"(r[1]) : "r"(a));
}
__device__ __forceinline__ void mma16816(float* c, const uint32_t* a, const uint32_t* b) {
    asm volatile("mma.sync.aligned.m16n8k16.row.col.f32.f16.f16.f32 "
                 "{%0,%1,%2,%3},{%4,%5,%6,%7},{%8,%9},{%0,%1,%2,%3};"
                 : "+f"(c[0]), "+f"(c[1]), "+f"(c[2]), "+f"(c[3])
                 : "r"(a[0]), "r"(a[1]), "r"(a[2]), "r"(a[3]), "r"(b[0]), "r"(b[1]));
}

// ---------------- prep: fp32 -> (hi, lo) fp16 ----------------------------------
__global__ void split_f32(const float* __restrict__ s, __half* __restrict__ h,
                          __half* __restrict__ l, int n)
{
    int i = (blockIdx.x * blockDim.x + threadIdx.x) * 4;
    if (i >= n) return;
    float4 v = *(const float4*)(s + i);
    __half hx = __float2half_rn(v.x), hy = __float2half_rn(v.y);
    __half hz = __float2half_rn(v.z), hw = __float2half_rn(v.w);
    *(__half2*)(h + i)     = __halves2half2(hx, hy);
    *(__half2*)(h + i + 2) = __halves2half2(hz, hw);
    *(__half2*)(l + i)     = __halves2half2(__float2half_rn(v.x - __half2float(hx)),
                                            __float2half_rn(v.y - __half2float(hy)));
    *(__half2*)(l + i + 2) = __halves2half2(__float2half_rn(v.z - __half2float(hz)),
                                            __float2half_rn(v.w - __half2float(hw)));
}

// ---------------- mask dtype detection -----------------------------------------
__global__ void detect_mask_mode(const unsigned char* __restrict__ m) {
    bool hi = false, f3 = false;
    for (int i = threadIdx.x; i < 8192; i += blockDim.x) {
        unsigned char v = m[i];
        int p = i & 3;
        if (p == 3 && v == 0x3f) f3 = true;
        if (p != 0 && v != 0)    hi = true;
    }
    int a3 = __syncthreads_or(f3 ? 1 : 0);
    int ah = __syncthreads_or(hi ? 1 : 0);
    if (threadIdx.x == 0) g_maskmode = a3 ? 2 : (ah ? 0 : 1);
}

// ---------------- GEMM: Y = A @ W^T (split-fp16, 3x mma, cp.async 2-stage) ----
// block 128x128, K-tile 32, 8 warps (2x4), warp tile 64x32.
// modeIn 1 -> A rows gathered from concat(A0,A1).
// modeOut 0 -> head-split hi/lo fp16; 1 -> flat fp32 [rows,C].
#define GKT 32
#define GSH 40
#define GSZ (128 * GSH)
#define GEMM_SMEM_BYTES (2 * 4 * GSZ * 2)   // 2 stages x 4 arrays x 128x40 halves

__global__ __launch_bounds__(256, 2) void gemm_mma(
    const __half* __restrict__ Ah0, const __half* __restrict__ Al0,
    const __half* __restrict__ Ah1, const __half* __restrict__ Al1,
    const __half* __restrict__ Wh,  const __half* __restrict__ Wl,
    float* __restrict__ outF, __half* __restrict__ outH, __half* __restrict__ outL,
    int MrowsPerB, int modeIn, int modeOut)
{
    extern __shared__ __half gs[];
    const int tid = threadIdx.x, lane = tid & 31, w = tid >> 5;
    const int wm = w >> 2, wn = w & 3;
    const int m0 = blockIdx.y * 128, n0 = blockIdx.x * 128;
    const int lrow = tid >> 2;           // 0..63
    const int lch  = (tid & 3) * 8;      // half offset of 16B chunk

    const __half *arh[2], *arl[2], *brh[2], *brl[2];
#pragma unroll
    for (int p = 0; p < 2; p++) {
        int r = lrow + p * 64, gm = m0 + r;
        int bb = gm / MrowsPerB, mm = gm - bb * MrowsPerB;
        size_t off;
        if (modeIn == 0 || mm < NT) {
            off = ((size_t)bb * NT + mm) * Cdim; arh[p] = Ah0 + off; arl[p] = Al0 + off;
        } else {
            off = ((size_t)bb * NT + (mm - NT)) * Cdim; arh[p] = Ah1 + off; arl[p] = Al1 + off;
        }
        size_t wo = (size_t)(n0 + r) * Cdim;
        brh[p] = Wh + wo; brl[p] = Wl + wo;
    }

    float acc[4][4][4];
#pragma unroll
    for (int a = 0; a < 4; a++)
#pragma unroll
        for (int b2 = 0; b2 < 4; b2++)
#pragma unroll
            for (int q = 0; q < 4; q++) acc[a][b2][q] = 0.f;

    const int arlr = wm * 64 + (lane & 15);
    const int acs  = (lane >> 4) * 8;
    const int brlr = wn * 32 + (lane & 7);
    const int bcs  = ((lane >> 3) & 1) * 8;

    auto loadStage = [&](int st, int k0) {
        __half* b = gs + st * 4 * GSZ;
        const uint32_t d0 = (uint32_t)(lrow * GSH + lch);
#pragma unroll
        for (int p = 0; p < 2; p++) {
            uint32_t d = d0 + p * 64 * GSH;
            cpa16(smaddr(b + d),           arh[p] + k0 + lch);
            cpa16(smaddr(b + GSZ + d),     arl[p] + k0 + lch);
            cpa16(smaddr(b + 2 * GSZ + d), brh[p] + k0 + lch);
            cpa16(smaddr(b + 3 * GSZ + d), brl[p] + k0 + lch);
        }
    };

    loadStage(0, 0); cpcommit();
    const int NTILES = Cdim / GKT;   // 16
    for (int t = 0; t < NTILES; t++) {
        cpwait0(); __syncthreads();
        if (t + 1 < NTILES) { loadStage((t + 1) & 1, (t + 1) * GKT); cpcommit(); }

        __half* Ash = gs + (t & 1) * 4 * GSZ;
        __half* Asl = Ash + GSZ;
        __half* Bsh = Ash + 2 * GSZ;
        __half* Bsl = Ash + 3 * GSZ;
#pragma unroll
        for (int ks = 0; ks < 2; ks++) {
            const int kcA = ks * 16 + acs, kcB = ks * 16 + bcs;
            uint32_t ah[4][4], al[4][4];
#pragma unroll
            for (int mt = 0; mt < 4; mt++) {
                ldmx4(smaddr(&Ash[(arlr + mt * 16) * GSH + kcA]), ah[mt]);
                ldmx4(smaddr(&Asl[(arlr + mt * 16) * GSH + kcA]), al[mt]);
            }
#pragma unroll
            for (int nt = 0; nt < 4; nt++) {
                uint32_t bh[2], bl[2];
                ldmx2(smaddr(&Bsh[(brlr + nt * 8) * GSH + kcB]), bh);
                ldmx2(smaddr(&Bsl[(brlr + nt * 8) * GSH + kcB]), bl);
#pragma unroll
                for (int mt = 0; mt < 4; mt++) {
                    mma16816(acc[mt][nt], ah[mt], bh);
                    mma16816(acc[mt][nt], al[mt], bh);
                    mma16816(acc[mt][nt], ah[mt], bl);
                }
            }
        }
    }

    const int er = m0 + wm * 64 + (lane >> 2);
    const int ec = n0 + wn * 32 + 2 * (lane & 3);
#pragma unroll
    for (int mt = 0; mt < 4; mt++)
#pragma unroll
        for (int nt = 0; nt < 4; nt++) {
            int col = ec + nt * 8;
#pragma unroll
            for (int hf = 0; hf < 2; hf++) {
                int   row = er + mt * 16 + hf * 8;
                float v0 = acc[mt][nt][hf * 2], v1 = acc[mt][nt][hf * 2 + 1];
                if (modeOut == 0) {
                    int bb = row / MrowsPerB, mm = row - bb * MrowsPerB;
                    int hh = col >> 6, dd = col & 63;
                    size_t p = (((size_t)(bb * Hh + hh)) * MrowsPerB + mm) * Dh + dd;
                    __half h0 = __float2half_rn(v0), h1 = __float2half_rn(v1);
                    *(__half2*)(outH + p) = __halves2half2(h0, h1);
                    *(__half2*)(outL + p) = __halves2half2(
                        __float2half_rn(v0 - __half2float(h0)),
                        __float2half_rn(v1 - __half2float(h1)));
                } else {
                    *(float2*)(outF + (size_t)row * Cdim + col) = make_float2(v0, v1);
                }
            }
        }
}

// ---------------- Flash attention (split-fp16, 3x mma) -------------------------
#define ASTR 72
#define SSTR 68
#define ATT_SMEM_BYTES (8 * 64 * ASTR * 2 + 64 * SSTR * 4 + 3 * 64 * 4)

__global__ __launch_bounds__(256, 2) void attn_mma(
    const __half* __restrict__ qhg, const __half* __restrict__ qlg,
    const __half* __restrict__ khg, const __half* __restrict__ klg,
    const __half* __restrict__ vhg, const __half* __restrict__ vlg,
    const void* __restrict__ maskp,
    __half* __restrict__ yh, __half* __restrict__ yl)
{
    extern __shared__ __half sh[];
    __half* Qh = sh;
    __half* Ql = Qh + 64 * ASTR;
    __half* Kh = Ql + 64 * ASTR;
    __half* Kl = Kh + 64 * ASTR;
    __half* Vh = Kl + 64 * ASTR;
    __half* Vl = Vh + 64 * ASTR;
    __half* Ph = Vl + 64 * ASTR;
    __half* Pl = Ph + 64 * ASTR;
    float*  Sf   = (float*)(Pl + 64 * ASTR);
    float*  mrow = Sf + 64 * SSTR;
    float*  lrow = mrow + 64;
    float*  crow = lrow + 64;

    const int tid = threadIdx.x, lane = tid & 31, w = tid >> 5;
    const int wq = w >> 1, wk = w & 1;
    const int b = blockIdx.z, h = blockIdx.y, qt = blockIdx.x;
    const int mode = g_maskmode;

    // --- load Q tile (cp.async), init stats ---
    {
        const size_t qo = (((size_t)(b * Hh + h)) * NT + qt * 64) * Dh;
#pragma unroll
        for (int i = 0; i < 2; i++) {
            int pos = tid + i * 256;
            int r = pos >> 3, cc = (pos & 7) * 8;
            cpa16(smaddr(Qh + r * ASTR + cc), qhg + qo + r * Dh + cc);
            cpa16(smaddr(Ql + r * ASTR + cc), qlg + qo + r * Dh + cc);
        }
        cpcommit();
    }
    if (tid < 64) { mrow[tid] = -1e30f; lrow[tid] = 0.f; }
    cpwait0(); __syncthreads();

    // --- preload Q fragments ---
    uint32_t qf[4][2][4];
    {
        const int rl = wq * 16 + (lane & 15);
        const int cs = (lane >> 4) * 8;
#pragma unroll
        for (int kc = 0; kc < 4; kc++) {
            ldmx4(smaddr(&Qh[rl * ASTR + kc * 16 + cs]), qf[kc][0]);
            ldmx4(smaddr(&Ql[rl * ASTR + kc * 16 + cs]), qf[kc][1]);
        }
    }

    float oacc[4][4];
#pragma unroll
    for (int nt = 0; nt < 4; nt++)
#pragma unroll
        for (int q = 0; q < 4; q++) oacc[nt][q] = 0.f;

    const size_t kvo = ((size_t)(b * Hh + h)) * NKT * Dh;
    const size_t mbase0 = ((size_t)b * NT + (size_t)qt * 64) * NKT;

    for (int kt = 0; kt < NKT / 64; kt++) {
        __syncthreads();  // previous tile fully consumed
#pragma unroll
        for (int i = 0; i < 2; i++) {
            int pos = tid + i * 256;
            int r = pos >> 3, cc = (pos & 7) * 8;
            size_t go = kvo + (size_t)(kt * 64 + r) * Dh + cc;
            uint32_t so = r * ASTR + cc;
            cpa16(smaddr(Kh + so), khg + go);
            cpa16(smaddr(Kl + so), klg + go);
            cpa16(smaddr(Vh + so), vhg + go);
            cpa16(smaddr(Vl + so), vlg + go);
        }
        cpcommit(); cpwait0(); __syncthreads();

        // --- S = Q K^T ---
        float sacc[4][4];
#pragma unroll
        for (int nt = 0; nt < 4; nt++)
#pragma unroll
            for (int q = 0; q < 4; q++) sacc[nt][q] = 0.f;
        {
            const int brl = wk * 32 + (lane & 7);
            const int bcs = ((lane >> 3) & 1) * 8;
#pragma unroll
            for (int kc = 0; kc < 4; kc++) {
#pragma unroll
                for (int nt = 0; nt < 4; nt++) {
                    uint32_t bh[2], bl[2];
                    ldmx2(smaddr(&Kh[(brl + nt * 8) * ASTR + kc * 16 + bcs]), bh);
                    ldmx2(smaddr(&Kl[(brl + nt * 8) * ASTR + kc * 16 + bcs]), bl);
                    mma16816(sacc[nt], qf[kc][0], bh);
                    mma16816(sacc[nt], qf[kc][1], bh);
                    mma16816(sacc[nt], qf[kc][0], bl);
                }
            }
        }
        {
            const int r0 = wq * 16 + (lane >> 2);
            const int c0 = wk * 32 + 2 * (lane & 3);
#pragma unroll
            for (int nt = 0; nt < 4; nt++) {
                *(float2*)&Sf[r0 * SSTR + c0 + nt * 8]       = make_float2(sacc[nt][0], sacc[nt][1]);
                *(float2*)&Sf[(r0 + 8) * SSTR + c0 + nt * 8] = make_float2(sacc[nt][2], sacc[nt][3]);
            }
        }
        __syncthreads();

        // --- softmax: 4 threads per row, 16 cols each ---
        {
            const int row = tid >> 2, sub = tid & 3;
            const size_t mb = mbase0 + (size_t)row * NKT + (size_t)kt * 64 + sub * 16;
            bool bm[16];
            if (mode == 0) {
                uint4 u = *(const uint4*)((const unsigned char*)maskp + mb);
                uint32_t ww[4] = {u.x, u.y, u.z, u.w};
#pragma unroll
                for (int q = 0; q < 4; q++)
#pragma unroll
                    for (int j = 0; j < 4; j++)
                        bm[q * 4 + j] = ((ww[q] >> (8 * j)) & 0xff) != 0;
            } else if (mode == 1) {
                const int* ip = (const int*)maskp + mb;
#pragma unroll
                for (int q = 0; q < 4; q++) {
                    int4 v = *(const int4*)(ip + q * 4);
                    bm[q * 4 + 0] = v.x != 0; bm[q * 4 + 1] = v.y != 0;
                    bm[q * 4 + 2] = v.z != 0; bm[q * 4 + 3] = v.w != 0;
                }
            } else {
                const float* fp = (const float*)maskp + mb;
#pragma unroll
                for (int q = 0; q < 4; q++) {
                    float4 v = *(const float4*)(fp + q * 4);
                    bm[q * 4 + 0] = v.x != 0.f; bm[q * 4 + 1] = v.y != 0.f;
                    bm[q * 4 + 2] = v.z != 0.f; bm[q * 4 + 3] = v.w != 0.f;
                }
            }
            const float* srow = &Sf[row * SSTR + sub * 16];
            float sv[16], rm = -1e30f;
#pragma unroll
            for (int j = 0; j < 16; j++) {
                sv[j] = bm[j] ? -1e30f : srow[j] * 0.125f;
                rm = fmaxf(rm, sv[j]);
            }
            rm = fmaxf(rm, __shfl_xor_sync(0xffffffffu, rm, 1));
            rm = fmaxf(rm, __shfl_xor_sync(0xffffffffu, rm, 2));
            float mold = mrow[row];
            float mnew = fmaxf(mold, rm);
            float cf   = __expf(mold - mnew);
            float rs   = 0.f, pv[16];
#pragma unroll
            for (int j = 0; j < 16; j++) { pv[j] = __expf(sv[j] - mnew); rs += pv[j]; }
            __half* php = &Ph[row * ASTR + sub * 16];
            __half* plp = &Pl[row * ASTR + sub * 16];
#pragma unroll
            for (int j = 0; j < 16; j += 2) {
                __half h0 = __float2half_rn(pv[j]), h1 = __float2half_rn(pv[j + 1]);
                *(__half2*)(php + j) = __halves2half2(h0, h1);
                *(__half2*)(plp + j) = __halves2half2(
                    __float2half_rn(pv[j] - __half2float(h0)),
                    __float2half_rn(pv[j + 1] - __half2float(h1)));
            }
            rs += __shfl_xor_sync(0xffffffffu, rs, 1);
            rs += __shfl_xor_sync(0xffffffffu, rs, 2);
            if (sub == 0) {
                mrow[row] = mnew;
                lrow[row] = lrow[row] * cf + rs;
                crow[row] = cf;
            }
        }
        __syncthreads();

        // --- rescale O, O += P V ---
        {
            float c0 = crow[wq * 16 + (lane >> 2)];
            float c1 = crow[wq * 16 + (lane >> 2) + 8];
#pragma unroll
            for (int nt = 0; nt < 4; nt++) {
                oacc[nt][0] *= c0; oacc[nt][1] *= c0;
                oacc[nt][2] *= c1; oacc[nt][3] *= c1;
            }
            const int prl = wq * 16 + (lane & 15);
            const int pcs = (lane >> 4) * 8;
            const int vrl = lane & 15;
#pragma unroll
            for (int kc = 0; kc < 4; kc++) {
                uint32_t pfh[4], pfl[4];
                ldmx4(smaddr(&Ph[prl * ASTR + kc * 16 + pcs]), pfh);
                ldmx4(smaddr(&Pl[prl * ASTR + kc * 16 + pcs]), pfl);
#pragma unroll
                for (int nt = 0; nt < 4; nt++) {
                    uint32_t vh[2], vl[2];
                    ldmx2t(smaddr(&Vh[(kc * 16 + vrl) * ASTR + wk * 32 + nt * 8]), vh);
                    ldmx2t(smaddr(&Vl[(kc * 16 + vrl) * ASTR + wk * 32 + nt * 8]), vl);
                    mma16816(oacc[nt], pfh, vh);
                    mma16816(oacc[nt], pfl, vh);
                    mma16816(oacc[nt], pfh, vl);
                }
            }
        }
    }

    // --- epilogue: normalize, write y as hi/lo fp16 [B,NT,C] ---
    {
        const int r0 = wq * 16 + (lane >> 2);
        float l0 = lrow[r0], l1 = lrow[r0 + 8];
        float i0 = (l0 > 0.f) ? 1.f / l0 : 0.f;
        float i1 = (l1 > 0.f) ? 1.f / l1 : 0.f;
        const int c0 = h * 64 + wk * 32 + 2 * (lane & 3);
        size_t o0 = ((size_t)b * NT + qt * 64 + r0) * Cdim + c0;
        size_t o1 = ((size_t)b * NT + qt * 64 + r0 + 8) * Cdim + c0;
#pragma unroll
        for (int nt = 0; nt < 4; nt++) {
            float a0 = oacc[nt][0] * i0, a1 = oacc[nt][1] * i0;
            float b0 = oacc[nt][2] * i1, b1 = oacc[nt][3] * i1;
            __half ha0 = __float2half_rn(a0), ha1 = __float2half_rn(a1);
            __half hb0 = __float2half_rn(b0), hb1 = __float2half_rn(b1);
            *(__half2*)(yh + o0 + nt * 8) = __halves2half2(ha0, ha1);
            *(__half2*)(yl + o0 + nt * 8) = __halves2half2(
                __float2half_rn(a0 - __half2float(ha0)),
                __float2half_rn(a1 - __half2float(ha1)));
            *(__half2*)(yh + o1 + nt * 8) = __halves2half2(hb0, hb1);
            *(__half2*)(yl + o1 + nt * 8) = __halves2half2(
                __float2half_rn(b0 - __half2float(hb0)),
                __float2half_rn(b1 - __half2float(hb1)));
        }
    }
}

// ---------------- launch --------------------------------------------------------
extern "C" void kernel_launch(void* const* d_in, const int* in_sizes, int n_in,
                              void* d_out, int out_size)
{
    const float* x  = (const float*)d_in[0];
    const float* c  = (const float*)d_in[1];
    const void*  mk = d_in[2];
    const float* Wq = (const float*)d_in[3];
    const float* Wk = (const float*)d_in[4];
    const float* Wv = (const float*)d_in[5];
    const float* Wp = (const float*)d_in[6];
    float* out = (float*)d_out;

    __half *xh, *xl, *ch_, *cl_, *wqh, *wql, *wkh, *wkl, *wvh, *wvl, *wph, *wpl;
    __half *qh, *ql, *kh, *kl, *vh, *vl, *yh, *yl;
    cudaGetSymbolAddress((void**)&xh,  g_xh);  cudaGetSymbolAddress((void**)&xl,  g_xl);
    cudaGetSymbolAddress((void**)&ch_, g_ch);  cudaGetSymbolAddress((void**)&cl_, g_cl);
    cudaGetSymbolAddress((void**)&wqh, g_wqh); cudaGetSymbolAddress((void**)&wql, g_wql);
    cudaGetSymbolAddress((void**)&wkh, g_wkh); cudaGetSymbolAddress((void**)&wkl, g_wkl);
    cudaGetSymbolAddress((void**)&wvh, g_wvh); cudaGetSymbolAddress((void**)&wvl, g_wvl);
    cudaGetSymbolAddress((void**)&wph, g_wph); cudaGetSymbolAddress((void**)&wpl, g_wpl);
    cudaGetSymbolAddress((void**)&qh,  g_qh);  cudaGetSymbolAddress((void**)&ql,  g_ql);
    cudaGetSymbolAddress((void**)&kh,  g_kh);  cudaGetSymbolAddress((void**)&kl,  g_kl);
    cudaGetSymbolAddress((void**)&vh,  g_vh);  cudaGetSymbolAddress((void**)&vl,  g_vl);
    cudaGetSymbolAddress((void**)&yh,  g_yh);  cudaGetSymbolAddress((void**)&yl,  g_yl);

    cudaFuncSetAttribute(gemm_mma, cudaFuncAttributeMaxDynamicSharedMemorySize,
                         GEMM_SMEM_BYTES);
    cudaFuncSetAttribute(attn_mma, cudaFuncAttributeMaxDynamicSharedMemorySize,
                         ATT_SMEM_BYTES);

    detect_mask_mode<<<1, 256>>>((const unsigned char*)mk);

    const int nx = Bc * NT * Cdim;     // 4,194,304
    const int nw = Cdim * Cdim;        // 262,144
    split_f32<<<nx / 1024, 256>>>(x,  xh,  xl,  nx);
    split_f32<<<nx / 1024, 256>>>(c,  ch_, cl_, nx);
    split_f32<<<nw / 1024, 256>>>(Wq, wqh, wql, nw);
    split_f32<<<nw / 1024, 256>>>(Wk, wkh, wkl, nw);
    split_f32<<<nw / 1024, 256>>>(Wv, wvh, wvl, nw);
    split_f32<<<nw / 1024, 256>>>(Wp, wph, wpl, nw);

    gemm_mma<<<dim3(Cdim / 128, Bc * NT  / 128), 256, GEMM_SMEM_BYTES>>>(
        xh, xl, nullptr, nullptr, wqh, wql, nullptr, qh, ql, NT,  0, 0);
    gemm_mma<<<dim3(Cdim / 128, Bc * NKT / 128), 256, GEMM_SMEM_BYTES>>>(
        xh, xl, ch_, cl_,         wkh, wkl, nullptr, kh, kl, NKT, 1, 0);
    gemm_mma<<<dim3(Cdim / 128, Bc * NKT / 128), 256, GEMM_SMEM_BYTES>>>(
        xh, xl, ch_, cl_,         wvh, wvl, nullptr, vh, vl, NKT, 1, 0);

    attn_mma<<<dim3(NT / 64, Hh, Bc), 256, ATT_SMEM_BYTES>>>(
        qh, ql, kh, kl, vh, vl, mk, yh, yl);

    gemm_mma<<<dim3(Cdim / 128, Bc * NT / 128), 256, GEMM_SMEM_BYTES>>>(
        yh, yl, nullptr, nullptr, wph, wpl, out, nullptr, nullptr, NT, 0, 1);
}

// round 7
// speedup vs baseline: 3.7186x; 1.1931x over previous
#include <cuda_runtime.h>
#include <cuda_fp16.h>
#include <stdint.h>

#define Bc   8
#define Hh   8
#define NT   1024
#define NKT  2048
#define Cdim 512
#define Dh   64

// ---------------- scratch (no allocation allowed) ------------------------------
__device__ __half g_xh[(size_t)Bc * NT * Cdim],  g_xl[(size_t)Bc * NT * Cdim];
__device__ __half g_ch[(size_t)Bc * NT * Cdim],  g_cl[(size_t)Bc * NT * Cdim];
__device__ __half g_wqh[Cdim * Cdim], g_wql[Cdim * Cdim];
__device__ __half g_wkh[Cdim * Cdim], g_wkl[Cdim * Cdim];
__device__ __half g_wvh[Cdim * Cdim], g_wvl[Cdim * Cdim];
__device__ __half g_wph[Cdim * Cdim], g_wpl[Cdim * Cdim];
__device__ __half g_qh[(size_t)Bc * Hh * NT  * Dh], g_ql[(size_t)Bc * Hh * NT  * Dh];
__device__ __half g_kh[(size_t)Bc * Hh * NKT * Dh], g_kl[(size_t)Bc * Hh * NKT * Dh];
__device__ __half g_vh[(size_t)Bc * Hh * NKT * Dh], g_vl[(size_t)Bc * Hh * NKT * Dh];
__device__ __half g_yh[(size_t)Bc * NT * Cdim],     g_yl[(size_t)Bc * NT * Cdim];
__device__ unsigned char g_m8[(size_t)Bc * NT * NKT];   // normalized uint8 mask
__device__ int    g_maskmode;

// ---------------- helpers -------------------------------------------------------
__device__ __forceinline__ uint32_t smaddr(const void* p) {
    return (uint32_t)__cvta_generic_to_shared(p);
}
__device__ __forceinline__ void cpa16(uint32_t d, const void* s) {
    asm volatile("cp.async.ca.shared.global [%0], [%1], 16;" :: "r"(d), "l"(s));
}
__device__ __forceinline__ void cpcommit() { asm volatile("cp.async.commit_group;"); }
__device__ __forceinline__ void cpwait0()  { asm volatile("cp.async.wait_group 0;"); }

__device__ __forceinline__ void ldmx4(uint32_t a, uint32_t* r) {
    asm volatile("ldmatrix.sync.aligned.m8n8.x4.shared.b16 {%0,%1,%2,%3}, [%4];"
                 : "=r"(r[0]), "=r"(r[1]), "=r"(r[2]), "=r"(r[3]) : "r"(a));
}
__device__ __forceinline__ void ldmx2(uint32_t a, uint32_t* r) {
    asm volatile("ldmatrix.sync.aligned.m8n8.x2.shared.b16 {%0,%1}, [%2];"
                 : "=r"(r[0]), "=r"(r[1]) : "r"(a));
}
__device__ __forceinline__ void ldmx2t(uint32_t a, uint32_t* r) {
    asm volatile("ldmatrix.sync.aligned.m8n8.x2.trans.shared.b16 {%0,%1}, [%2];"
                 : "=r"(r[0]), "=r"(r[1]) : "r"(a));
}
__device__ __forceinline__ void mma16816(float* c, const uint32_t* a, const uint32_t* b) {
    asm volatile("mma.sync.aligned.m16n8k16.row.col.f32.f16.f16.f32 "
                 "{%0,%1,%2,%3},{%4,%5,%6,%7},{%8,%9},{%0,%1,%2,%3};"
                 : "+f"(c[0]), "+f"(c[1]), "+f"(c[2]), "+f"(c[3])
                 : "r"(a[0]), "r"(a[1]), "r"(a[2]), "r"(a[3]), "r"(b[0]), "r"(b[1]));
}
__device__ __forceinline__ float ex2f(float x) {
    float y; asm("ex2.approx.f32 %0, %1;" : "=f"(y) : "f"(x)); return y;
}

// ---------------- prep kernels ---------------------------------------------------
__global__ void split_f32(const float* __restrict__ s, __half* __restrict__ h,
                          __half* __restrict__ l, int n)
{
    int i = (blockIdx.x * blockDim.x + threadIdx.x) * 4;
    if (i >= n) return;
    float4 v = *(const float4*)(s + i);
    __half hx = __float2half_rn(v.x), hy = __float2half_rn(v.y);
    __half hz = __float2half_rn(v.z), hw = __float2half_rn(v.w);
    *(__half2*)(h + i)     = __halves2half2(hx, hy);
    *(__half2*)(h + i + 2) = __halves2half2(hz, hw);
    *(__half2*)(l + i)     = __halves2half2(__float2half_rn(v.x - __half2float(hx)),
                                            __float2half_rn(v.y - __half2float(hy)));
    *(__half2*)(l + i + 2) = __halves2half2(__float2half_rn(v.z - __half2float(hz)),
                                            __float2half_rn(v.w - __half2float(hw)));
}

__global__ void detect_mask_mode(const unsigned char* __restrict__ m) {
    bool hi = false, f3 = false;
    for (int i = threadIdx.x; i < 8192; i += blockDim.x) {
        unsigned char v = m[i];
        int p = i & 3;
        if (p == 3 && v == 0x3f) f3 = true;
        if (p != 0 && v != 0)    hi = true;
    }
    int a3 = __syncthreads_or(f3 ? 1 : 0);
    int ah = __syncthreads_or(hi ? 1 : 0);
    if (threadIdx.x == 0) g_maskmode = a3 ? 2 : (ah ? 0 : 1);
}

// normalize mask to uint8 (skipped when already uint8; attention selects pointer)
__global__ void mask_to_u8(const void* __restrict__ mp, unsigned char* __restrict__ o) {
    int mode = g_maskmode;
    if (mode == 0) return;
    size_t i = ((size_t)blockIdx.x * blockDim.x + threadIdx.x) * 16;
    if (mode == 1) {
        const int* ip = (const int*)mp + i;
        uchar4 a, b, c, d;
        int4 v0 = *(const int4*)(ip + 0),  v1 = *(const int4*)(ip + 4);
        int4 v2 = *(const int4*)(ip + 8),  v3 = *(const int4*)(ip + 12);
        a = make_uchar4(v0.x != 0, v0.y != 0, v0.z != 0, v0.w != 0);
        b = make_uchar4(v1.x != 0, v1.y != 0, v1.z != 0, v1.w != 0);
        c = make_uchar4(v2.x != 0, v2.y != 0, v2.z != 0, v2.w != 0);
        d = make_uchar4(v3.x != 0, v3.y != 0, v3.z != 0, v3.w != 0);
        *(uchar4*)(o + i)      = a; *(uchar4*)(o + i + 4)  = b;
        *(uchar4*)(o + i + 8)  = c; *(uchar4*)(o + i + 12) = d;
    } else {
        const float* fp = (const float*)mp + i;
#pragma unroll
        for (int q = 0; q < 4; q++) {
            float4 v = *(const float4*)(fp + q * 4);
            *(uchar4*)(o + i + q * 4) =
                make_uchar4(v.x != 0.f, v.y != 0.f, v.z != 0.f, v.w != 0.f);
        }
    }
}

// ---------------- GEMM (unchanged from R6) ---------------------------------------
#define GKT 32
#define GSH 40
#define GSZ (128 * GSH)
#define GEMM_SMEM_BYTES (2 * 4 * GSZ * 2)

__global__ __launch_bounds__(256, 2) void gemm_mma(
    const __half* __restrict__ Ah0, const __half* __restrict__ Al0,
    const __half* __restrict__ Ah1, const __half* __restrict__ Al1,
    const __half* __restrict__ Wh,  const __half* __restrict__ Wl,
    float* __restrict__ outF, __half* __restrict__ outH, __half* __restrict__ outL,
    int MrowsPerB, int modeIn, int modeOut)
{
    extern __shared__ __half gs[];
    const int tid = threadIdx.x, lane = tid & 31, w = tid >> 5;
    const int wm = w >> 2, wn = w & 3;
    const int m0 = blockIdx.y * 128, n0 = blockIdx.x * 128;
    const int lrow = tid >> 2;
    const int lch  = (tid & 3) * 8;

    const __half *arh[2], *arl[2], *brh[2], *brl[2];
#pragma unroll
    for (int p = 0; p < 2; p++) {
        int r = lrow + p * 64, gm = m0 + r;
        int bb = gm / MrowsPerB, mm = gm - bb * MrowsPerB;
        size_t off;
        if (modeIn == 0 || mm < NT) {
            off = ((size_t)bb * NT + mm) * Cdim; arh[p] = Ah0 + off; arl[p] = Al0 + off;
        } else {
            off = ((size_t)bb * NT + (mm - NT)) * Cdim; arh[p] = Ah1 + off; arl[p] = Al1 + off;
        }
        size_t wo = (size_t)(n0 + r) * Cdim;
        brh[p] = Wh + wo; brl[p] = Wl + wo;
    }

    float acc[4][4][4];
#pragma unroll
    for (int a = 0; a < 4; a++)
#pragma unroll
        for (int b2 = 0; b2 < 4; b2++)
#pragma unroll
            for (int q = 0; q < 4; q++) acc[a][b2][q] = 0.f;

    const int arlr = wm * 64 + (lane & 15);
    const int acs  = (lane >> 4) * 8;
    const int brlr = wn * 32 + (lane & 7);
    const int bcs  = ((lane >> 3) & 1) * 8;

    auto loadStage = [&](int st, int k0) {
        __half* b = gs + st * 4 * GSZ;
        const uint32_t d0 = (uint32_t)(lrow * GSH + lch);
#pragma unroll
        for (int p = 0; p < 2; p++) {
            uint32_t d = d0 + p * 64 * GSH;
            cpa16(smaddr(b + d),           arh[p] + k0 + lch);
            cpa16(smaddr(b + GSZ + d),     arl[p] + k0 + lch);
            cpa16(smaddr(b + 2 * GSZ + d), brh[p] + k0 + lch);
            cpa16(smaddr(b + 3 * GSZ + d), brl[p] + k0 + lch);
        }
    };

    loadStage(0, 0); cpcommit();
    const int NTILES = Cdim / GKT;
    for (int t = 0; t < NTILES; t++) {
        cpwait0(); __syncthreads();
        if (t + 1 < NTILES) { loadStage((t + 1) & 1, (t + 1) * GKT); cpcommit(); }

        __half* Ash = gs + (t & 1) * 4 * GSZ;
        __half* Asl = Ash + GSZ;
        __half* Bsh = Ash + 2 * GSZ;
        __half* Bsl = Ash + 3 * GSZ;
#pragma unroll
        for (int ks = 0; ks < 2; ks++) {
            const int kcA = ks * 16 + acs, kcB = ks * 16 + bcs;
            uint32_t ah[4][4], al[4][4];
#pragma unroll
            for (int mt = 0; mt < 4; mt++) {
                ldmx4(smaddr(&Ash[(arlr + mt * 16) * GSH + kcA]), ah[mt]);
                ldmx4(smaddr(&Asl[(arlr + mt * 16) * GSH + kcA]), al[mt]);
            }
#pragma unroll
            for (int nt = 0; nt < 4; nt++) {
                uint32_t bh[2], bl[2];
                ldmx2(smaddr(&Bsh[(brlr + nt * 8) * GSH + kcB]), bh);
                ldmx2(smaddr(&Bsl[(brlr + nt * 8) * GSH + kcB]), bl);
#pragma unroll
                for (int mt = 0; mt < 4; mt++) {
                    mma16816(acc[mt][nt], ah[mt], bh);
                    mma16816(acc[mt][nt], al[mt], bh);
                    mma16816(acc[mt][nt], ah[mt], bl);
                }
            }
        }
    }

    const int er = m0 + wm * 64 + (lane >> 2);
    const int ec = n0 + wn * 32 + 2 * (lane & 3);
#pragma unroll
    for (int mt = 0; mt < 4; mt++)
#pragma unroll
        for (int nt = 0; nt < 4; nt++) {
            int col = ec + nt * 8;
#pragma unroll
            for (int hf = 0; hf < 2; hf++) {
                int   row = er + mt * 16 + hf * 8;
                float v0 = acc[mt][nt][hf * 2], v1 = acc[mt][nt][hf * 2 + 1];
                if (modeOut == 0) {
                    int bb = row / MrowsPerB, mm = row - bb * MrowsPerB;
                    int hh = col >> 6, dd = col & 63;
                    size_t p = (((size_t)(bb * Hh + hh)) * MrowsPerB + mm) * Dh + dd;
                    __half h0 = __float2half_rn(v0), h1 = __float2half_rn(v1);
                    *(__half2*)(outH + p) = __halves2half2(h0, h1);
                    *(__half2*)(outL + p) = __halves2half2(
                        __float2half_rn(v0 - __half2float(h0)),
                        __float2half_rn(v1 - __half2float(h1)));
                } else {
                    *(float2*)(outF + (size_t)row * Cdim + col) = make_float2(v0, v1);
                }
            }
        }
}

// ---------------- Flash attention v2 ---------------------------------------------
// 64 q-rows/block, 64 kv/tile, double-buffered cp.async (K/V/mask), register
// softmax with per-row shfl + single partner-warp smem exchange, fp16 P (hi only),
// V hi/lo 2-term PV. 3 syncs/tile.
#define ASTR 72
#define MPAD 80
#define TSZ  (64 * ASTR)            // halves per tile array
#define MSZ  (64 * MPAD)            // bytes per mask tile
// layout: Qh Ql | K[2][h,l] | V[2][h,l] | Mb[2] | Ph | pm[8][16] ps[8][16]
#define OFF_Q   0
#define OFF_K   (2 * TSZ)
#define OFF_V   (OFF_K + 4 * TSZ)
#define OFF_M   ((OFF_V + 4 * TSZ) * 2)            // byte offset
#define OFF_P   (OFF_M + 2 * MSZ)                  // byte offset
#define OFF_PM  (OFF_P + TSZ * 2)                  // byte offset
#define ATT_SMEM_BYTES (OFF_PM + 2 * 8 * 16 * 4)

__global__ __launch_bounds__(256, 2) void attn_mma(
    const __half* __restrict__ qhg, const __half* __restrict__ qlg,
    const __half* __restrict__ khg, const __half* __restrict__ klg,
    const __half* __restrict__ vhg, const __half* __restrict__ vlg,
    const unsigned char* __restrict__ m8a, const unsigned char* __restrict__ m8b,
    __half* __restrict__ yh, __half* __restrict__ yl)
{
    extern __shared__ __half sh[];
    __half* Qh = sh;
    __half* Ql = sh + TSZ;
    __half* Kb = sh + OFF_K;                        // [stage][h/l]
    __half* Vb = sh + OFF_V;
    unsigned char* Mb = (unsigned char*)sh + OFF_M; // [stage]
    __half* Ph = (__half*)((char*)sh + OFF_P);
    float*  pm = (float*)((char*)sh + OFF_PM);      // [8][16]
    float*  ps = pm + 8 * 16;

    const int tid = threadIdx.x, lane = tid & 31, w = tid >> 5;
    const int wq = w >> 1, wk = w & 1;
    const int b = blockIdx.z, h = blockIdx.y, qt = blockIdx.x;
    const unsigned char* mg = (g_maskmode == 0) ? m8a : m8b;

    const size_t kvo    = ((size_t)(b * Hh + h)) * NKT * Dh;
    const size_t mbase0 = ((size_t)b * NT + (size_t)qt * 64) * NKT;

    auto loadStage = [&](int kt, int st) {
        __half* Khp = Kb + st * 2 * TSZ;
        __half* Klp = Khp + TSZ;
        __half* Vhp = Vb + st * 2 * TSZ;
        __half* Vlp = Vhp + TSZ;
#pragma unroll
        for (int i = 0; i < 2; i++) {
            int pos = tid + i * 256;
            int r = pos >> 3, cc = (pos & 7) * 8;
            size_t go = kvo + (size_t)(kt * 64 + r) * Dh + cc;
            uint32_t so = r * ASTR + cc;
            cpa16(smaddr(Khp + so), khg + go);
            cpa16(smaddr(Klp + so), klg + go);
            cpa16(smaddr(Vhp + so), vhg + go);
            cpa16(smaddr(Vlp + so), vlg + go);
        }
        {
            int r = tid >> 2, cs = (tid & 3) * 16;
            cpa16(smaddr(Mb + st * MSZ + r * MPAD + cs),
                  mg + mbase0 + (size_t)r * NKT + (size_t)kt * 64 + cs);
        }
    };

    // prologue: Q + stage 0
    {
        const size_t qo = (((size_t)(b * Hh + h)) * NT + qt * 64) * Dh;
#pragma unroll
        for (int i = 0; i < 2; i++) {
            int pos = tid + i * 256;
            int r = pos >> 3, cc = (pos & 7) * 8;
            cpa16(smaddr(Qh + r * ASTR + cc), qhg + qo + r * Dh + cc);
            cpa16(smaddr(Ql + r * ASTR + cc), qlg + qo + r * Dh + cc);
        }
        loadStage(0, 0);
        cpcommit();
    }
    cpwait0(); __syncthreads();

    uint32_t qf[4][2][4];
    {
        const int rl = wq * 16 + (lane & 15);
        const int cs = (lane >> 4) * 8;
#pragma unroll
        for (int kc = 0; kc < 4; kc++) {
            ldmx4(smaddr(&Qh[rl * ASTR + kc * 16 + cs]), qf[kc][0]);
            ldmx4(smaddr(&Ql[rl * ASTR + kc * 16 + cs]), qf[kc][1]);
        }
    }

    float oacc[4][4];
#pragma unroll
    for (int nt = 0; nt < 4; nt++)
#pragma unroll
        for (int q = 0; q < 4; q++) oacc[nt][q] = 0.f;
    float m_reg[2] = {-1e30f, -1e30f};
    float l_reg[2] = {0.f, 0.f};

    const int rg   = lane >> 2;            // row-in-group 0..7
    const int mr0  = wq * 16 + rg;         // block-local rows
    const int mr1  = mr0 + 8;
    const float SCL = 0.125f * 1.44269504f;

    for (int kt = 0; kt < NKT / 64; kt++) {
        const int st = kt & 1;
        if (kt > 0) { cpwait0(); __syncthreads(); }
        if (kt + 1 < NKT / 64) { loadStage(kt + 1, st ^ 1); cpcommit(); }

        __half* Khp = Kb + st * 2 * TSZ;
        __half* Klp = Khp + TSZ;
        __half* Vhp = Vb + st * 2 * TSZ;
        __half* Vlp = Vhp + TSZ;
        unsigned char* Mp = Mb + st * MSZ;

        // --- S = Q K^T (3-term split) ---
        float sacc[4][4];
#pragma unroll
        for (int nt = 0; nt < 4; nt++)
#pragma unroll
            for (int q = 0; q < 4; q++) sacc[nt][q] = 0.f;
        {
            const int brl = wk * 32 + (lane & 7);
            const int bcs = ((lane >> 3) & 1) * 8;
#pragma unroll
            for (int kc = 0; kc < 4; kc++) {
#pragma unroll
                for (int nt = 0; nt < 4; nt++) {
                    uint32_t bh[2], bl[2];
                    ldmx2(smaddr(&Khp[(brl + nt * 8) * ASTR + kc * 16 + bcs]), bh);
                    ldmx2(smaddr(&Klp[(brl + nt * 8) * ASTR + kc * 16 + bcs]), bl);
                    mma16816(sacc[nt], qf[kc][0], bh);
                    mma16816(sacc[nt], qf[kc][1], bh);
                    mma16816(sacc[nt], qf[kc][0], bl);
                }
            }
        }

        // --- mask + scale (exp2 units), register softmax ---
        float t0[8], t1[8];
        float rm0 = -1e30f, rm1 = -1e30f;
#pragma unroll
        for (int nt = 0; nt < 4; nt++) {
            const int colb = wk * 32 + nt * 8 + (lane & 3) * 2;
            uint16_t w0 = *(const uint16_t*)&Mp[mr0 * MPAD + colb];
            uint16_t w1 = *(const uint16_t*)&Mp[mr1 * MPAD + colb];
            t0[nt * 2 + 0] = (w0 & 0xff)  ? -1e30f : sacc[nt][0] * SCL;
            t0[nt * 2 + 1] = (w0 >> 8)    ? -1e30f : sacc[nt][1] * SCL;
            t1[nt * 2 + 0] = (w1 & 0xff)  ? -1e30f : sacc[nt][2] * SCL;
            t1[nt * 2 + 1] = (w1 >> 8)    ? -1e30f : sacc[nt][3] * SCL;
            rm0 = fmaxf(rm0, fmaxf(t0[nt * 2], t0[nt * 2 + 1]));
            rm1 = fmaxf(rm1, fmaxf(t1[nt * 2], t1[nt * 2 + 1]));
        }
        rm0 = fmaxf(rm0, __shfl_xor_sync(0xffffffffu, rm0, 1));
        rm0 = fmaxf(rm0, __shfl_xor_sync(0xffffffffu, rm0, 2));
        rm1 = fmaxf(rm1, __shfl_xor_sync(0xffffffffu, rm1, 1));
        rm1 = fmaxf(rm1, __shfl_xor_sync(0xffffffffu, rm1, 2));
        if ((lane & 3) == 0) { pm[w * 16 + rg] = rm0; pm[w * 16 + rg + 8] = rm1; }
        __syncthreads();
        float mn0 = fmaxf(m_reg[0], fmaxf(rm0, pm[(w ^ 1) * 16 + rg]));
        float mn1 = fmaxf(m_reg[1], fmaxf(rm1, pm[(w ^ 1) * 16 + rg + 8]));
        float cf0 = ex2f(m_reg[0] - mn0);
        float cf1 = ex2f(m_reg[1] - mn1);

        float rs0 = 0.f, rs1 = 0.f;
#pragma unroll
        for (int nt = 0; nt < 4; nt++) {
            const int colb = wk * 32 + nt * 8 + (lane & 3) * 2;
            float p00 = ex2f(t0[nt * 2] - mn0), p01 = ex2f(t0[nt * 2 + 1] - mn0);
            float p10 = ex2f(t1[nt * 2] - mn1), p11 = ex2f(t1[nt * 2 + 1] - mn1);
            rs0 += p00 + p01; rs1 += p10 + p11;
            *(__half2*)&Ph[mr0 * ASTR + colb] =
                __halves2half2(__float2half_rn(p00), __float2half_rn(p01));
            *(__half2*)&Ph[mr1 * ASTR + colb] =
                __halves2half2(__float2half_rn(p10), __float2half_rn(p11));
        }
        rs0 += __shfl_xor_sync(0xffffffffu, rs0, 1);
        rs0 += __shfl_xor_sync(0xffffffffu, rs0, 2);
        rs1 += __shfl_xor_sync(0xffffffffu, rs1, 1);
        rs1 += __shfl_xor_sync(0xffffffffu, rs1, 2);
        if ((lane & 3) == 0) { ps[w * 16 + rg] = rs0; ps[w * 16 + rg + 8] = rs1; }

        // rescale O while waiting
#pragma unroll
        for (int nt = 0; nt < 4; nt++) {
            oacc[nt][0] *= cf0; oacc[nt][1] *= cf0;
            oacc[nt][2] *= cf1; oacc[nt][3] *= cf1;
        }
        __syncthreads();
        l_reg[0] = l_reg[0] * cf0 + rs0 + ps[(w ^ 1) * 16 + rg];
        l_reg[1] = l_reg[1] * cf1 + rs1 + ps[(w ^ 1) * 16 + rg + 8];
        m_reg[0] = mn0; m_reg[1] = mn1;

        // --- O += P V (P hi only, V hi/lo) ---
        {
            const int prl = wq * 16 + (lane & 15);
            const int pcs = (lane >> 4) * 8;
            const int vrl = lane & 15;
#pragma unroll
            for (int kc = 0; kc < 4; kc++) {
                uint32_t pfh[4];
                ldmx4(smaddr(&Ph[prl * ASTR + kc * 16 + pcs]), pfh);
#pragma unroll
                for (int nt = 0; nt < 4; nt++) {
                    uint32_t vh[2], vl[2];
                    ldmx2t(smaddr(&Vhp[(kc * 16 + vrl) * ASTR + wk * 32 + nt * 8]), vh);
                    ldmx2t(smaddr(&Vlp[(kc * 16 + vrl) * ASTR + wk * 32 + nt * 8]), vl);
                    mma16816(oacc[nt], pfh, vh);
                    mma16816(oacc[nt], pfh, vl);
                }
            }
        }
    }

    // --- epilogue ---
    {
        float i0 = (l_reg[0] > 0.f) ? 1.f / l_reg[0] : 0.f;
        float i1 = (l_reg[1] > 0.f) ? 1.f / l_reg[1] : 0.f;
        const int c0 = h * 64 + wk * 32 + 2 * (lane & 3);
        size_t o0 = ((size_t)b * NT + qt * 64 + mr0) * Cdim + c0;
        size_t o1 = ((size_t)b * NT + qt * 64 + mr1) * Cdim + c0;
#pragma unroll
        for (int nt = 0; nt < 4; nt++) {
            float a0 = oacc[nt][0] * i0, a1 = oacc[nt][1] * i0;
            float b0 = oacc[nt][2] * i1, b1 = oacc[nt][3] * i1;
            __half ha0 = __float2half_rn(a0), ha1 = __float2half_rn(a1);
            __half hb0 = __float2half_rn(b0), hb1 = __float2half_rn(b1);
            *(__half2*)(yh + o0 + nt * 8) = __halves2half2(ha0, ha1);
            *(__half2*)(yl + o0 + nt * 8) = __halves2half2(
                __float2half_rn(a0 - __half2float(ha0)),
                __float2half_rn(a1 - __half2float(ha1)));
            *(__half2*)(yh + o1 + nt * 8) = __halves2half2(hb0, hb1);
            *(__half2*)(yl + o1 + nt * 8) = __halves2half2(
                __float2half_rn(b0 - __half2float(hb0)),
                __float2half_rn(b1 - __half2float(hb1)));
        }
    }
}

// ---------------- launch -----------------------------------------------------------
extern "C" void kernel_launch(void* const* d_in, const int* in_sizes, int n_in,
                              void* d_out, int out_size)
{
    const float* x  = (const float*)d_in[0];
    const float* c  = (const float*)d_in[1];
    const void*  mk = d_in[2];
    const float* Wq = (const float*)d_in[3];
    const float* Wk = (const float*)d_in[4];
    const float* Wv = (const float*)d_in[5];
    const float* Wp = (const float*)d_in[6];
    float* out = (float*)d_out;

    __half *xh, *xl, *ch_, *cl_, *wqh, *wql, *wkh, *wkl, *wvh, *wvl, *wph, *wpl;
    __half *qh, *ql, *kh, *kl, *vh, *vl, *yh, *yl;
    unsigned char* m8;
    cudaGetSymbolAddress((void**)&xh,  g_xh);  cudaGetSymbolAddress((void**)&xl,  g_xl);
    cudaGetSymbolAddress((void**)&ch_, g_ch);  cudaGetSymbolAddress((void**)&cl_, g_cl);
    cudaGetSymbolAddress((void**)&wqh, g_wqh); cudaGetSymbolAddress((void**)&wql, g_wql);
    cudaGetSymbolAddress((void**)&wkh, g_wkh); cudaGetSymbolAddress((void**)&wkl, g_wkl);
    cudaGetSymbolAddress((void**)&wvh, g_wvh); cudaGetSymbolAddress((void**)&wvl, g_wvl);
    cudaGetSymbolAddress((void**)&wph, g_wph); cudaGetSymbolAddress((void**)&wpl, g_wpl);
    cudaGetSymbolAddress((void**)&qh,  g_qh);  cudaGetSymbolAddress((void**)&ql,  g_ql);
    cudaGetSymbolAddress((void**)&kh,  g_kh);  cudaGetSymbolAddress((void**)&kl,  g_kl);
    cudaGetSymbolAddress((void**)&vh,  g_vh);  cudaGetSymbolAddress((void**)&vl,  g_vl);
    cudaGetSymbolAddress((void**)&yh,  g_yh);  cudaGetSymbolAddress((void**)&yl,  g_yl);
    cudaGetSymbolAddress((void**)&m8,  g_m8);

    cudaFuncSetAttribute(gemm_mma, cudaFuncAttributeMaxDynamicSharedMemorySize,
                         GEMM_SMEM_BYTES);
    cudaFuncSetAttribute(attn_mma, cudaFuncAttributeMaxDynamicSharedMemorySize,
                         ATT_SMEM_BYTES);

    detect_mask_mode<<<1, 256>>>((const unsigned char*)mk);
    mask_to_u8<<<(Bc * NT * NKT) / (256 * 16), 256>>>(mk, m8);

    const int nx = Bc * NT * Cdim;
    const int nw = Cdim * Cdim;
    split_f32<<<nx / 1024, 256>>>(x,  xh,  xl,  nx);
    split_f32<<<nx / 1024, 256>>>(c,  ch_, cl_, nx);
    split_f32<<<nw / 1024, 256>>>(Wq, wqh, wql, nw);
    split_f32<<<nw / 1024, 256>>>(Wk, wkh, wkl, nw);
    split_f32<<<nw / 1024, 256>>>(Wv, wvh, wvl, nw);
    split_f32<<<nw / 1024, 256>>>(Wp, wph, wpl, nw);

    gemm_mma<<<dim3(Cdim / 128, Bc * NT  / 128), 256, GEMM_SMEM_BYTES>>>(
        xh, xl, nullptr, nullptr, wqh, wql, nullptr, qh, ql, NT,  0, 0);
    gemm_mma<<<dim3(Cdim / 128, Bc * NKT / 128), 256, GEMM_SMEM_BYTES>>>(
        xh, xl, ch_, cl_,         wkh, wkl, nullptr, kh, kl, NKT, 1, 0);
    gemm_mma<<<dim3(Cdim / 128, Bc * NKT / 128), 256, GEMM_SMEM_BYTES>>>(
        xh, xl, ch_, cl_,         wvh, wvl, nullptr, vh, vl, NKT, 1, 0);

    attn_mma<<<dim3(NT / 64, Hh, Bc), 256, ATT_SMEM_BYTES>>>(
        qh, ql, kh, kl, vh, vl, (const unsigned char*)mk, m8, yh, yl);

    gemm_mma<<<dim3(Cdim / 128, Bc * NT / 128), 256, GEMM_SMEM_BYTES>>>(
        yh, yl, nullptr, nullptr, wph, wpl, out, nullptr, nullptr, NT, 0, 1);
}

// round 9
// speedup vs baseline: 4.3927x; 1.1813x over previous
#include <cuda_runtime.h>
#include <cuda_fp16.h>
#include <stdint.h>

#define Bc   8
#define Hh   8
#define NT   1024
#define NKT  2048
#define Cdim 512
#define Dh   64

// ---------------- scratch (no allocation allowed) ------------------------------
__device__ __half g_xh[(size_t)Bc * NT * Cdim],  g_xl[(size_t)Bc * NT * Cdim];
__device__ __half g_ch[(size_t)Bc * NT * Cdim],  g_cl[(size_t)Bc * NT * Cdim];
__device__ __half g_wqh[Cdim * Cdim], g_wql[Cdim * Cdim];
__device__ __half g_wkh[Cdim * Cdim], g_wkl[Cdim * Cdim];
__device__ __half g_wvh[Cdim * Cdim], g_wvl[Cdim * Cdim];
__device__ __half g_wph[Cdim * Cdim], g_wpl[Cdim * Cdim];
__device__ __half g_qh[(size_t)Bc * Hh * NT  * Dh], g_ql[(size_t)Bc * Hh * NT  * Dh];
__device__ __half g_kh[(size_t)Bc * Hh * NKT * Dh], g_kl[(size_t)Bc * Hh * NKT * Dh];
__device__ __half g_vh[(size_t)Bc * Hh * NKT * Dh];
__device__ __half g_yh[(size_t)Bc * NT * Cdim],     g_yl[(size_t)Bc * NT * Cdim];
__device__ unsigned char g_m8[(size_t)Bc * NT * NKT];
__device__ int    g_maskmode;

// ---------------- helpers -------------------------------------------------------
__device__ __forceinline__ uint32_t smaddr(const void* p) {
    return (uint32_t)__cvta_generic_to_shared(p);
}
__device__ __forceinline__ void cpa16(uint32_t d, const void* s) {
    asm volatile("cp.async.ca.shared.global [%0], [%1], 16;" :: "r"(d), "l"(s));
}
__device__ __forceinline__ void cpcommit() { asm volatile("cp.async.commit_group;"); }
__device__ __forceinline__ void cpwait0()  { asm volatile("cp.async.wait_group 0;"); }
__device__ __forceinline__ void cpwait1()  { asm volatile("cp.async.wait_group 1;"); }

__device__ __forceinline__ void ldmx4(uint32_t a, uint32_t* r) {
    asm volatile("ldmatrix.sync.aligned.m8n8.x4.shared.b16 {%0,%1,%2,%3}, [%4];"
                 : "=r"(r[0]), "=r"(r[1]), "=r"(r[2]), "=r"(r[3]) : "r"(a));
}
__device__ __forceinline__ void ldmx2(uint32_t a, uint32_t* r) {
    asm volatile("ldmatrix.sync.aligned.m8n8.x2.shared.b16 {%0,%1}, [%2];"
                 : "=r"(r[0]), "=r"(r[1]) : "r"(a));
}
__device__ __forceinline__ void ldmx2t(uint32_t a, uint32_t* r) {
    asm volatile("ldmatrix.sync.aligned.m8n8.x2.trans.shared.b16 {%0,%1}, [%2];"
                 : "=r"(r[0]), "=r"(r[1]) : "r"(a));
}
__device__ __forceinline__ void mma16816(float* c, const uint32_t* a, const uint32_t* b) {
    asm volatile("mma.sync.aligned.m16n8k16.row.col.f32.f16.f16.f32 "
                 "{%0,%1,%2,%3},{%4,%5,%6,%7},{%8,%9},{%0,%1,%2,%3};"
                 : "+f"(c[0]), "+f"(c[1]), "+f"(c[2]), "+f"(c[3])
                 : "r"(a[0]), "r"(a[1]), "r"(a[2]), "r"(a[3]), "r"(b[0]), "r"(b[1]));
}
__device__ __forceinline__ float ex2f(float x) {
    float y; asm("ex2.approx.f32 %0, %1;" : "=f"(y) : "f"(x)); return y;
}
__device__ __forceinline__ void pairbar(int id) {
    asm volatile("bar.sync %0, 64;" :: "r"(id) : "memory");
}

// ---------------- prep kernels ---------------------------------------------------
__global__ void split_f32(const float* __restrict__ s, __half* __restrict__ h,
                          __half* __restrict__ l, int n)
{
    int i = (blockIdx.x * blockDim.x + threadIdx.x) * 4;
    if (i >= n) return;
    float4 v = *(const float4*)(s + i);
    __half hx = __float2half_rn(v.x), hy = __float2half_rn(v.y);
    __half hz = __float2half_rn(v.z), hw = __float2half_rn(v.w);
    *(__half2*)(h + i)     = __halves2half2(hx, hy);
    *(__half2*)(h + i + 2) = __halves2half2(hz, hw);
    *(__half2*)(l + i)     = __halves2half2(__float2half_rn(v.x - __half2float(hx)),
                                            __float2half_rn(v.y - __half2float(hy)));
    *(__half2*)(l + i + 2) = __halves2half2(__float2half_rn(v.z - __half2float(hz)),
                                            __float2half_rn(v.w - __half2float(hw)));
}

__global__ void detect_mask_mode(const unsigned char* __restrict__ m) {
    bool hi = false, f3 = false;
    for (int i = threadIdx.x; i < 8192; i += blockDim.x) {
        unsigned char v = m[i];
        int p = i & 3;
        if (p == 3 && v == 0x3f) f3 = true;
        if (p != 0 && v != 0)    hi = true;
    }
    int a3 = __syncthreads_or(f3 ? 1 : 0);
    int ah = __syncthreads_or(hi ? 1 : 0);
    if (threadIdx.x == 0) g_maskmode = a3 ? 2 : (ah ? 0 : 1);
}

__global__ void mask_to_u8(const void* __restrict__ mp, unsigned char* __restrict__ o) {
    int mode = g_maskmode;
    if (mode == 0) return;
    size_t i = ((size_t)blockIdx.x * blockDim.x + threadIdx.x) * 16;
    if (mode == 1) {
        const int* ip = (const int*)mp + i;
        int4 v0 = *(const int4*)(ip + 0),  v1 = *(const int4*)(ip + 4);
        int4 v2 = *(const int4*)(ip + 8),  v3 = *(const int4*)(ip + 12);
        *(uchar4*)(o + i)      = make_uchar4(v0.x != 0, v0.y != 0, v0.z != 0, v0.w != 0);
        *(uchar4*)(o + i + 4)  = make_uchar4(v1.x != 0, v1.y != 0, v1.z != 0, v1.w != 0);
        *(uchar4*)(o + i + 8)  = make_uchar4(v2.x != 0, v2.y != 0, v2.z != 0, v2.w != 0);
        *(uchar4*)(o + i + 12) = make_uchar4(v3.x != 0, v3.y != 0, v3.z != 0, v3.w != 0);
    } else {
        const float* fp = (const float*)mp + i;
#pragma unroll
        for (int q = 0; q < 4; q++) {
            float4 v = *(const float4*)(fp + q * 4);
            *(uchar4*)(o + i + q * 4) =
                make_uchar4(v.x != 0.f, v.y != 0.f, v.z != 0.f, v.w != 0.f);
        }
    }
}

// ---------------- GEMM: Y = A @ W^T (split-fp16, TERMS mma, cp.async 2-stage) ----
#define GKT 32
#define GSH 40
#define GSZ (128 * GSH)
#define GEMM_SMEM_BYTES (2 * 4 * GSZ * 2)

template <int TERMS>
__global__ __launch_bounds__(256, 2) void gemm_mma(
    const __half* __restrict__ Ah0, const __half* __restrict__ Al0,
    const __half* __restrict__ Ah1, const __half* __restrict__ Al1,
    const __half* __restrict__ Wh,  const __half* __restrict__ Wl,
    float* __restrict__ outF, __half* __restrict__ outH, __half* __restrict__ outL,
    int MrowsPerB, int modeIn, int modeOut)
{
    extern __shared__ __half gs[];
    const int tid = threadIdx.x, lane = tid & 31, w = tid >> 5;
    const int wm = w >> 2, wn = w & 3;
    const int m0 = blockIdx.y * 128, n0 = blockIdx.x * 128;
    const int lrow = tid >> 2;
    const int lch  = (tid & 3) * 8;

    const __half *arh[2], *arl[2], *brh[2], *brl[2];
#pragma unroll
    for (int p = 0; p < 2; p++) {
        int r = lrow + p * 64, gm = m0 + r;
        int bb = gm / MrowsPerB, mm = gm - bb * MrowsPerB;
        size_t off;
        if (modeIn == 0 || mm < NT) {
            off = ((size_t)bb * NT + mm) * Cdim; arh[p] = Ah0 + off; arl[p] = Al0 + off;
        } else {
            off = ((size_t)bb * NT + (mm - NT)) * Cdim; arh[p] = Ah1 + off; arl[p] = Al1 + off;
        }
        size_t wo = (size_t)(n0 + r) * Cdim;
        brh[p] = Wh + wo; brl[p] = Wl + wo;
    }

    float acc[4][4][4];
#pragma unroll
    for (int a = 0; a < 4; a++)
#pragma unroll
        for (int b2 = 0; b2 < 4; b2++)
#pragma unroll
            for (int q = 0; q < 4; q++) acc[a][b2][q] = 0.f;

    const int arlr = wm * 64 + (lane & 15);
    const int acs  = (lane >> 4) * 8;
    const int brlr = wn * 32 + (lane & 7);
    const int bcs  = ((lane >> 3) & 1) * 8;

    auto loadStage = [&](int st, int k0) {
        __half* b = gs + st * 4 * GSZ;
        const uint32_t d0 = (uint32_t)(lrow * GSH + lch);
#pragma unroll
        for (int p = 0; p < 2; p++) {
            uint32_t d = d0 + p * 64 * GSH;
            cpa16(smaddr(b + d),           arh[p] + k0 + lch);
            cpa16(smaddr(b + GSZ + d),     arl[p] + k0 + lch);
            cpa16(smaddr(b + 2 * GSZ + d), brh[p] + k0 + lch);
            if (TERMS == 3)
                cpa16(smaddr(b + 3 * GSZ + d), brl[p] + k0 + lch);
        }
    };

    loadStage(0, 0); cpcommit();
    const int NTILES = Cdim / GKT;
    for (int t = 0; t < NTILES; t++) {
        cpwait0(); __syncthreads();
        if (t + 1 < NTILES) { loadStage((t + 1) & 1, (t + 1) * GKT); cpcommit(); }

        __half* Ash = gs + (t & 1) * 4 * GSZ;
        __half* Asl = Ash + GSZ;
        __half* Bsh = Ash + 2 * GSZ;
        __half* Bsl = Ash + 3 * GSZ;
#pragma unroll
        for (int ks = 0; ks < 2; ks++) {
            const int kcA = ks * 16 + acs, kcB = ks * 16 + bcs;
            uint32_t ah[4][4], al[4][4];
#pragma unroll
            for (int mt = 0; mt < 4; mt++) {
                ldmx4(smaddr(&Ash[(arlr + mt * 16) * GSH + kcA]), ah[mt]);
                ldmx4(smaddr(&Asl[(arlr + mt * 16) * GSH + kcA]), al[mt]);
            }
#pragma unroll
            for (int nt = 0; nt < 4; nt++) {
                uint32_t bh[2], bl[2];
                ldmx2(smaddr(&Bsh[(brlr + nt * 8) * GSH + kcB]), bh);
                if (TERMS == 3)
                    ldmx2(smaddr(&Bsl[(brlr + nt * 8) * GSH + kcB]), bl);
#pragma unroll
                for (int mt = 0; mt < 4; mt++) {
                    mma16816(acc[mt][nt], ah[mt], bh);
                    mma16816(acc[mt][nt], al[mt], bh);
                    if (TERMS == 3)
                        mma16816(acc[mt][nt], ah[mt], bl);
                }
            }
        }
    }

    const int er = m0 + wm * 64 + (lane >> 2);
    const int ec = n0 + wn * 32 + 2 * (lane & 3);
#pragma unroll
    for (int mt = 0; mt < 4; mt++)
#pragma unroll
        for (int nt = 0; nt < 4; nt++) {
            int col = ec + nt * 8;
#pragma unroll
            for (int hf = 0; hf < 2; hf++) {
                int   row = er + mt * 16 + hf * 8;
                float v0 = acc[mt][nt][hf * 2], v1 = acc[mt][nt][hf * 2 + 1];
                if (modeOut == 0) {
                    int bb = row / MrowsPerB, mm = row - bb * MrowsPerB;
                    int hh = col >> 6, dd = col & 63;
                    size_t p = (((size_t)(bb * Hh + hh)) * MrowsPerB + mm) * Dh + dd;
                    __half h0 = __float2half_rn(v0), h1 = __float2half_rn(v1);
                    *(__half2*)(outH + p) = __halves2half2(h0, h1);
                    if (outL)
                        *(__half2*)(outL + p) = __halves2half2(
                            __float2half_rn(v0 - __half2float(h0)),
                            __float2half_rn(v1 - __half2float(h1)));
                } else {
                    *(float2*)(outF + (size_t)row * Cdim + col) = make_float2(v0, v1);
                }
            }
        }
}

// ---------------- Flash attention v3 ----------------------------------------------
// 64 q-rows/block, 64 kv/tile, double-buffered cp.async (Kh,Kl,Vh,mask).
// Register softmax; warp-PAIR barriers for the two softmax exchanges (block sync
// only once per tile, for the cp.async tile arrival). PV = P·Vh (1 mma).
#define ASTR 72
#define MPAD 80
#define TSZ  (64 * ASTR)            // halves
#define MSZ  (64 * MPAD)            // bytes
#define ATT_SMEM_BYTES (8 * TSZ * 2 + 2 * MSZ + TSZ * 2 + 2 * 128 * 4)

__global__ __launch_bounds__(256, 2) void attn_mma(
    const __half* __restrict__ qhg, const __half* __restrict__ qlg,
    const __half* __restrict__ khg, const __half* __restrict__ klg,
    const __half* __restrict__ vhg,
    const unsigned char* __restrict__ m8a, const unsigned char* __restrict__ m8b,
    __half* __restrict__ yh, __half* __restrict__ yl)
{
    extern __shared__ __half sh[];
    __half* Qh = sh;
    __half* Ql = sh + TSZ;
    __half* Kb = sh + 2 * TSZ;                       // 2 stages x (h,l)
    __half* Vb = sh + 6 * TSZ;                       // 2 stages x h
    unsigned char* Mb = (unsigned char*)(sh + 8 * TSZ);
    __half* Ph = (__half*)(Mb + 2 * MSZ);
    float*  pm = (float*)(Ph + TSZ);                 // [8][16]
    float*  ps = pm + 8 * 16;

    const int tid = threadIdx.x, lane = tid & 31, w = tid >> 5;
    const int wq = w >> 1, wk = w & 1;
    const int pb = 1 + (w >> 1);                     // pair barrier id 1..4
    const int b = blockIdx.z, h = blockIdx.y, qt = blockIdx.x;
    const unsigned char* mg = (g_maskmode == 0) ? m8a : m8b;

    const size_t kvo    = ((size_t)(b * Hh + h)) * NKT * Dh;
    const size_t mbase0 = ((size_t)b * NT + (size_t)qt * 64) * NKT;

    auto loadStage = [&](int kt, int st) {
        __half* Khp = Kb + st * 2 * TSZ;
        __half* Klp = Khp + TSZ;
        __half* Vhp = Vb + st * TSZ;
#pragma unroll
        for (int i = 0; i < 2; i++) {
            int pos = tid + i * 256;
            int r = pos >> 3, cc = (pos & 7) * 8;
            size_t go = kvo + (size_t)(kt * 64 + r) * Dh + cc;
            uint32_t so = r * ASTR + cc;
            cpa16(smaddr(Khp + so), khg + go);
            cpa16(smaddr(Klp + so), klg + go);
            cpa16(smaddr(Vhp + so), vhg + go);
        }
        {
            int r = tid >> 2, cs = (tid & 3) * 16;
            cpa16(smaddr(Mb + st * MSZ + r * MPAD + cs),
                  mg + mbase0 + (size_t)r * NKT + (size_t)kt * 64 + cs);
        }
    };

    // prologue: Q + stage 0
    {
        const size_t qo = (((size_t)(b * Hh + h)) * NT + qt * 64) * Dh;
#pragma unroll
        for (int i = 0; i < 2; i++) {
            int pos = tid + i * 256;
            int r = pos >> 3, cc = (pos & 7) * 8;
            cpa16(smaddr(Qh + r * ASTR + cc), qhg + qo + r * Dh + cc);
            cpa16(smaddr(Ql + r * ASTR + cc), qlg + qo + r * Dh + cc);
        }
        loadStage(0, 0);
        cpcommit();
    }
    cpwait0(); __syncthreads();

    uint32_t qf[4][2][4];
    {
        const int rl = wq * 16 + (lane & 15);
        const int cs = (lane >> 4) * 8;
#pragma unroll
        for (int kc = 0; kc < 4; kc++) {
            ldmx4(smaddr(&Qh[rl * ASTR + kc * 16 + cs]), qf[kc][0]);
            ldmx4(smaddr(&Ql[rl * ASTR + kc * 16 + cs]), qf[kc][1]);
        }
    }

    float oacc[4][4];
#pragma unroll
    for (int nt = 0; nt < 4; nt++)
#pragma unroll
        for (int q = 0; q < 4; q++) oacc[nt][q] = 0.f;
    float m_reg[2] = {-1e30f, -1e30f};
    float l_reg[2] = {0.f, 0.f};

    const int rg  = lane >> 2;
    const int mr0 = wq * 16 + rg;
    const int mr1 = mr0 + 8;
    const float SCL = 0.125f * 1.44269504f;

    for (int kt = 0; kt < NKT / 64; kt++) {
        const int st = kt & 1;
        if (kt > 0) { cpwait0(); __syncthreads(); }
        if (kt + 1 < NKT / 64) { loadStage(kt + 1, st ^ 1); cpcommit(); }

        __half* Khp = Kb + st * 2 * TSZ;
        __half* Klp = Khp + TSZ;
        __half* Vhp = Vb + st * TSZ;
        unsigned char* Mp = Mb + st * MSZ;

        // --- S = Q K^T (3-term) ---
        float sacc[4][4];
#pragma unroll
        for (int nt = 0; nt < 4; nt++)
#pragma unroll
            for (int q = 0; q < 4; q++) sacc[nt][q] = 0.f;
        {
            const int brl = wk * 32 + (lane & 7);
            const int bcs = ((lane >> 3) & 1) * 8;
#pragma unroll
            for (int kc = 0; kc < 4; kc++) {
#pragma unroll
                for (int nt = 0; nt < 4; nt++) {
                    uint32_t bh[2], bl[2];
                    ldmx2(smaddr(&Khp[(brl + nt * 8) * ASTR + kc * 16 + bcs]), bh);
                    ldmx2(smaddr(&Klp[(brl + nt * 8) * ASTR + kc * 16 + bcs]), bl);
                    mma16816(sacc[nt], qf[kc][0], bh);
                    mma16816(sacc[nt], qf[kc][1], bh);
                    mma16816(sacc[nt], qf[kc][0], bl);
                }
            }
        }

        // --- mask + scale, row max (4-lane shfl + pair exchange) ---
        float t0[8], t1[8];
        float rm0 = -1e30f, rm1 = -1e30f;
#pragma unroll
        for (int nt = 0; nt < 4; nt++) {
            const int colb = wk * 32 + nt * 8 + (lane & 3) * 2;
            uint16_t w0 = *(const uint16_t*)&Mp[mr0 * MPAD + colb];
            uint16_t w1 = *(const uint16_t*)&Mp[mr1 * MPAD + colb];
            t0[nt * 2 + 0] = (w0 & 0xff) ? -1e30f : sacc[nt][0] * SCL;
            t0[nt * 2 + 1] = (w0 >> 8)   ? -1e30f : sacc[nt][1] * SCL;
            t1[nt * 2 + 0] = (w1 & 0xff) ? -1e30f : sacc[nt][2] * SCL;
            t1[nt * 2 + 1] = (w1 >> 8)   ? -1e30f : sacc[nt][3] * SCL;
            rm0 = fmaxf(rm0, fmaxf(t0[nt * 2], t0[nt * 2 + 1]));
            rm1 = fmaxf(rm1, fmaxf(t1[nt * 2], t1[nt * 2 + 1]));
        }
        rm0 = fmaxf(rm0, __shfl_xor_sync(0xffffffffu, rm0, 1));
        rm0 = fmaxf(rm0, __shfl_xor_sync(0xffffffffu, rm0, 2));
        rm1 = fmaxf(rm1, __shfl_xor_sync(0xffffffffu, rm1, 1));
        rm1 = fmaxf(rm1, __shfl_xor_sync(0xffffffffu, rm1, 2));
        if ((lane & 3) == 0) { pm[w * 16 + rg] = rm0; pm[w * 16 + rg + 8] = rm1; }
        pairbar(pb);
        float mn0 = fmaxf(m_reg[0], fmaxf(rm0, pm[(w ^ 1) * 16 + rg]));
        float mn1 = fmaxf(m_reg[1], fmaxf(rm1, pm[(w ^ 1) * 16 + rg + 8]));
        float cf0 = ex2f(m_reg[0] - mn0);
        float cf1 = ex2f(m_reg[1] - mn1);

        // --- exp, P store, row sum ---
        float rs0 = 0.f, rs1 = 0.f;
#pragma unroll
        for (int nt = 0; nt < 4; nt++) {
            const int colb = wk * 32 + nt * 8 + (lane & 3) * 2;
            float p00 = ex2f(t0[nt * 2] - mn0), p01 = ex2f(t0[nt * 2 + 1] - mn0);
            float p10 = ex2f(t1[nt * 2] - mn1), p11 = ex2f(t1[nt * 2 + 1] - mn1);
            rs0 += p00 + p01; rs1 += p10 + p11;
            *(__half2*)&Ph[mr0 * ASTR + colb] =
                __halves2half2(__float2half_rn(p00), __float2half_rn(p01));
            *(__half2*)&Ph[mr1 * ASTR + colb] =
                __halves2half2(__float2half_rn(p10), __float2half_rn(p11));
        }
        rs0 += __shfl_xor_sync(0xffffffffu, rs0, 1);
        rs0 += __shfl_xor_sync(0xffffffffu, rs0, 2);
        rs1 += __shfl_xor_sync(0xffffffffu, rs1, 1);
        rs1 += __shfl_xor_sync(0xffffffffu, rs1, 2);
        if ((lane & 3) == 0) { ps[w * 16 + rg] = rs0; ps[w * 16 + rg + 8] = rs1; }

        // rescale O while the partner finishes
#pragma unroll
        for (int nt = 0; nt < 4; nt++) {
            oacc[nt][0] *= cf0; oacc[nt][1] *= cf0;
            oacc[nt][2] *= cf1; oacc[nt][3] *= cf1;
        }
        pairbar(pb);
        l_reg[0] = l_reg[0] * cf0 + rs0 + ps[(w ^ 1) * 16 + rg];
        l_reg[1] = l_reg[1] * cf1 + rs1 + ps[(w ^ 1) * 16 + rg + 8];
        m_reg[0] = mn0; m_reg[1] = mn1;

        // --- O += P Vh ---
        {
            const int prl = wq * 16 + (lane & 15);
            const int pcs = (lane >> 4) * 8;
            const int vrl = lane & 15;
#pragma unroll
            for (int kc = 0; kc < 4; kc++) {
                uint32_t pfh[4];
                ldmx4(smaddr(&Ph[prl * ASTR + kc * 16 + pcs]), pfh);
#pragma unroll
                for (int nt = 0; nt < 4; nt++) {
                    uint32_t vh[2];
                    ldmx2t(smaddr(&Vhp[(kc * 16 + vrl) * ASTR + wk * 32 + nt * 8]), vh);
                    mma16816(oacc[nt], pfh, vh);
                }
            }
        }
    }

    // --- epilogue ---
    {
        float i0 = (l_reg[0] > 0.f) ? 1.f / l_reg[0] : 0.f;
        float i1 = (l_reg[1] > 0.f) ? 1.f / l_reg[1] : 0.f;
        const int c0 = h * 64 + wk * 32 + 2 * (lane & 3);
        size_t o0 = ((size_t)b * NT + qt * 64 + mr0) * Cdim + c0;
        size_t o1 = ((size_t)b * NT + qt * 64 + mr1) * Cdim + c0;
#pragma unroll
        for (int nt = 0; nt < 4; nt++) {
            float a0 = oacc[nt][0] * i0, a1 = oacc[nt][1] * i0;
            float b0 = oacc[nt][2] * i1, b1 = oacc[nt][3] * i1;
            __half ha0 = __float2half_rn(a0), ha1 = __float2half_rn(a1);
            __half hb0 = __float2half_rn(b0), hb1 = __float2half_rn(b1);
            *(__half2*)(yh + o0 + nt * 8) = __halves2half2(ha0, ha1);
            *(__half2*)(yl + o0 + nt * 8) = __halves2half2(
                __float2half_rn(a0 - __half2float(ha0)),
                __float2half_rn(a1 - __half2float(ha1)));
            *(__half2*)(yh + o1 + nt * 8) = __halves2half2(hb0, hb1);
            *(__half2*)(yl + o1 + nt * 8) = __halves2half2(
                __float2half_rn(b0 - __half2float(hb0)),
                __float2half_rn(b1 - __half2float(hb1)));
        }
    }
}

// ---------------- launch ------------------------------------------------------------
extern "C" void kernel_launch(void* const* d_in, const int* in_sizes, int n_in,
                              void* d_out, int out_size)
{
    const float* x  = (const float*)d_in[0];
    const float* c  = (const float*)d_in[1];
    const void*  mk = d_in[2];
    const float* Wq = (const float*)d_in[3];
    const float* Wk = (const float*)d_in[4];
    const float* Wv = (const float*)d_in[5];
    const float* Wp = (const float*)d_in[6];
    float* out = (float*)d_out;

    __half *xh, *xl, *ch_, *cl_, *wqh, *wql, *wkh, *wkl, *wvh, *wvl, *wph, *wpl;
    __half *qh, *ql, *kh, *kl, *vh, *yh, *yl;
    unsigned char* m8;
    cudaGetSymbolAddress((void**)&xh,  g_xh);  cudaGetSymbolAddress((void**)&xl,  g_xl);
    cudaGetSymbolAddress((void**)&ch_, g_ch);  cudaGetSymbolAddress((void**)&cl_, g_cl);
    cudaGetSymbolAddress((void**)&wqh, g_wqh); cudaGetSymbolAddress((void**)&wql, g_wql);
    cudaGetSymbolAddress((void**)&wkh, g_wkh); cudaGetSymbolAddress((void**)&wkl, g_wkl);
    cudaGetSymbolAddress((void**)&wvh, g_wvh); cudaGetSymbolAddress((void**)&wvl, g_wvl);
    cudaGetSymbolAddress((void**)&wph, g_wph); cudaGetSymbolAddress((void**)&wpl, g_wpl);
    cudaGetSymbolAddress((void**)&qh,  g_qh);  cudaGetSymbolAddress((void**)&ql,  g_ql);
    cudaGetSymbolAddress((void**)&kh,  g_kh);  cudaGetSymbolAddress((void**)&kl,  g_kl);
    cudaGetSymbolAddress((void**)&vh,  g_vh);
    cudaGetSymbolAddress((void**)&yh,  g_yh);  cudaGetSymbolAddress((void**)&yl,  g_yl);
    cudaGetSymbolAddress((void**)&m8,  g_m8);

    cudaFuncSetAttribute(gemm_mma<3>, cudaFuncAttributeMaxDynamicSharedMemorySize,
                         GEMM_SMEM_BYTES);
    cudaFuncSetAttribute(gemm_mma<2>, cudaFuncAttributeMaxDynamicSharedMemorySize,
                         GEMM_SMEM_BYTES);
    cudaFuncSetAttribute(attn_mma, cudaFuncAttributeMaxDynamicSharedMemorySize,
                         ATT_SMEM_BYTES);

    detect_mask_mode<<<1, 256>>>((const unsigned char*)mk);
    mask_to_u8<<<(Bc * NT * NKT) / (256 * 16), 256>>>(mk, m8);

    const int nx = Bc * NT * Cdim;
    const int nw = Cdim * Cdim;
    split_f32<<<nx / 1024, 256>>>(x,  xh,  xl,  nx);
    split_f32<<<nx / 1024, 256>>>(c,  ch_, cl_, nx);
    split_f32<<<nw / 1024, 256>>>(Wq, wqh, wql, nw);
    split_f32<<<nw / 1024, 256>>>(Wk, wkh, wkl, nw);
    split_f32<<<nw / 1024, 256>>>(Wv, wvh, wvl, nw);
    split_f32<<<nw / 1024, 256>>>(Wp, wph, wpl, nw);

    gemm_mma<3><<<dim3(Cdim / 128, Bc * NT  / 128), 256, GEMM_SMEM_BYTES>>>(
        xh, xl, nullptr, nullptr, wqh, wql, nullptr, qh, ql, NT,  0, 0);
    gemm_mma<3><<<dim3(Cdim / 128, Bc * NKT / 128), 256, GEMM_SMEM_BYTES>>>(
        xh, xl, ch_, cl_,         wkh, wkl, nullptr, kh, kl, NKT, 1, 0);
    gemm_mma<2><<<dim3(Cdim / 128, Bc * NKT / 128), 256, GEMM_SMEM_BYTES>>>(
        xh, xl, ch_, cl_,         wvh, wvl, nullptr, vh, nullptr, NKT, 1, 0);

    attn_mma<<<dim3(NT / 64, Hh, Bc), 256, ATT_SMEM_BYTES>>>(
        qh, ql, kh, kl, vh, (const unsigned char*)mk, m8, yh, yl);

    gemm_mma<3><<<dim3(Cdim / 128, Bc * NT / 128), 256, GEMM_SMEM_BYTES>>>(
        yh, yl, nullptr, nullptr, wph, wpl, out, nullptr, nullptr, NT, 0, 1);
}

// round 10
// speedup vs baseline: 5.3575x; 1.2196x over previous
#include <cuda_runtime.h>
#include <cuda_fp16.h>
#include <stdint.h>

#define Bc   8
#define Hh   8
#define NT   1024
#define NKT  2048
#define Cdim 512
#define Dh   64

// ---------------- scratch (no allocation allowed) ------------------------------
__device__ __half g_xh[(size_t)Bc * NT * Cdim],  g_xl[(size_t)Bc * NT * Cdim];
__device__ __half g_ch[(size_t)Bc * NT * Cdim],  g_cl[(size_t)Bc * NT * Cdim];
__device__ __half g_wqh[Cdim * Cdim], g_wql[Cdim * Cdim];
__device__ __half g_wkh[Cdim * Cdim], g_wkl[Cdim * Cdim];
__device__ __half g_wvh[Cdim * Cdim], g_wvl[Cdim * Cdim];
__device__ __half g_wph[Cdim * Cdim], g_wpl[Cdim * Cdim];
__device__ __half g_qh[(size_t)Bc * Hh * NT  * Dh];
__device__ __half g_kh[(size_t)Bc * Hh * NKT * Dh];
__device__ __half g_vh[(size_t)Bc * Hh * NKT * Dh];
__device__ __half g_yh[(size_t)Bc * NT * Cdim], g_yl[(size_t)Bc * NT * Cdim];
__device__ unsigned char g_m8[(size_t)Bc * NT * NKT];
__device__ int    g_maskmode;

// ---------------- helpers -------------------------------------------------------
__device__ __forceinline__ uint32_t smaddr(const void* p) {
    return (uint32_t)__cvta_generic_to_shared(p);
}
__device__ __forceinline__ void cpa16(uint32_t d, const void* s) {
    asm volatile("cp.async.ca.shared.global [%0], [%1], 16;" :: "r"(d), "l"(s));
}
__device__ __forceinline__ void cpcommit() { asm volatile("cp.async.commit_group;"); }
__device__ __forceinline__ void cpwait0()  { asm volatile("cp.async.wait_group 0;"); }

__device__ __forceinline__ void ldmx4(uint32_t a, uint32_t* r) {
    asm volatile("ldmatrix.sync.aligned.m8n8.x4.shared.b16 {%0,%1,%2,%3}, [%4];"
                 : "=r"(r[0]), "=r"(r[1]), "=r"(r[2]), "=r"(r[3]) : "r"(a));
}
__device__ __forceinline__ void ldmx2(uint32_t a, uint32_t* r) {
    asm volatile("ldmatrix.sync.aligned.m8n8.x2.shared.b16 {%0,%1}, [%2];"
                 : "=r"(r[0]), "=r"(r[1]) : "r"(a));
}
__device__ __forceinline__ void ldmx2t(uint32_t a, uint32_t* r) {
    asm volatile("ldmatrix.sync.aligned.m8n8.x2.trans.shared.b16 {%0,%1}, [%2];"
                 : "=r"(r[0]), "=r"(r[1]) : "r"(a));
}
__device__ __forceinline__ void mma16816(float* c, const uint32_t* a, const uint32_t* b) {
    asm volatile("mma.sync.aligned.m16n8k16.row.col.f32.f16.f16.f32 "
                 "{%0,%1,%2,%3},{%4,%5,%6,%7},{%8,%9},{%0,%1,%2,%3};"
                 : "+f"(c[0]), "+f"(c[1]), "+f"(c[2]), "+f"(c[3])
                 : "r"(a[0]), "r"(a[1]), "r"(a[2]), "r"(a[3]), "r"(b[0]), "r"(b[1]));
}
__device__ __forceinline__ float ex2f(float x) {
    float y; asm("ex2.approx.f32 %0, %1;" : "=f"(y) : "f"(x)); return y;
}
__device__ __forceinline__ void pairbar(int id) {
    asm volatile("bar.sync %0, 64;" :: "r"(id) : "memory");
}

// ---------------- prep kernels ---------------------------------------------------
__global__ void split_f32(const float* __restrict__ s, __half* __restrict__ h,
                          __half* __restrict__ l, int n)
{
    int i = (blockIdx.x * blockDim.x + threadIdx.x) * 4;
    if (i >= n) return;
    float4 v = *(const float4*)(s + i);
    __half hx = __float2half_rn(v.x), hy = __float2half_rn(v.y);
    __half hz = __float2half_rn(v.z), hw = __float2half_rn(v.w);
    *(__half2*)(h + i)     = __halves2half2(hx, hy);
    *(__half2*)(h + i + 2) = __halves2half2(hz, hw);
    if (l) {
        *(__half2*)(l + i)     = __halves2half2(__float2half_rn(v.x - __half2float(hx)),
                                                __float2half_rn(v.y - __half2float(hy)));
        *(__half2*)(l + i + 2) = __halves2half2(__float2half_rn(v.z - __half2float(hz)),
                                                __float2half_rn(v.w - __half2float(hw)));
    }
}

__global__ void detect_mask_mode(const unsigned char* __restrict__ m) {
    bool hi = false, f3 = false;
    for (int i = threadIdx.x; i < 8192; i += blockDim.x) {
        unsigned char v = m[i];
        int p = i & 3;
        if (p == 3 && v == 0x3f) f3 = true;
        if (p != 0 && v != 0)    hi = true;
    }
    int a3 = __syncthreads_or(f3 ? 1 : 0);
    int ah = __syncthreads_or(hi ? 1 : 0);
    if (threadIdx.x == 0) g_maskmode = a3 ? 2 : (ah ? 0 : 1);
}

__global__ void mask_to_u8(const void* __restrict__ mp, unsigned char* __restrict__ o) {
    int mode = g_maskmode;
    if (mode == 0) return;
    size_t i = ((size_t)blockIdx.x * blockDim.x + threadIdx.x) * 16;
    if (mode == 1) {
        const int* ip = (const int*)mp + i;
        int4 v0 = *(const int4*)(ip + 0),  v1 = *(const int4*)(ip + 4);
        int4 v2 = *(const int4*)(ip + 8),  v3 = *(const int4*)(ip + 12);
        *(uchar4*)(o + i)      = make_uchar4(v0.x != 0, v0.y != 0, v0.z != 0, v0.w != 0);
        *(uchar4*)(o + i + 4)  = make_uchar4(v1.x != 0, v1.y != 0, v1.z != 0, v1.w != 0);
        *(uchar4*)(o + i + 8)  = make_uchar4(v2.x != 0, v2.y != 0, v2.z != 0, v2.w != 0);
        *(uchar4*)(o + i + 12) = make_uchar4(v3.x != 0, v3.y != 0, v3.z != 0, v3.w != 0);
    } else {
        const float* fp = (const float*)mp + i;
#pragma unroll
        for (int q = 0; q < 4; q++) {
            float4 v = *(const float4*)(fp + q * 4);
            *(uchar4*)(o + i + q * 4) =
                make_uchar4(v.x != 0.f, v.y != 0.f, v.z != 0.f, v.w != 0.f);
        }
    }
}

// ---------------- GEMM: Y = A @ W^T (split-fp16, TERMS mma, cp.async 2-stage) ----
#define GKT 32
#define GSH 40
#define GSZ (128 * GSH)
#define GEMM_SMEM_BYTES (2 * 4 * GSZ * 2)

template <int TERMS>
__global__ __launch_bounds__(256, 2) void gemm_mma(
    const __half* __restrict__ Ah0, const __half* __restrict__ Al0,
    const __half* __restrict__ Ah1, const __half* __restrict__ Al1,
    const __half* __restrict__ Wh,  const __half* __restrict__ Wl,
    float* __restrict__ outF, __half* __restrict__ outH, __half* __restrict__ outL,
    int MrowsPerB, int modeIn, int modeOut)
{
    extern __shared__ __half gs[];
    const int tid = threadIdx.x, lane = tid & 31, w = tid >> 5;
    const int wm = w >> 2, wn = w & 3;
    const int m0 = blockIdx.y * 128, n0 = blockIdx.x * 128;
    const int lrow = tid >> 2;
    const int lch  = (tid & 3) * 8;

    const __half *arh[2], *arl[2], *brh[2], *brl[2];
#pragma unroll
    for (int p = 0; p < 2; p++) {
        int r = lrow + p * 64, gm = m0 + r;
        int bb = gm / MrowsPerB, mm = gm - bb * MrowsPerB;
        size_t off;
        if (modeIn == 0 || mm < NT) {
            off = ((size_t)bb * NT + mm) * Cdim; arh[p] = Ah0 + off; arl[p] = Al0 + off;
        } else {
            off = ((size_t)bb * NT + (mm - NT)) * Cdim; arh[p] = Ah1 + off; arl[p] = Al1 + off;
        }
        size_t wo = (size_t)(n0 + r) * Cdim;
        brh[p] = Wh + wo; brl[p] = Wl + wo;
    }

    float acc[4][4][4];
#pragma unroll
    for (int a = 0; a < 4; a++)
#pragma unroll
        for (int b2 = 0; b2 < 4; b2++)
#pragma unroll
            for (int q = 0; q < 4; q++) acc[a][b2][q] = 0.f;

    const int arlr = wm * 64 + (lane & 15);
    const int acs  = (lane >> 4) * 8;
    const int brlr = wn * 32 + (lane & 7);
    const int bcs  = ((lane >> 3) & 1) * 8;

    auto loadStage = [&](int st, int k0) {
        __half* b = gs + st * 4 * GSZ;
        const uint32_t d0 = (uint32_t)(lrow * GSH + lch);
#pragma unroll
        for (int p = 0; p < 2; p++) {
            uint32_t d = d0 + p * 64 * GSH;
            cpa16(smaddr(b + d),           arh[p] + k0 + lch);
            cpa16(smaddr(b + GSZ + d),     arl[p] + k0 + lch);
            cpa16(smaddr(b + 2 * GSZ + d), brh[p] + k0 + lch);
            if (TERMS == 3)
                cpa16(smaddr(b + 3 * GSZ + d), brl[p] + k0 + lch);
        }
    };

    loadStage(0, 0); cpcommit();
    const int NTILES = Cdim / GKT;
    for (int t = 0; t < NTILES; t++) {
        cpwait0(); __syncthreads();
        if (t + 1 < NTILES) { loadStage((t + 1) & 1, (t + 1) * GKT); cpcommit(); }

        __half* Ash = gs + (t & 1) * 4 * GSZ;
        __half* Asl = Ash + GSZ;
        __half* Bsh = Ash + 2 * GSZ;
        __half* Bsl = Ash + 3 * GSZ;
#pragma unroll
        for (int ks = 0; ks < 2; ks++) {
            const int kcA = ks * 16 + acs, kcB = ks * 16 + bcs;
            uint32_t ah[4][4], al[4][4];
#pragma unroll
            for (int mt = 0; mt < 4; mt++) {
                ldmx4(smaddr(&Ash[(arlr + mt * 16) * GSH + kcA]), ah[mt]);
                ldmx4(smaddr(&Asl[(arlr + mt * 16) * GSH + kcA]), al[mt]);
            }
#pragma unroll
            for (int nt = 0; nt < 4; nt++) {
                uint32_t bh[2], bl[2];
                ldmx2(smaddr(&Bsh[(brlr + nt * 8) * GSH + kcB]), bh);
                if (TERMS == 3)
                    ldmx2(smaddr(&Bsl[(brlr + nt * 8) * GSH + kcB]), bl);
#pragma unroll
                for (int mt = 0; mt < 4; mt++) {
                    mma16816(acc[mt][nt], ah[mt], bh);
                    mma16816(acc[mt][nt], al[mt], bh);
                    if (TERMS == 3)
                        mma16816(acc[mt][nt], ah[mt], bl);
                }
            }
        }
    }

    const int er = m0 + wm * 64 + (lane >> 2);
    const int ec = n0 + wn * 32 + 2 * (lane & 3);
#pragma unroll
    for (int mt = 0; mt < 4; mt++)
#pragma unroll
        for (int nt = 0; nt < 4; nt++) {
            int col = ec + nt * 8;
#pragma unroll
            for (int hf = 0; hf < 2; hf++) {
                int   row = er + mt * 16 + hf * 8;
                float v0 = acc[mt][nt][hf * 2], v1 = acc[mt][nt][hf * 2 + 1];
                if (modeOut == 0) {
                    int bb = row / MrowsPerB, mm = row - bb * MrowsPerB;
                    int hh = col >> 6, dd = col & 63;
                    size_t p = (((size_t)(bb * Hh + hh)) * MrowsPerB + mm) * Dh + dd;
                    __half h0 = __float2half_rn(v0), h1 = __float2half_rn(v1);
                    *(__half2*)(outH + p) = __halves2half2(h0, h1);
                    if (outL)
                        *(__half2*)(outL + p) = __halves2half2(
                            __float2half_rn(v0 - __half2float(h0)),
                            __float2half_rn(v1 - __half2float(h1)));
                } else {
                    *(float2*)(outF + (size_t)row * Cdim + col) = make_float2(v0, v1);
                }
            }
        }
}

// ---------------- Flash attention v4 (1-term S, 1-term PV) -------------------------
// 64 q-rows/block, 64 kv/tile, double-buffered cp.async (Kh, Vh, mask).
// Register softmax, warp-pair barriers; S = Qh*Kh^T, PV = P*Vh.
#define ASTR 72
#define MPAD 80
#define TSZ  (64 * ASTR)            // halves
#define MSZ  (64 * MPAD)            // bytes
#define ATT_SMEM_BYTES (6 * TSZ * 2 + 2 * MSZ + 2 * 128 * 4)

__global__ __launch_bounds__(256, 2) void attn_mma(
    const __half* __restrict__ qhg, const __half* __restrict__ khg,
    const __half* __restrict__ vhg,
    const unsigned char* __restrict__ m8a, const unsigned char* __restrict__ m8b,
    __half* __restrict__ yh, __half* __restrict__ yl)
{
    extern __shared__ __half sh[];
    __half* Qh = sh;                                 // 1 tile
    __half* Kb = sh + TSZ;                           // 2 stages
    __half* Vb = sh + 3 * TSZ;                       // 2 stages
    unsigned char* Mb = (unsigned char*)(sh + 5 * TSZ);
    __half* Ph = (__half*)(Mb + 2 * MSZ);
    float*  pm = (float*)(Ph + TSZ);                 // [8][16]
    float*  ps = pm + 8 * 16;

    const int tid = threadIdx.x, lane = tid & 31, w = tid >> 5;
    const int wq = w >> 1, wk = w & 1;
    const int pb = 1 + (w >> 1);
    const int b = blockIdx.z, h = blockIdx.y, qt = blockIdx.x;
    const unsigned char* mg = (g_maskmode == 0) ? m8a : m8b;

    const size_t kvo    = ((size_t)(b * Hh + h)) * NKT * Dh;
    const size_t mbase0 = ((size_t)b * NT + (size_t)qt * 64) * NKT;

    auto loadStage = [&](int kt, int st) {
        __half* Khp = Kb + st * TSZ;
        __half* Vhp = Vb + st * TSZ;
#pragma unroll
        for (int i = 0; i < 2; i++) {
            int pos = tid + i * 256;
            int r = pos >> 3, cc = (pos & 7) * 8;
            size_t go = kvo + (size_t)(kt * 64 + r) * Dh + cc;
            uint32_t so = r * ASTR + cc;
            cpa16(smaddr(Khp + so), khg + go);
            cpa16(smaddr(Vhp + so), vhg + go);
        }
        {
            int r = tid >> 2, cs = (tid & 3) * 16;
            cpa16(smaddr(Mb + st * MSZ + r * MPAD + cs),
                  mg + mbase0 + (size_t)r * NKT + (size_t)kt * 64 + cs);
        }
    };

    // prologue
    {
        const size_t qo = (((size_t)(b * Hh + h)) * NT + qt * 64) * Dh;
#pragma unroll
        for (int i = 0; i < 2; i++) {
            int pos = tid + i * 256;
            int r = pos >> 3, cc = (pos & 7) * 8;
            cpa16(smaddr(Qh + r * ASTR + cc), qhg + qo + r * Dh + cc);
        }
        loadStage(0, 0);
        cpcommit();
    }
    cpwait0(); __syncthreads();

    uint32_t qf[4][4];
    {
        const int rl = wq * 16 + (lane & 15);
        const int cs = (lane >> 4) * 8;
#pragma unroll
        for (int kc = 0; kc < 4; kc++)
            ldmx4(smaddr(&Qh[rl * ASTR + kc * 16 + cs]), qf[kc]);
    }

    float oacc[4][4];
#pragma unroll
    for (int nt = 0; nt < 4; nt++)
#pragma unroll
        for (int q = 0; q < 4; q++) oacc[nt][q] = 0.f;
    float m_reg[2] = {-1e30f, -1e30f};
    float l_reg[2] = {0.f, 0.f};

    const int rg  = lane >> 2;
    const int mr0 = wq * 16 + rg;
    const int mr1 = mr0 + 8;
    const float SCL = 0.125f * 1.44269504f;

    for (int kt = 0; kt < NKT / 64; kt++) {
        const int st = kt & 1;
        if (kt > 0) { cpwait0(); __syncthreads(); }
        if (kt + 1 < NKT / 64) { loadStage(kt + 1, st ^ 1); cpcommit(); }

        __half* Khp = Kb + st * TSZ;
        __half* Vhp = Vb + st * TSZ;
        unsigned char* Mp = Mb + st * MSZ;

        // --- S = Qh Kh^T ---
        float sacc[4][4];
#pragma unroll
        for (int nt = 0; nt < 4; nt++)
#pragma unroll
            for (int q = 0; q < 4; q++) sacc[nt][q] = 0.f;
        {
            const int brl = wk * 32 + (lane & 7);
            const int bcs = ((lane >> 3) & 1) * 8;
#pragma unroll
            for (int kc = 0; kc < 4; kc++) {
#pragma unroll
                for (int nt = 0; nt < 4; nt++) {
                    uint32_t bh[2];
                    ldmx2(smaddr(&Khp[(brl + nt * 8) * ASTR + kc * 16 + bcs]), bh);
                    mma16816(sacc[nt], qf[kc], bh);
                }
            }
        }

        // --- mask + scale, row max ---
        float t0[8], t1[8];
        float rm0 = -1e30f, rm1 = -1e30f;
#pragma unroll
        for (int nt = 0; nt < 4; nt++) {
            const int colb = wk * 32 + nt * 8 + (lane & 3) * 2;
            uint16_t w0 = *(const uint16_t*)&Mp[mr0 * MPAD + colb];
            uint16_t w1 = *(const uint16_t*)&Mp[mr1 * MPAD + colb];
            t0[nt * 2 + 0] = (w0 & 0xff) ? -1e30f : sacc[nt][0] * SCL;
            t0[nt * 2 + 1] = (w0 >> 8)   ? -1e30f : sacc[nt][1] * SCL;
            t1[nt * 2 + 0] = (w1 & 0xff) ? -1e30f : sacc[nt][2] * SCL;
            t1[nt * 2 + 1] = (w1 >> 8)   ? -1e30f : sacc[nt][3] * SCL;
            rm0 = fmaxf(rm0, fmaxf(t0[nt * 2], t0[nt * 2 + 1]));
            rm1 = fmaxf(rm1, fmaxf(t1[nt * 2], t1[nt * 2 + 1]));
        }
        rm0 = fmaxf(rm0, __shfl_xor_sync(0xffffffffu, rm0, 1));
        rm0 = fmaxf(rm0, __shfl_xor_sync(0xffffffffu, rm0, 2));
        rm1 = fmaxf(rm1, __shfl_xor_sync(0xffffffffu, rm1, 1));
        rm1 = fmaxf(rm1, __shfl_xor_sync(0xffffffffu, rm1, 2));
        if ((lane & 3) == 0) { pm[w * 16 + rg] = rm0; pm[w * 16 + rg + 8] = rm1; }
        pairbar(pb);
        float mn0 = fmaxf(m_reg[0], fmaxf(rm0, pm[(w ^ 1) * 16 + rg]));
        float mn1 = fmaxf(m_reg[1], fmaxf(rm1, pm[(w ^ 1) * 16 + rg + 8]));
        float cf0 = ex2f(m_reg[0] - mn0);
        float cf1 = ex2f(m_reg[1] - mn1);

        // --- exp, P store, row sum ---
        float rs0 = 0.f, rs1 = 0.f;
#pragma unroll
        for (int nt = 0; nt < 4; nt++) {
            const int colb = wk * 32 + nt * 8 + (lane & 3) * 2;
            float p00 = ex2f(t0[nt * 2] - mn0), p01 = ex2f(t0[nt * 2 + 1] - mn0);
            float p10 = ex2f(t1[nt * 2] - mn1), p11 = ex2f(t1[nt * 2 + 1] - mn1);
            rs0 += p00 + p01; rs1 += p10 + p11;
            *(__half2*)&Ph[mr0 * ASTR + colb] =
                __halves2half2(__float2half_rn(p00), __float2half_rn(p01));
            *(__half2*)&Ph[mr1 * ASTR + colb] =
                __halves2half2(__float2half_rn(p10), __float2half_rn(p11));
        }
        rs0 += __shfl_xor_sync(0xffffffffu, rs0, 1);
        rs0 += __shfl_xor_sync(0xffffffffu, rs0, 2);
        rs1 += __shfl_xor_sync(0xffffffffu, rs1, 1);
        rs1 += __shfl_xor_sync(0xffffffffu, rs1, 2);
        if ((lane & 3) == 0) { ps[w * 16 + rg] = rs0; ps[w * 16 + rg + 8] = rs1; }

#pragma unroll
        for (int nt = 0; nt < 4; nt++) {
            oacc[nt][0] *= cf0; oacc[nt][1] *= cf0;
            oacc[nt][2] *= cf1; oacc[nt][3] *= cf1;
        }
        pairbar(pb);
        l_reg[0] = l_reg[0] * cf0 + rs0 + ps[(w ^ 1) * 16 + rg];
        l_reg[1] = l_reg[1] * cf1 + rs1 + ps[(w ^ 1) * 16 + rg + 8];
        m_reg[0] = mn0; m_reg[1] = mn1;

        // --- O += P Vh ---
        {
            const int prl = wq * 16 + (lane & 15);
            const int pcs = (lane >> 4) * 8;
            const int vrl = lane & 15;
#pragma unroll
            for (int kc = 0; kc < 4; kc++) {
                uint32_t pfh[4];
                ldmx4(smaddr(&Ph[prl * ASTR + kc * 16 + pcs]), pfh);
#pragma unroll
                for (int nt = 0; nt < 4; nt++) {
                    uint32_t vh[2];
                    ldmx2t(smaddr(&Vhp[(kc * 16 + vrl) * ASTR + wk * 32 + nt * 8]), vh);
                    mma16816(oacc[nt], pfh, vh);
                }
            }
        }
    }

    // --- epilogue ---
    {
        float i0 = (l_reg[0] > 0.f) ? 1.f / l_reg[0] : 0.f;
        float i1 = (l_reg[1] > 0.f) ? 1.f / l_reg[1] : 0.f;
        const int c0 = h * 64 + wk * 32 + 2 * (lane & 3);
        size_t o0 = ((size_t)b * NT + qt * 64 + mr0) * Cdim + c0;
        size_t o1 = ((size_t)b * NT + qt * 64 + mr1) * Cdim + c0;
#pragma unroll
        for (int nt = 0; nt < 4; nt++) {
            float a0 = oacc[nt][0] * i0, a1 = oacc[nt][1] * i0;
            float b0 = oacc[nt][2] * i1, b1 = oacc[nt][3] * i1;
            __half ha0 = __float2half_rn(a0), ha1 = __float2half_rn(a1);
            __half hb0 = __float2half_rn(b0), hb1 = __float2half_rn(b1);
            *(__half2*)(yh + o0 + nt * 8) = __halves2half2(ha0, ha1);
            *(__half2*)(yl + o0 + nt * 8) = __halves2half2(
                __float2half_rn(a0 - __half2float(ha0)),
                __float2half_rn(a1 - __half2float(ha1)));
            *(__half2*)(yh + o1 + nt * 8) = __halves2half2(hb0, hb1);
            *(__half2*)(yl + o1 + nt * 8) = __halves2half2(
                __float2half_rn(b0 - __half2float(hb0)),
                __float2half_rn(b1 - __half2float(hb1)));
        }
    }
}

// ---------------- launch ------------------------------------------------------------
extern "C" void kernel_launch(void* const* d_in, const int* in_sizes, int n_in,
                              void* d_out, int out_size)
{
    const float* x  = (const float*)d_in[0];
    const float* c  = (const float*)d_in[1];
    const void*  mk = d_in[2];
    const float* Wq = (const float*)d_in[3];
    const float* Wk = (const float*)d_in[4];
    const float* Wv = (const float*)d_in[5];
    const float* Wp = (const float*)d_in[6];
    float* out = (float*)d_out;

    __half *xh, *xl, *ch_, *cl_, *wqh, *wql, *wkh, *wkl, *wvh, *wvl, *wph, *wpl;
    __half *qh, *kh, *vh, *yh, *yl;
    unsigned char* m8;
    cudaGetSymbolAddress((void**)&xh,  g_xh);  cudaGetSymbolAddress((void**)&xl,  g_xl);
    cudaGetSymbolAddress((void**)&ch_, g_ch);  cudaGetSymbolAddress((void**)&cl_, g_cl);
    cudaGetSymbolAddress((void**)&wqh, g_wqh); cudaGetSymbolAddress((void**)&wql, g_wql);
    cudaGetSymbolAddress((void**)&wkh, g_wkh); cudaGetSymbolAddress((void**)&wkl, g_wkl);
    cudaGetSymbolAddress((void**)&wvh, g_wvh); cudaGetSymbolAddress((void**)&wvl, g_wvl);
    cudaGetSymbolAddress((void**)&wph, g_wph); cudaGetSymbolAddress((void**)&wpl, g_wpl);
    cudaGetSymbolAddress((void**)&qh,  g_qh);
    cudaGetSymbolAddress((void**)&kh,  g_kh);
    cudaGetSymbolAddress((void**)&vh,  g_vh);
    cudaGetSymbolAddress((void**)&yh,  g_yh);  cudaGetSymbolAddress((void**)&yl,  g_yl);
    cudaGetSymbolAddress((void**)&m8,  g_m8);

    cudaFuncSetAttribute(gemm_mma<3>, cudaFuncAttributeMaxDynamicSharedMemorySize,
                         GEMM_SMEM_BYTES);
    cudaFuncSetAttribute(gemm_mma<2>, cudaFuncAttributeMaxDynamicSharedMemorySize,
                         GEMM_SMEM_BYTES);
    cudaFuncSetAttribute(attn_mma, cudaFuncAttributeMaxDynamicSharedMemorySize,
                         ATT_SMEM_BYTES);

    detect_mask_mode<<<1, 256>>>((const unsigned char*)mk);
    mask_to_u8<<<(Bc * NT * NKT) / (256 * 16), 256>>>(mk, m8);

    const int nx = Bc * NT * Cdim;
    const int nw = Cdim * Cdim;
    split_f32<<<nx / 1024, 256>>>(x,  xh,  xl,  nx);
    split_f32<<<nx / 1024, 256>>>(c,  ch_, cl_, nx);
    split_f32<<<nw / 1024, 256>>>(Wq, wqh, nullptr, nw);
    split_f32<<<nw / 1024, 256>>>(Wk, wkh, nullptr, nw);
    split_f32<<<nw / 1024, 256>>>(Wv, wvh, nullptr, nw);
    split_f32<<<nw / 1024, 256>>>(Wp, wph, wpl, nw);

    // Q/K/V projections: 2-term (A exact, W fp16), hi-only outputs
    gemm_mma<2><<<dim3(Cdim / 128, Bc * NT  / 128), 256, GEMM_SMEM_BYTES>>>(
        xh, xl, nullptr, nullptr, wqh, wql, nullptr, qh, nullptr, NT,  0, 0);
    gemm_mma<2><<<dim3(Cdim / 128, Bc * NKT / 128), 256, GEMM_SMEM_BYTES>>>(
        xh, xl, ch_, cl_,         wkh, wkl, nullptr, kh, nullptr, NKT, 1, 0);
    gemm_mma<2><<<dim3(Cdim / 128, Bc * NKT / 128), 256, GEMM_SMEM_BYTES>>>(
        xh, xl, ch_, cl_,         wvh, wvl, nullptr, vh, nullptr, NKT, 1, 0);

    attn_mma<<<dim3(NT / 64, Hh, Bc), 256, ATT_SMEM_BYTES>>>(
        qh, kh, vh, (const unsigned char*)mk, m8, yh, yl);

    // output projection: full 3-term
    gemm_mma<3><<<dim3(Cdim / 128, Bc * NT / 128), 256, GEMM_SMEM_BYTES>>>(
        yh, yl, nullptr, nullptr, wph, wpl, out, nullptr, nullptr, NT, 0, 1);
}

// round 11
// speedup vs baseline: 5.7356x; 1.0706x over previous
#include <cuda_runtime.h>
#include <cuda_fp16.h>
#include <stdint.h>

#define Bc   8
#define Hh   8
#define NT   1024
#define NKT  2048
#define Cdim 512
#define Dh   64

// ---------------- scratch (no allocation allowed) ------------------------------
__device__ __half g_xh[(size_t)Bc * NT * Cdim],  g_xl[(size_t)Bc * NT * Cdim];
__device__ __half g_ch[(size_t)Bc * NT * Cdim],  g_cl[(size_t)Bc * NT * Cdim];
__device__ __half g_wqh[Cdim * Cdim], g_wql[Cdim * Cdim];
__device__ __half g_wkh[Cdim * Cdim], g_wkl[Cdim * Cdim];
__device__ __half g_wvh[Cdim * Cdim];
__device__ __half g_wph[Cdim * Cdim], g_wpl[Cdim * Cdim];
__device__ __half g_qh[(size_t)Bc * Hh * NT  * Dh];
__device__ __half g_kh[(size_t)Bc * Hh * NKT * Dh];
__device__ __half g_vh[(size_t)Bc * Hh * NKT * Dh];
__device__ __half g_yh[(size_t)Bc * NT * Cdim], g_yl[(size_t)Bc * NT * Cdim];
__device__ uint32_t g_mbits[(size_t)Bc * NT * NKT / 32];   // bit-packed mask (2 MB)
__device__ int    g_maskmode;

// ---------------- helpers -------------------------------------------------------
__device__ __forceinline__ uint32_t smaddr(const void* p) {
    return (uint32_t)__cvta_generic_to_shared(p);
}
__device__ __forceinline__ void cpa16(uint32_t d, const void* s) {
    asm volatile("cp.async.ca.shared.global [%0], [%1], 16;" :: "r"(d), "l"(s));
}
__device__ __forceinline__ void cpcommit() { asm volatile("cp.async.commit_group;"); }
__device__ __forceinline__ void cpwait0()  { asm volatile("cp.async.wait_group 0;"); }

__device__ __forceinline__ void ldmx4(uint32_t a, uint32_t* r) {
    asm volatile("ldmatrix.sync.aligned.m8n8.x4.shared.b16 {%0,%1,%2,%3}, [%4];"
                 : "=r"(r[0]), "=r"(r[1]), "=r"(r[2]), "=r"(r[3]) : "r"(a));
}
__device__ __forceinline__ void ldmx2(uint32_t a, uint32_t* r) {
    asm volatile("ldmatrix.sync.aligned.m8n8.x2.shared.b16 {%0,%1}, [%2];"
                 : "=r"(r[0]), "=r"(r[1]) : "r"(a));
}
__device__ __forceinline__ void ldmx2t(uint32_t a, uint32_t* r) {
    asm volatile("ldmatrix.sync.aligned.m8n8.x2.trans.shared.b16 {%0,%1}, [%2];"
                 : "=r"(r[0]), "=r"(r[1]) : "r"(a));
}
__device__ __forceinline__ void mma16816(float* c, const uint32_t* a, const uint32_t* b) {
    asm volatile("mma.sync.aligned.m16n8k16.row.col.f32.f16.f16.f32 "
                 "{%0,%1,%2,%3},{%4,%5,%6,%7},{%8,%9},{%0,%1,%2,%3};"
                 : "+f"(c[0]), "+f"(c[1]), "+f"(c[2]), "+f"(c[3])
                 : "r"(a[0]), "r"(a[1]), "r"(a[2]), "r"(a[3]), "r"(b[0]), "r"(b[1]));
}
__device__ __forceinline__ float ex2f(float x) {
    float y; asm("ex2.approx.f32 %0, %1;" : "=f"(y) : "f"(x)); return y;
}
__device__ __forceinline__ void pairbar(int id) {
    asm volatile("bar.sync %0, 64;" :: "r"(id) : "memory");
}

// ---------------- prep kernels ---------------------------------------------------
__global__ void split_f32(const float* __restrict__ s, __half* __restrict__ h,
                          __half* __restrict__ l, int n)
{
    int i = (blockIdx.x * blockDim.x + threadIdx.x) * 4;
    if (i >= n) return;
    float4 v = *(const float4*)(s + i);
    __half hx = __float2half_rn(v.x), hy = __float2half_rn(v.y);
    __half hz = __float2half_rn(v.z), hw = __float2half_rn(v.w);
    *(__half2*)(h + i)     = __halves2half2(hx, hy);
    *(__half2*)(h + i + 2) = __halves2half2(hz, hw);
    if (l) {
        *(__half2*)(l + i)     = __halves2half2(__float2half_rn(v.x - __half2float(hx)),
                                                __float2half_rn(v.y - __half2float(hy)));
        *(__half2*)(l + i + 2) = __halves2half2(__float2half_rn(v.z - __half2float(hz)),
                                                __float2half_rn(v.w - __half2float(hw)));
    }
}

__global__ void detect_mask_mode(const unsigned char* __restrict__ m) {
    bool hi = false, f3 = false;
    for (int i = threadIdx.x; i < 8192; i += blockDim.x) {
        unsigned char v = m[i];
        int p = i & 3;
        if (p == 3 && v == 0x3f) f3 = true;
        if (p != 0 && v != 0)    hi = true;
    }
    int a3 = __syncthreads_or(f3 ? 1 : 0);
    int ah = __syncthreads_or(hi ? 1 : 0);
    if (threadIdx.x == 0) g_maskmode = a3 ? 2 : (ah ? 0 : 1);
}

// pack mask (any dtype) into 1 bit per element
__global__ void mask_to_bits(const void* __restrict__ mp, uint32_t* __restrict__ o) {
    int mode = g_maskmode;
    size_t w = (size_t)blockIdx.x * blockDim.x + threadIdx.x;
    size_t base = w * 32;
    uint32_t bits = 0;
    if (mode == 0) {
        const uchar4* p = (const uchar4*)((const unsigned char*)mp + base);
#pragma unroll
        for (int q = 0; q < 8; q++) {
            uchar4 v = p[q];
            bits |= ((uint32_t)(v.x != 0) << (q * 4))
                  | ((uint32_t)(v.y != 0) << (q * 4 + 1))
                  | ((uint32_t)(v.z != 0) << (q * 4 + 2))
                  | ((uint32_t)(v.w != 0) << (q * 4 + 3));
        }
    } else if (mode == 1) {
        const int4* p = (const int4*)((const int*)mp + base);
#pragma unroll
        for (int q = 0; q < 8; q++) {
            int4 v = p[q];
            bits |= ((uint32_t)(v.x != 0) << (q * 4))
                  | ((uint32_t)(v.y != 0) << (q * 4 + 1))
                  | ((uint32_t)(v.z != 0) << (q * 4 + 2))
                  | ((uint32_t)(v.w != 0) << (q * 4 + 3));
        }
    } else {
        const float4* p = (const float4*)((const float*)mp + base);
#pragma unroll
        for (int q = 0; q < 8; q++) {
            float4 v = p[q];
            bits |= ((uint32_t)(v.x != 0.f) << (q * 4))
                  | ((uint32_t)(v.y != 0.f) << (q * 4 + 1))
                  | ((uint32_t)(v.z != 0.f) << (q * 4 + 2))
                  | ((uint32_t)(v.w != 0.f) << (q * 4 + 3));
        }
    }
    o[w] = bits;
}

// ---------------- GEMM: Y = A @ W^T (split-fp16, TERMS mma, cp.async 2-stage) ----
#define GKT 32
#define GSH 40
#define GSZ (128 * GSH)
#define GEMM_SMEM_BYTES (2 * 4 * GSZ * 2)

template <int TERMS>
__global__ __launch_bounds__(256, 2) void gemm_mma(
    const __half* __restrict__ Ah0, const __half* __restrict__ Al0,
    const __half* __restrict__ Ah1, const __half* __restrict__ Al1,
    const __half* __restrict__ Wh,  const __half* __restrict__ Wl,
    float* __restrict__ outF, __half* __restrict__ outH, __half* __restrict__ outL,
    int MrowsPerB, int modeIn, int modeOut)
{
    extern __shared__ __half gs[];
    const int tid = threadIdx.x, lane = tid & 31, w = tid >> 5;
    const int wm = w >> 2, wn = w & 3;
    const int m0 = blockIdx.y * 128, n0 = blockIdx.x * 128;
    const int lrow = tid >> 2;
    const int lch  = (tid & 3) * 8;

    const __half *arh[2], *arl[2], *brh[2], *brl[2];
#pragma unroll
    for (int p = 0; p < 2; p++) {
        int r = lrow + p * 64, gm = m0 + r;
        int bb = gm / MrowsPerB, mm = gm - bb * MrowsPerB;
        if (modeIn == 0 || mm < NT) {
            size_t off = ((size_t)bb * NT + mm) * Cdim;
            arh[p] = Ah0 + off;
            arl[p] = (TERMS >= 2) ? (Al0 + off) : nullptr;
        } else {
            size_t off = ((size_t)bb * NT + (mm - NT)) * Cdim;
            arh[p] = Ah1 + off;
            arl[p] = (TERMS >= 2) ? (Al1 + off) : nullptr;
        }
        size_t wo = (size_t)(n0 + r) * Cdim;
        brh[p] = Wh + wo;
        brl[p] = (TERMS == 3) ? (Wl + wo) : nullptr;
    }

    float acc[4][4][4];
#pragma unroll
    for (int a = 0; a < 4; a++)
#pragma unroll
        for (int b2 = 0; b2 < 4; b2++)
#pragma unroll
            for (int q = 0; q < 4; q++) acc[a][b2][q] = 0.f;

    const int arlr = wm * 64 + (lane & 15);
    const int acs  = (lane >> 4) * 8;
    const int brlr = wn * 32 + (lane & 7);
    const int bcs  = ((lane >> 3) & 1) * 8;

    auto loadStage = [&](int st, int k0) {
        __half* b = gs + st * 4 * GSZ;
        const uint32_t d0 = (uint32_t)(lrow * GSH + lch);
#pragma unroll
        for (int p = 0; p < 2; p++) {
            uint32_t d = d0 + p * 64 * GSH;
            cpa16(smaddr(b + d),           arh[p] + k0 + lch);
            if (TERMS >= 2)
                cpa16(smaddr(b + GSZ + d), arl[p] + k0 + lch);
            cpa16(smaddr(b + 2 * GSZ + d), brh[p] + k0 + lch);
            if (TERMS == 3)
                cpa16(smaddr(b + 3 * GSZ + d), brl[p] + k0 + lch);
        }
    };

    loadStage(0, 0); cpcommit();
    const int NTILES = Cdim / GKT;
    for (int t = 0; t < NTILES; t++) {
        cpwait0(); __syncthreads();
        if (t + 1 < NTILES) { loadStage((t + 1) & 1, (t + 1) * GKT); cpcommit(); }

        __half* Ash = gs + (t & 1) * 4 * GSZ;
        __half* Asl = Ash + GSZ;
        __half* Bsh = Ash + 2 * GSZ;
        __half* Bsl = Ash + 3 * GSZ;
#pragma unroll
        for (int ks = 0; ks < 2; ks++) {
            const int kcA = ks * 16 + acs, kcB = ks * 16 + bcs;
            uint32_t ah[4][4], al[4][4];
#pragma unroll
            for (int mt = 0; mt < 4; mt++) {
                ldmx4(smaddr(&Ash[(arlr + mt * 16) * GSH + kcA]), ah[mt]);
                if (TERMS >= 2)
                    ldmx4(smaddr(&Asl[(arlr + mt * 16) * GSH + kcA]), al[mt]);
            }
#pragma unroll
            for (int nt = 0; nt < 4; nt++) {
                uint32_t bh[2], bl[2];
                ldmx2(smaddr(&Bsh[(brlr + nt * 8) * GSH + kcB]), bh);
                if (TERMS == 3)
                    ldmx2(smaddr(&Bsl[(brlr + nt * 8) * GSH + kcB]), bl);
#pragma unroll
                for (int mt = 0; mt < 4; mt++) {
                    mma16816(acc[mt][nt], ah[mt], bh);
                    if (TERMS >= 2)
                        mma16816(acc[mt][nt], al[mt], bh);
                    if (TERMS == 3)
                        mma16816(acc[mt][nt], ah[mt], bl);
                }
            }
        }
    }

    const int er = m0 + wm * 64 + (lane >> 2);
    const int ec = n0 + wn * 32 + 2 * (lane & 3);
#pragma unroll
    for (int mt = 0; mt < 4; mt++)
#pragma unroll
        for (int nt = 0; nt < 4; nt++) {
            int col = ec + nt * 8;
#pragma unroll
            for (int hf = 0; hf < 2; hf++) {
                int   row = er + mt * 16 + hf * 8;
                float v0 = acc[mt][nt][hf * 2], v1 = acc[mt][nt][hf * 2 + 1];
                if (modeOut == 0) {
                    int bb = row / MrowsPerB, mm = row - bb * MrowsPerB;
                    int hh = col >> 6, dd = col & 63;
                    size_t p = (((size_t)(bb * Hh + hh)) * MrowsPerB + mm) * Dh + dd;
                    __half h0 = __float2half_rn(v0), h1 = __float2half_rn(v1);
                    *(__half2*)(outH + p) = __halves2half2(h0, h1);
                    if (outL)
                        *(__half2*)(outL + p) = __halves2half2(
                            __float2half_rn(v0 - __half2float(h0)),
                            __float2half_rn(v1 - __half2float(h1)));
                } else {
                    *(float2*)(outF + (size_t)row * Cdim + col) = make_float2(v0, v1);
                }
            }
        }
}

// ---------------- Flash attention v5 -----------------------------------------------
// 64 q-rows/block, 128 kv/tile (16 iterations), double-buffered cp.async (K, V, bits).
// Register softmax with warp-pair barriers; bit mask; S = Qh*Kh^T, PV = P*Vh.
#define QSTR 72
#define KSTR 72
#define PSTR 136
#define QSZ  (64 * QSTR)             // 4608 halves
#define KSZ  (128 * KSTR)            // 9216 halves
#define PSZ  (64 * PSTR)             // 8704 halves
#define MBSZ (64 * 16)               // 1024 bytes per stage
#define ATT_SMEM_BYTES ((QSZ + 4 * KSZ + PSZ) * 2 + 2 * MBSZ + 2 * 128 * 4)

__global__ __launch_bounds__(256, 2) void attn_mma(
    const __half* __restrict__ qhg, const __half* __restrict__ khg,
    const __half* __restrict__ vhg, const uint32_t* __restrict__ mbits,
    __half* __restrict__ yh, __half* __restrict__ yl)
{
    extern __shared__ __half sh[];
    __half* Qh = sh;
    __half* Kb = sh + QSZ;                       // 2 stages
    __half* Vb = sh + QSZ + 2 * KSZ;             // 2 stages
    __half* Ph = sh + QSZ + 4 * KSZ;
    unsigned char* Mb = (unsigned char*)(sh + QSZ + 4 * KSZ + PSZ);
    float*  pm = (float*)(Mb + 2 * MBSZ);        // [8][16]
    float*  ps = pm + 128;

    const int tid = threadIdx.x, lane = tid & 31, w = tid >> 5;
    const int wq = w >> 1, wk = w & 1;
    const int pb = 1 + (w >> 1);
    const int b = blockIdx.z, h = blockIdx.y, qt = blockIdx.x;

    const size_t kvo = ((size_t)(b * Hh + h)) * NKT * Dh;
    const unsigned char* mgb =
        (const unsigned char*)mbits + ((size_t)b * NT + (size_t)qt * 64) * (NKT / 8);

    auto loadStage = [&](int kt, int st) {
        __half* Khp = Kb + st * KSZ;
        __half* Vhp = Vb + st * KSZ;
#pragma unroll
        for (int i = 0; i < 4; i++) {
            int pos = tid + i * 256;
            int r = pos >> 3, cc = (pos & 7) * 8;
            size_t go = kvo + (size_t)(kt * 128 + r) * Dh + cc;
            uint32_t so = r * KSTR + cc;
            cpa16(smaddr(Khp + so), khg + go);
            cpa16(smaddr(Vhp + so), vhg + go);
        }
        if (tid < 64)
            cpa16(smaddr(Mb + st * MBSZ + tid * 16),
                  mgb + (size_t)tid * (NKT / 8) + kt * 16);
    };

    // prologue
    {
        const size_t qo = (((size_t)(b * Hh + h)) * NT + qt * 64) * Dh;
#pragma unroll
        for (int i = 0; i < 2; i++) {
            int pos = tid + i * 256;
            int r = pos >> 3, cc = (pos & 7) * 8;
            cpa16(smaddr(Qh + r * QSTR + cc), qhg + qo + r * Dh + cc);
        }
        loadStage(0, 0);
        cpcommit();
    }
    cpwait0(); __syncthreads();

    uint32_t qf[4][4];
    {
        const int rl = wq * 16 + (lane & 15);
        const int cs = (lane >> 4) * 8;
#pragma unroll
        for (int kc = 0; kc < 4; kc++)
            ldmx4(smaddr(&Qh[rl * QSTR + kc * 16 + cs]), qf[kc]);
    }

    float oacc[4][4];
#pragma unroll
    for (int nt = 0; nt < 4; nt++)
#pragma unroll
        for (int q = 0; q < 4; q++) oacc[nt][q] = 0.f;
    float m_reg[2] = {-1e30f, -1e30f};
    float l_reg[2] = {0.f, 0.f};

    const int rg  = lane >> 2;
    const int mr0 = wq * 16 + rg;
    const int mr1 = mr0 + 8;
    const int ql2 = (lane & 3) * 2;
    const float SCL = 0.125f * 1.44269504f;

    for (int kt = 0; kt < NKT / 128; kt++) {
        const int st = kt & 1;
        if (kt > 0) { cpwait0(); __syncthreads(); }
        if (kt + 1 < NKT / 128) { loadStage(kt + 1, st ^ 1); cpcommit(); }

        __half* Khp = Kb + st * KSZ;
        __half* Vhp = Vb + st * KSZ;
        const uint32_t* M32 = (const uint32_t*)(Mb + st * MBSZ);

        // --- S = Qh Kh^T (16q x 128kv per warp-pair; this warp: 64 kv cols) ---
        float sacc[8][4];
#pragma unroll
        for (int nt = 0; nt < 8; nt++)
#pragma unroll
            for (int q = 0; q < 4; q++) sacc[nt][q] = 0.f;
        {
            const int brl = wk * 64 + (lane & 7);
            const int bcs = ((lane >> 3) & 1) * 8;
#pragma unroll
            for (int kc = 0; kc < 4; kc++) {
#pragma unroll
                for (int nt = 0; nt < 8; nt++) {
                    uint32_t bh[2];
                    ldmx2(smaddr(&Khp[(brl + nt * 8) * KSTR + kc * 16 + bcs]), bh);
                    mma16816(sacc[nt], qf[kc], bh);
                }
            }
        }

        // --- mask + scale in place, row max ---
        uint32_t w0a = M32[mr0 * 4 + wk * 2],     w0b = M32[mr0 * 4 + wk * 2 + 1];
        uint32_t w1a = M32[mr1 * 4 + wk * 2],     w1b = M32[mr1 * 4 + wk * 2 + 1];
        float rm0 = -1e30f, rm1 = -1e30f;
#pragma unroll
        for (int nt = 0; nt < 8; nt++) {
            const int bit = (nt & 3) * 8 + ql2;
            uint32_t mw0 = (nt < 4) ? w0a : w0b;
            uint32_t mw1 = (nt < 4) ? w1a : w1b;
            sacc[nt][0] = ((mw0 >> bit) & 1)       ? -1e30f : sacc[nt][0] * SCL;
            sacc[nt][1] = ((mw0 >> (bit + 1)) & 1) ? -1e30f : sacc[nt][1] * SCL;
            sacc[nt][2] = ((mw1 >> bit) & 1)       ? -1e30f : sacc[nt][2] * SCL;
            sacc[nt][3] = ((mw1 >> (bit + 1)) & 1) ? -1e30f : sacc[nt][3] * SCL;
            rm0 = fmaxf(rm0, fmaxf(sacc[nt][0], sacc[nt][1]));
            rm1 = fmaxf(rm1, fmaxf(sacc[nt][2], sacc[nt][3]));
        }
        rm0 = fmaxf(rm0, __shfl_xor_sync(0xffffffffu, rm0, 1));
        rm0 = fmaxf(rm0, __shfl_xor_sync(0xffffffffu, rm0, 2));
        rm1 = fmaxf(rm1, __shfl_xor_sync(0xffffffffu, rm1, 1));
        rm1 = fmaxf(rm1, __shfl_xor_sync(0xffffffffu, rm1, 2));
        if ((lane & 3) == 0) { pm[w * 16 + rg] = rm0; pm[w * 16 + rg + 8] = rm1; }
        pairbar(pb);
        float mn0 = fmaxf(m_reg[0], fmaxf(rm0, pm[(w ^ 1) * 16 + rg]));
        float mn1 = fmaxf(m_reg[1], fmaxf(rm1, pm[(w ^ 1) * 16 + rg + 8]));
        float cf0 = ex2f(m_reg[0] - mn0);
        float cf1 = ex2f(m_reg[1] - mn1);

        // --- exp, P store, row sum ---
        float rs0 = 0.f, rs1 = 0.f;
#pragma unroll
        for (int nt = 0; nt < 8; nt++) {
            const int colb = wk * 64 + nt * 8 + ql2;
            float p00 = ex2f(sacc[nt][0] - mn0), p01 = ex2f(sacc[nt][1] - mn0);
            float p10 = ex2f(sacc[nt][2] - mn1), p11 = ex2f(sacc[nt][3] - mn1);
            rs0 += p00 + p01; rs1 += p10 + p11;
            *(__half2*)&Ph[mr0 * PSTR + colb] =
                __halves2half2(__float2half_rn(p00), __float2half_rn(p01));
            *(__half2*)&Ph[mr1 * PSTR + colb] =
                __halves2half2(__float2half_rn(p10), __float2half_rn(p11));
        }
        rs0 += __shfl_xor_sync(0xffffffffu, rs0, 1);
        rs0 += __shfl_xor_sync(0xffffffffu, rs0, 2);
        rs1 += __shfl_xor_sync(0xffffffffu, rs1, 1);
        rs1 += __shfl_xor_sync(0xffffffffu, rs1, 2);
        if ((lane & 3) == 0) { ps[w * 16 + rg] = rs0; ps[w * 16 + rg + 8] = rs1; }

#pragma unroll
        for (int nt = 0; nt < 4; nt++) {
            oacc[nt][0] *= cf0; oacc[nt][1] *= cf0;
            oacc[nt][2] *= cf1; oacc[nt][3] *= cf1;
        }
        pairbar(pb);
        l_reg[0] = l_reg[0] * cf0 + rs0 + ps[(w ^ 1) * 16 + rg];
        l_reg[1] = l_reg[1] * cf1 + rs1 + ps[(w ^ 1) * 16 + rg + 8];
        m_reg[0] = mn0; m_reg[1] = mn1;

        // --- O += P Vh (K-dim 128) ---
        {
            const int prl = wq * 16 + (lane & 15);
            const int pcs = (lane >> 4) * 8;
            const int vrl = lane & 15;
#pragma unroll
            for (int kc = 0; kc < 8; kc++) {
                uint32_t pfh[4];
                ldmx4(smaddr(&Ph[prl * PSTR + kc * 16 + pcs]), pfh);
#pragma unroll
                for (int nt = 0; nt < 4; nt++) {
                    uint32_t vh[2];
                    ldmx2t(smaddr(&Vhp[(kc * 16 + vrl) * KSTR + wk * 32 + nt * 8]), vh);
                    mma16816(oacc[nt], pfh, vh);
                }
            }
        }
    }

    // --- epilogue ---
    {
        float i0 = (l_reg[0] > 0.f) ? 1.f / l_reg[0] : 0.f;
        float i1 = (l_reg[1] > 0.f) ? 1.f / l_reg[1] : 0.f;
        const int c0 = h * 64 + wk * 32 + ql2;
        size_t o0 = ((size_t)b * NT + qt * 64 + mr0) * Cdim + c0;
        size_t o1 = ((size_t)b * NT + qt * 64 + mr1) * Cdim + c0;
#pragma unroll
        for (int nt = 0; nt < 4; nt++) {
            float a0 = oacc[nt][0] * i0, a1 = oacc[nt][1] * i0;
            float b0 = oacc[nt][2] * i1, b1 = oacc[nt][3] * i1;
            __half ha0 = __float2half_rn(a0), ha1 = __float2half_rn(a1);
            __half hb0 = __float2half_rn(b0), hb1 = __float2half_rn(b1);
            *(__half2*)(yh + o0 + nt * 8) = __halves2half2(ha0, ha1);
            *(__half2*)(yl + o0 + nt * 8) = __halves2half2(
                __float2half_rn(a0 - __half2float(ha0)),
                __float2half_rn(a1 - __half2float(ha1)));
            *(__half2*)(yh + o1 + nt * 8) = __halves2half2(hb0, hb1);
            *(__half2*)(yl + o1 + nt * 8) = __halves2half2(
                __float2half_rn(b0 - __half2float(hb0)),
                __float2half_rn(b1 - __half2float(hb1)));
        }
    }
}

// ---------------- launch ------------------------------------------------------------
extern "C" void kernel_launch(void* const* d_in, const int* in_sizes, int n_in,
                              void* d_out, int out_size)
{
    const float* x  = (const float*)d_in[0];
    const float* c  = (const float*)d_in[1];
    const void*  mk = d_in[2];
    const float* Wq = (const float*)d_in[3];
    const float* Wk = (const float*)d_in[4];
    const float* Wv = (const float*)d_in[5];
    const float* Wp = (const float*)d_in[6];
    float* out = (float*)d_out;

    __half *xh, *xl, *ch_, *cl_, *wqh, *wql, *wkh, *wkl, *wvh, *wph, *wpl;
    __half *qh, *kh, *vh, *yh, *yl;
    uint32_t* mb;
    cudaGetSymbolAddress((void**)&xh,  g_xh);  cudaGetSymbolAddress((void**)&xl,  g_xl);
    cudaGetSymbolAddress((void**)&ch_, g_ch);  cudaGetSymbolAddress((void**)&cl_, g_cl);
    cudaGetSymbolAddress((void**)&wqh, g_wqh); cudaGetSymbolAddress((void**)&wql, g_wql);
    cudaGetSymbolAddress((void**)&wkh, g_wkh); cudaGetSymbolAddress((void**)&wkl, g_wkl);
    cudaGetSymbolAddress((void**)&wvh, g_wvh);
    cudaGetSymbolAddress((void**)&wph, g_wph); cudaGetSymbolAddress((void**)&wpl, g_wpl);
    cudaGetSymbolAddress((void**)&qh,  g_qh);
    cudaGetSymbolAddress((void**)&kh,  g_kh);
    cudaGetSymbolAddress((void**)&vh,  g_vh);
    cudaGetSymbolAddress((void**)&yh,  g_yh);  cudaGetSymbolAddress((void**)&yl,  g_yl);
    cudaGetSymbolAddress((void**)&mb,  g_mbits);

    cudaFuncSetAttribute(gemm_mma<3>, cudaFuncAttributeMaxDynamicSharedMemorySize,
                         GEMM_SMEM_BYTES);
    cudaFuncSetAttribute(gemm_mma<2>, cudaFuncAttributeMaxDynamicSharedMemorySize,
                         GEMM_SMEM_BYTES);
    cudaFuncSetAttribute(gemm_mma<1>, cudaFuncAttributeMaxDynamicSharedMemorySize,
                         GEMM_SMEM_BYTES);
    cudaFuncSetAttribute(attn_mma, cudaFuncAttributeMaxDynamicSharedMemorySize,
                         ATT_SMEM_BYTES);

    detect_mask_mode<<<1, 256>>>((const unsigned char*)mk);
    mask_to_bits<<<(Bc * NT * NKT / 32) / 256, 256>>>(mk, mb);

    const int nx = Bc * NT * Cdim;
    const int nw = Cdim * Cdim;
    split_f32<<<nx / 1024, 256>>>(x,  xh,  xl,  nx);
    split_f32<<<nx / 1024, 256>>>(c,  ch_, cl_, nx);
    split_f32<<<nw / 1024, 256>>>(Wq, wqh, nullptr, nw);
    split_f32<<<nw / 1024, 256>>>(Wk, wkh, nullptr, nw);
    split_f32<<<nw / 1024, 256>>>(Wv, wvh, nullptr, nw);
    split_f32<<<nw / 1024, 256>>>(Wp, wph, wpl, nw);

    // Q/K projections: 2-term (x exact, W fp16); V: 1-term; hi-only outputs
    gemm_mma<2><<<dim3(Cdim / 128, Bc * NT  / 128), 256, GEMM_SMEM_BYTES>>>(
        xh, xl, nullptr, nullptr, wqh, nullptr, nullptr, qh, nullptr, NT,  0, 0);
    gemm_mma<2><<<dim3(Cdim / 128, Bc * NKT / 128), 256, GEMM_SMEM_BYTES>>>(
        xh, xl, ch_, cl_,         wkh, nullptr, nullptr, kh, nullptr, NKT, 1, 0);
    gemm_mma<1><<<dim3(Cdim / 128, Bc * NKT / 128), 256, GEMM_SMEM_BYTES>>>(
        xh, nullptr, ch_, nullptr, wvh, nullptr, nullptr, vh, nullptr, NKT, 1, 0);

    attn_mma<<<dim3(NT / 64, Hh, Bc), 256, ATT_SMEM_BYTES>>>(
        qh, kh, vh, mb, yh, yl);

    // output projection: full 3-term
    gemm_mma<3><<<dim3(Cdim / 128, Bc * NT / 128), 256, GEMM_SMEM_BYTES>>>(
        yh, yl, nullptr, nullptr, wph, wpl, out, nullptr, nullptr, NT, 0, 1);
}

// round 12
// speedup vs baseline: 5.8944x; 1.0277x over previous
#include <cuda_runtime.h>
#include <cuda_fp16.h>
#include <stdint.h>

#define Bc   8
#define Hh   8
#define NT   1024
#define NKT  2048
#define Cdim 512
#define Dh   64

// ---------------- scratch (no allocation allowed) ------------------------------
__device__ __half g_xh[(size_t)Bc * NT * Cdim],  g_xl[(size_t)Bc * NT * Cdim];
__device__ __half g_ch[(size_t)Bc * NT * Cdim],  g_cl[(size_t)Bc * NT * Cdim];
__device__ __half g_wqh[Cdim * Cdim];
__device__ __half g_wkh[Cdim * Cdim];
__device__ __half g_wvh[Cdim * Cdim];
__device__ __half g_wph[Cdim * Cdim];
__device__ __half g_qh[(size_t)Bc * Hh * NT  * Dh];
__device__ __half g_kh[(size_t)Bc * Hh * NKT * Dh];
__device__ __half g_vh[(size_t)Bc * Hh * NKT * Dh];
__device__ __half g_yh[(size_t)Bc * NT * Cdim], g_yl[(size_t)Bc * NT * Cdim];
__device__ uint32_t g_mbits[(size_t)Bc * NT * NKT / 32];   // bit-packed mask (2 MB)
__device__ int    g_maskmode;

// ---------------- helpers -------------------------------------------------------
__device__ __forceinline__ uint32_t smaddr(const void* p) {
    return (uint32_t)__cvta_generic_to_shared(p);
}
__device__ __forceinline__ void cpa16(uint32_t d, const void* s) {
    asm volatile("cp.async.ca.shared.global [%0], [%1], 16;" :: "r"(d), "l"(s));
}
__device__ __forceinline__ void cpcommit() { asm volatile("cp.async.commit_group;"); }
__device__ __forceinline__ void cpwait0()  { asm volatile("cp.async.wait_group 0;"); }

__device__ __forceinline__ void ldmx4(uint32_t a, uint32_t* r) {
    asm volatile("ldmatrix.sync.aligned.m8n8.x4.shared.b16 {%0,%1,%2,%3}, [%4];"
                 : "=r"(r[0]), "=r"(r[1]), "=r"(r[2]), "=r"(r[3]) : "r"(a));
}
__device__ __forceinline__ void ldmx2(uint32_t a, uint32_t* r) {
    asm volatile("ldmatrix.sync.aligned.m8n8.x2.shared.b16 {%0,%1}, [%2];"
                 : "=r"(r[0]), "=r"(r[1]) : "r"(a));
}
__device__ __forceinline__ void ldmx2t(uint32_t a, uint32_t* r) {
    asm volatile("ldmatrix.sync.aligned.m8n8.x2.trans.shared.b16 {%0,%1}, [%2];"
                 : "=r"(r[0]), "=r"(r[1]) : "r"(a));
}
__device__ __forceinline__ void mma16816(float* c, const uint32_t* a, const uint32_t* b) {
    asm volatile("mma.sync.aligned.m16n8k16.row.col.f32.f16.f16.f32 "
                 "{%0,%1,%2,%3},{%4,%5,%6,%7},{%8,%9},{%0,%1,%2,%3};"
                 : "+f"(c[0]), "+f"(c[1]), "+f"(c[2]), "+f"(c[3])
                 : "r"(a[0]), "r"(a[1]), "r"(a[2]), "r"(a[3]), "r"(b[0]), "r"(b[1]));
}
__device__ __forceinline__ float ex2f(float x) {
    float y; asm("ex2.approx.f32 %0, %1;" : "=f"(y) : "f"(x)); return y;
}
__device__ __forceinline__ void pairbar(int id) {
    asm volatile("bar.sync %0, 64;" :: "r"(id) : "memory");
}

// ---------------- prep kernels ---------------------------------------------------
__global__ void split_f32(const float* __restrict__ s, __half* __restrict__ h,
                          __half* __restrict__ l, int n)
{
    int i = (blockIdx.x * blockDim.x + threadIdx.x) * 4;
    if (i >= n) return;
    float4 v = *(const float4*)(s + i);
    __half hx = __float2half_rn(v.x), hy = __float2half_rn(v.y);
    __half hz = __float2half_rn(v.z), hw = __float2half_rn(v.w);
    *(__half2*)(h + i)     = __halves2half2(hx, hy);
    *(__half2*)(h + i + 2) = __halves2half2(hz, hw);
    if (l) {
        *(__half2*)(l + i)     = __halves2half2(__float2half_rn(v.x - __half2float(hx)),
                                                __float2half_rn(v.y - __half2float(hy)));
        *(__half2*)(l + i + 2) = __halves2half2(__float2half_rn(v.z - __half2float(hz)),
                                                __float2half_rn(v.w - __half2float(hw)));
    }
}

__global__ void detect_mask_mode(const unsigned char* __restrict__ m) {
    bool hi = false, f3 = false;
    for (int i = threadIdx.x; i < 8192; i += blockDim.x) {
        unsigned char v = m[i];
        int p = i & 3;
        if (p == 3 && v == 0x3f) f3 = true;
        if (p != 0 && v != 0)    hi = true;
    }
    int a3 = __syncthreads_or(f3 ? 1 : 0);
    int ah = __syncthreads_or(hi ? 1 : 0);
    if (threadIdx.x == 0) g_maskmode = a3 ? 2 : (ah ? 0 : 1);
}

// pack mask (any dtype) into 1 bit per element
__global__ void mask_to_bits(const void* __restrict__ mp, uint32_t* __restrict__ o) {
    int mode = g_maskmode;
    size_t w = (size_t)blockIdx.x * blockDim.x + threadIdx.x;
    size_t base = w * 32;
    uint32_t bits = 0;
    if (mode == 0) {
        const uchar4* p = (const uchar4*)((const unsigned char*)mp + base);
#pragma unroll
        for (int q = 0; q < 8; q++) {
            uchar4 v = p[q];
            bits |= ((uint32_t)(v.x != 0) << (q * 4))
                  | ((uint32_t)(v.y != 0) << (q * 4 + 1))
                  | ((uint32_t)(v.z != 0) << (q * 4 + 2))
                  | ((uint32_t)(v.w != 0) << (q * 4 + 3));
        }
    } else if (mode == 1) {
        const int4* p = (const int4*)((const int*)mp + base);
#pragma unroll
        for (int q = 0; q < 8; q++) {
            int4 v = p[q];
            bits |= ((uint32_t)(v.x != 0) << (q * 4))
                  | ((uint32_t)(v.y != 0) << (q * 4 + 1))
                  | ((uint32_t)(v.z != 0) << (q * 4 + 2))
                  | ((uint32_t)(v.w != 0) << (q * 4 + 3));
        }
    } else {
        const float4* p = (const float4*)((const float*)mp + base);
#pragma unroll
        for (int q = 0; q < 8; q++) {
            float4 v = p[q];
            bits |= ((uint32_t)(v.x != 0.f) << (q * 4))
                  | ((uint32_t)(v.y != 0.f) << (q * 4 + 1))
                  | ((uint32_t)(v.z != 0.f) << (q * 4 + 2))
                  | ((uint32_t)(v.w != 0.f) << (q * 4 + 3));
        }
    }
    o[w] = bits;
}

// ---------------- GEMM: Y = A @ W^T (split-fp16, TERMS mma, cp.async 2-stage) ----
// mma issue order: per nt, term-major across mt -> same-accumulator reuse
// distance of 4 (was 1), hiding HMMA latency.
#define GKT 32
#define GSH 40
#define GSZ (128 * GSH)
#define GEMM_SMEM_BYTES (2 * 4 * GSZ * 2)

template <int TERMS>
__global__ __launch_bounds__(256, 2) void gemm_mma(
    const __half* __restrict__ Ah0, const __half* __restrict__ Al0,
    const __half* __restrict__ Ah1, const __half* __restrict__ Al1,
    const __half* __restrict__ Wh,  const __half* __restrict__ Wl,
    float* __restrict__ outF, __half* __restrict__ outH, __half* __restrict__ outL,
    int MrowsPerB, int modeIn, int modeOut)
{
    extern __shared__ __half gs[];
    const int tid = threadIdx.x, lane = tid & 31, w = tid >> 5;
    const int wm = w >> 2, wn = w & 3;
    const int m0 = blockIdx.y * 128, n0 = blockIdx.x * 128;
    const int lrow = tid >> 2;
    const int lch  = (tid & 3) * 8;

    const __half *arh[2], *arl[2], *brh[2], *brl[2];
#pragma unroll
    for (int p = 0; p < 2; p++) {
        int r = lrow + p * 64, gm = m0 + r;
        int bb = gm / MrowsPerB, mm = gm - bb * MrowsPerB;
        if (modeIn == 0 || mm < NT) {
            size_t off = ((size_t)bb * NT + mm) * Cdim;
            arh[p] = Ah0 + off;
            arl[p] = (TERMS >= 2) ? (Al0 + off) : nullptr;
        } else {
            size_t off = ((size_t)bb * NT + (mm - NT)) * Cdim;
            arh[p] = Ah1 + off;
            arl[p] = (TERMS >= 2) ? (Al1 + off) : nullptr;
        }
        size_t wo = (size_t)(n0 + r) * Cdim;
        brh[p] = Wh + wo;
        brl[p] = (TERMS == 3) ? (Wl + wo) : nullptr;
    }

    float acc[4][4][4];
#pragma unroll
    for (int a = 0; a < 4; a++)
#pragma unroll
        for (int b2 = 0; b2 < 4; b2++)
#pragma unroll
            for (int q = 0; q < 4; q++) acc[a][b2][q] = 0.f;

    const int arlr = wm * 64 + (lane & 15);
    const int acs  = (lane >> 4) * 8;
    const int brlr = wn * 32 + (lane & 7);
    const int bcs  = ((lane >> 3) & 1) * 8;

    auto loadStage = [&](int st, int k0) {
        __half* b = gs + st * 4 * GSZ;
        const uint32_t d0 = (uint32_t)(lrow * GSH + lch);
#pragma unroll
        for (int p = 0; p < 2; p++) {
            uint32_t d = d0 + p * 64 * GSH;
            cpa16(smaddr(b + d),           arh[p] + k0 + lch);
            if (TERMS >= 2)
                cpa16(smaddr(b + GSZ + d), arl[p] + k0 + lch);
            cpa16(smaddr(b + 2 * GSZ + d), brh[p] + k0 + lch);
            if (TERMS == 3)
                cpa16(smaddr(b + 3 * GSZ + d), brl[p] + k0 + lch);
        }
    };

    loadStage(0, 0); cpcommit();
    const int NTILES = Cdim / GKT;
    for (int t = 0; t < NTILES; t++) {
        cpwait0(); __syncthreads();
        if (t + 1 < NTILES) { loadStage((t + 1) & 1, (t + 1) * GKT); cpcommit(); }

        __half* Ash = gs + (t & 1) * 4 * GSZ;
        __half* Asl = Ash + GSZ;
        __half* Bsh = Ash + 2 * GSZ;
        __half* Bsl = Ash + 3 * GSZ;
#pragma unroll
        for (int ks = 0; ks < 2; ks++) {
            const int kcA = ks * 16 + acs, kcB = ks * 16 + bcs;
            uint32_t ah[4][4], al[4][4];
#pragma unroll
            for (int mt = 0; mt < 4; mt++) {
                ldmx4(smaddr(&Ash[(arlr + mt * 16) * GSH + kcA]), ah[mt]);
                if (TERMS >= 2)
                    ldmx4(smaddr(&Asl[(arlr + mt * 16) * GSH + kcA]), al[mt]);
            }
#pragma unroll
            for (int nt = 0; nt < 4; nt++) {
                uint32_t bh[2], bl[2];
                ldmx2(smaddr(&Bsh[(brlr + nt * 8) * GSH + kcB]), bh);
                if (TERMS == 3)
                    ldmx2(smaddr(&Bsl[(brlr + nt * 8) * GSH + kcB]), bl);
                // term-major: 4 independent mma between same-acc reuses
#pragma unroll
                for (int mt = 0; mt < 4; mt++)
                    mma16816(acc[mt][nt], ah[mt], bh);
                if (TERMS >= 2)
#pragma unroll
                    for (int mt = 0; mt < 4; mt++)
                        mma16816(acc[mt][nt], al[mt], bh);
                if (TERMS == 3)
#pragma unroll
                    for (int mt = 0; mt < 4; mt++)
                        mma16816(acc[mt][nt], ah[mt], bl);
            }
        }
    }

    const int er = m0 + wm * 64 + (lane >> 2);
    const int ec = n0 + wn * 32 + 2 * (lane & 3);
#pragma unroll
    for (int mt = 0; mt < 4; mt++)
#pragma unroll
        for (int nt = 0; nt < 4; nt++) {
            int col = ec + nt * 8;
#pragma unroll
            for (int hf = 0; hf < 2; hf++) {
                int   row = er + mt * 16 + hf * 8;
                float v0 = acc[mt][nt][hf * 2], v1 = acc[mt][nt][hf * 2 + 1];
                if (modeOut == 0) {
                    int bb = row / MrowsPerB, mm = row - bb * MrowsPerB;
                    int hh = col >> 6, dd = col & 63;
                    size_t p = (((size_t)(bb * Hh + hh)) * MrowsPerB + mm) * Dh + dd;
                    __half h0 = __float2half_rn(v0), h1 = __float2half_rn(v1);
                    *(__half2*)(outH + p) = __halves2half2(h0, h1);
                    if (outL)
                        *(__half2*)(outL + p) = __halves2half2(
                            __float2half_rn(v0 - __half2float(h0)),
                            __float2half_rn(v1 - __half2float(h1)));
                } else {
                    *(float2*)(outF + (size_t)row * Cdim + col) = make_float2(v0, v1);
                }
            }
        }
}

// ---------------- Flash attention v5 (unchanged from R11) --------------------------
#define QSTR 72
#define KSTR 72
#define PSTR 136
#define QSZ  (64 * QSTR)
#define KSZ  (128 * KSTR)
#define PSZ  (64 * PSTR)
#define MBSZ (64 * 16)
#define ATT_SMEM_BYTES ((QSZ + 4 * KSZ + PSZ) * 2 + 2 * MBSZ + 2 * 128 * 4)

__global__ __launch_bounds__(256, 2) void attn_mma(
    const __half* __restrict__ qhg, const __half* __restrict__ khg,
    const __half* __restrict__ vhg, const uint32_t* __restrict__ mbits,
    __half* __restrict__ yh, __half* __restrict__ yl)
{
    extern __shared__ __half sh[];
    __half* Qh = sh;
    __half* Kb = sh + QSZ;
    __half* Vb = sh + QSZ + 2 * KSZ;
    __half* Ph = sh + QSZ + 4 * KSZ;
    unsigned char* Mb = (unsigned char*)(sh + QSZ + 4 * KSZ + PSZ);
    float*  pm = (float*)(Mb + 2 * MBSZ);
    float*  ps = pm + 128;

    const int tid = threadIdx.x, lane = tid & 31, w = tid >> 5;
    const int wq = w >> 1, wk = w & 1;
    const int pb = 1 + (w >> 1);
    const int b = blockIdx.z, h = blockIdx.y, qt = blockIdx.x;

    const size_t kvo = ((size_t)(b * Hh + h)) * NKT * Dh;
    const unsigned char* mgb =
        (const unsigned char*)mbits + ((size_t)b * NT + (size_t)qt * 64) * (NKT / 8);

    auto loadStage = [&](int kt, int st) {
        __half* Khp = Kb + st * KSZ;
        __half* Vhp = Vb + st * KSZ;
#pragma unroll
        for (int i = 0; i < 4; i++) {
            int pos = tid + i * 256;
            int r = pos >> 3, cc = (pos & 7) * 8;
            size_t go = kvo + (size_t)(kt * 128 + r) * Dh + cc;
            uint32_t so = r * KSTR + cc;
            cpa16(smaddr(Khp + so), khg + go);
            cpa16(smaddr(Vhp + so), vhg + go);
        }
        if (tid < 64)
            cpa16(smaddr(Mb + st * MBSZ + tid * 16),
                  mgb + (size_t)tid * (NKT / 8) + kt * 16);
    };

    {
        const size_t qo = (((size_t)(b * Hh + h)) * NT + qt * 64) * Dh;
#pragma unroll
        for (int i = 0; i < 2; i++) {
            int pos = tid + i * 256;
            int r = pos >> 3, cc = (pos & 7) * 8;
            cpa16(smaddr(Qh + r * QSTR + cc), qhg + qo + r * Dh + cc);
        }
        loadStage(0, 0);
        cpcommit();
    }
    cpwait0(); __syncthreads();

    uint32_t qf[4][4];
    {
        const int rl = wq * 16 + (lane & 15);
        const int cs = (lane >> 4) * 8;
#pragma unroll
        for (int kc = 0; kc < 4; kc++)
            ldmx4(smaddr(&Qh[rl * QSTR + kc * 16 + cs]), qf[kc]);
    }

    float oacc[4][4];
#pragma unroll
    for (int nt = 0; nt < 4; nt++)
#pragma unroll
        for (int q = 0; q < 4; q++) oacc[nt][q] = 0.f;
    float m_reg[2] = {-1e30f, -1e30f};
    float l_reg[2] = {0.f, 0.f};

    const int rg  = lane >> 2;
    const int mr0 = wq * 16 + rg;
    const int mr1 = mr0 + 8;
    const int ql2 = (lane & 3) * 2;
    const float SCL = 0.125f * 1.44269504f;

    for (int kt = 0; kt < NKT / 128; kt++) {
        const int st = kt & 1;
        if (kt > 0) { cpwait0(); __syncthreads(); }
        if (kt + 1 < NKT / 128) { loadStage(kt + 1, st ^ 1); cpcommit(); }

        __half* Khp = Kb + st * KSZ;
        __half* Vhp = Vb + st * KSZ;
        const uint32_t* M32 = (const uint32_t*)(Mb + st * MBSZ);

        float sacc[8][4];
#pragma unroll
        for (int nt = 0; nt < 8; nt++)
#pragma unroll
            for (int q = 0; q < 4; q++) sacc[nt][q] = 0.f;
        {
            const int brl = wk * 64 + (lane & 7);
            const int bcs = ((lane >> 3) & 1) * 8;
#pragma unroll
            for (int kc = 0; kc < 4; kc++) {
#pragma unroll
                for (int nt = 0; nt < 8; nt++) {
                    uint32_t bh[2];
                    ldmx2(smaddr(&Khp[(brl + nt * 8) * KSTR + kc * 16 + bcs]), bh);
                    mma16816(sacc[nt], qf[kc], bh);
                }
            }
        }

        uint32_t w0a = M32[mr0 * 4 + wk * 2],     w0b = M32[mr0 * 4 + wk * 2 + 1];
        uint32_t w1a = M32[mr1 * 4 + wk * 2],     w1b = M32[mr1 * 4 + wk * 2 + 1];
        float rm0 = -1e30f, rm1 = -1e30f;
#pragma unroll
        for (int nt = 0; nt < 8; nt++) {
            const int bit = (nt & 3) * 8 + ql2;
            uint32_t mw0 = (nt < 4) ? w0a : w0b;
            uint32_t mw1 = (nt < 4) ? w1a : w1b;
            sacc[nt][0] = ((mw0 >> bit) & 1)       ? -1e30f : sacc[nt][0] * SCL;
            sacc[nt][1] = ((mw0 >> (bit + 1)) & 1) ? -1e30f : sacc[nt][1] * SCL;
            sacc[nt][2] = ((mw1 >> bit) & 1)       ? -1e30f : sacc[nt][2] * SCL;
            sacc[nt][3] = ((mw1 >> (bit + 1)) & 1) ? -1e30f : sacc[nt][3] * SCL;
            rm0 = fmaxf(rm0, fmaxf(sacc[nt][0], sacc[nt][1]));
            rm1 = fmaxf(rm1, fmaxf(sacc[nt][2], sacc[nt][3]));
        }
        rm0 = fmaxf(rm0, __shfl_xor_sync(0xffffffffu, rm0, 1));
        rm0 = fmaxf(rm0, __shfl_xor_sync(0xffffffffu, rm0, 2));
        rm1 = fmaxf(rm1, __shfl_xor_sync(0xffffffffu, rm1, 1));
        rm1 = fmaxf(rm1, __shfl_xor_sync(0xffffffffu, rm1, 2));
        if ((lane & 3) == 0) { pm[w * 16 + rg] = rm0; pm[w * 16 + rg + 8] = rm1; }
        pairbar(pb);
        float mn0 = fmaxf(m_reg[0], fmaxf(rm0, pm[(w ^ 1) * 16 + rg]));
        float mn1 = fmaxf(m_reg[1], fmaxf(rm1, pm[(w ^ 1) * 16 + rg + 8]));
        float cf0 = ex2f(m_reg[0] - mn0);
        float cf1 = ex2f(m_reg[1] - mn1);

        float rs0 = 0.f, rs1 = 0.f;
#pragma unroll
        for (int nt = 0; nt < 8; nt++) {
            const int colb = wk * 64 + nt * 8 + ql2;
            float p00 = ex2f(sacc[nt][0] - mn0), p01 = ex2f(sacc[nt][1] - mn0);
            float p10 = ex2f(sacc[nt][2] - mn1), p11 = ex2f(sacc[nt][3] - mn1);
            rs0 += p00 + p01; rs1 += p10 + p11;
            *(__half2*)&Ph[mr0 * PSTR + colb] =
                __halves2half2(__float2half_rn(p00), __float2half_rn(p01));
            *(__half2*)&Ph[mr1 * PSTR + colb] =
                __halves2half2(__float2half_rn(p10), __float2half_rn(p11));
        }
        rs0 += __shfl_xor_sync(0xffffffffu, rs0, 1);
        rs0 += __shfl_xor_sync(0xffffffffu, rs0, 2);
        rs1 += __shfl_xor_sync(0xffffffffu, rs1, 1);
        rs1 += __shfl_xor_sync(0xffffffffu, rs1, 2);
        if ((lane & 3) == 0) { ps[w * 16 + rg] = rs0; ps[w * 16 + rg + 8] = rs1; }

#pragma unroll
        for (int nt = 0; nt < 4; nt++) {
            oacc[nt][0] *= cf0; oacc[nt][1] *= cf0;
            oacc[nt][2] *= cf1; oacc[nt][3] *= cf1;
        }
        pairbar(pb);
        l_reg[0] = l_reg[0] * cf0 + rs0 + ps[(w ^ 1) * 16 + rg];
        l_reg[1] = l_reg[1] * cf1 + rs1 + ps[(w ^ 1) * 16 + rg + 8];
        m_reg[0] = mn0; m_reg[1] = mn1;

        {
            const int prl = wq * 16 + (lane & 15);
            const int pcs = (lane >> 4) * 8;
            const int vrl = lane & 15;
#pragma unroll
            for (int kc = 0; kc < 8; kc++) {
                uint32_t pfh[4];
                ldmx4(smaddr(&Ph[prl * PSTR + kc * 16 + pcs]), pfh);
#pragma unroll
                for (int nt = 0; nt < 4; nt++) {
                    uint32_t vh[2];
                    ldmx2t(smaddr(&Vhp[(kc * 16 + vrl) * KSTR + wk * 32 + nt * 8]), vh);
                    mma16816(oacc[nt], pfh, vh);
                }
            }
        }
    }

    {
        float i0 = (l_reg[0] > 0.f) ? 1.f / l_reg[0] : 0.f;
        float i1 = (l_reg[1] > 0.f) ? 1.f / l_reg[1] : 0.f;
        const int c0 = h * 64 + wk * 32 + ql2;
        size_t o0 = ((size_t)b * NT + qt * 64 + mr0) * Cdim + c0;
        size_t o1 = ((size_t)b * NT + qt * 64 + mr1) * Cdim + c0;
#pragma unroll
        for (int nt = 0; nt < 4; nt++) {
            float a0 = oacc[nt][0] * i0, a1 = oacc[nt][1] * i0;
            float b0 = oacc[nt][2] * i1, b1 = oacc[nt][3] * i1;
            __half ha0 = __float2half_rn(a0), ha1 = __float2half_rn(a1);
            __half hb0 = __float2half_rn(b0), hb1 = __float2half_rn(b1);
            *(__half2*)(yh + o0 + nt * 8) = __halves2half2(ha0, ha1);
            *(__half2*)(yl + o0 + nt * 8) = __halves2half2(
                __float2half_rn(a0 - __half2float(ha0)),
                __float2half_rn(a1 - __half2float(ha1)));
            *(__half2*)(yh + o1 + nt * 8) = __halves2half2(hb0, hb1);
            *(__half2*)(yl + o1 + nt * 8) = __halves2half2(
                __float2half_rn(b0 - __half2float(hb0)),
                __float2half_rn(b1 - __half2float(hb1)));
        }
    }
}

// ---------------- launch ------------------------------------------------------------
extern "C" void kernel_launch(void* const* d_in, const int* in_sizes, int n_in,
                              void* d_out, int out_size)
{
    const float* x  = (const float*)d_in[0];
    const float* c  = (const float*)d_in[1];
    const void*  mk = d_in[2];
    const float* Wq = (const float*)d_in[3];
    const float* Wk = (const float*)d_in[4];
    const float* Wv = (const float*)d_in[5];
    const float* Wp = (const float*)d_in[6];
    float* out = (float*)d_out;

    __half *xh, *xl, *ch_, *cl_, *wqh, *wkh, *wvh, *wph;
    __half *qh, *kh, *vh, *yh, *yl;
    uint32_t* mb;
    cudaGetSymbolAddress((void**)&xh,  g_xh);  cudaGetSymbolAddress((void**)&xl,  g_xl);
    cudaGetSymbolAddress((void**)&ch_, g_ch);  cudaGetSymbolAddress((void**)&cl_, g_cl);
    cudaGetSymbolAddress((void**)&wqh, g_wqh);
    cudaGetSymbolAddress((void**)&wkh, g_wkh);
    cudaGetSymbolAddress((void**)&wvh, g_wvh);
    cudaGetSymbolAddress((void**)&wph, g_wph);
    cudaGetSymbolAddress((void**)&qh,  g_qh);
    cudaGetSymbolAddress((void**)&kh,  g_kh);
    cudaGetSymbolAddress((void**)&vh,  g_vh);
    cudaGetSymbolAddress((void**)&yh,  g_yh);  cudaGetSymbolAddress((void**)&yl,  g_yl);
    cudaGetSymbolAddress((void**)&mb,  g_mbits);

    cudaFuncSetAttribute(gemm_mma<2>, cudaFuncAttributeMaxDynamicSharedMemorySize,
                         GEMM_SMEM_BYTES);
    cudaFuncSetAttribute(gemm_mma<1>, cudaFuncAttributeMaxDynamicSharedMemorySize,
                         GEMM_SMEM_BYTES);
    cudaFuncSetAttribute(attn_mma, cudaFuncAttributeMaxDynamicSharedMemorySize,
                         ATT_SMEM_BYTES);

    detect_mask_mode<<<1, 256>>>((const unsigned char*)mk);
    mask_to_bits<<<(Bc * NT * NKT / 32) / 256, 256>>>(mk, mb);

    const int nx = Bc * NT * Cdim;
    const int nw = Cdim * Cdim;
    split_f32<<<nx / 1024, 256>>>(x,  xh,  xl,  nx);
    split_f32<<<nx / 1024, 256>>>(c,  ch_, cl_, nx);
    split_f32<<<nw / 1024, 256>>>(Wq, wqh, nullptr, nw);
    split_f32<<<nw / 1024, 256>>>(Wk, wkh, nullptr, nw);
    split_f32<<<nw / 1024, 256>>>(Wv, wvh, nullptr, nw);
    split_f32<<<nw / 1024, 256>>>(Wp, wph, nullptr, nw);

    // Q/K: 2-term (x exact, W fp16); V: 1-term; hi-only outputs
    gemm_mma<2><<<dim3(Cdim / 128, Bc * NT  / 128), 256, GEMM_SMEM_BYTES>>>(
        xh, xl, nullptr, nullptr, wqh, nullptr, nullptr, qh, nullptr, NT,  0, 0);
    gemm_mma<2><<<dim3(Cdim / 128, Bc * NKT / 128), 256, GEMM_SMEM_BYTES>>>(
        xh, xl, ch_, cl_,         wkh, nullptr, nullptr, kh, nullptr, NKT, 1, 0);
    gemm_mma<1><<<dim3(Cdim / 128, Bc * NKT / 128), 256, GEMM_SMEM_BYTES>>>(
        xh, nullptr, ch_, nullptr, wvh, nullptr, nullptr, vh, nullptr, NKT, 1, 0);

    attn_mma<<<dim3(NT / 64, Hh, Bc), 256, ATT_SMEM_BYTES>>>(
        qh, kh, vh, mb, yh, yl);

    // output projection: 2-term (y split exact-ish, Wp fp16)
    gemm_mma<2><<<dim3(Cdim / 128, Bc * NT / 128), 256, GEMM_SMEM_BYTES>>>(
        yh, yl, nullptr, nullptr, wph, nullptr, out, nullptr, nullptr, NT, 0, 1);
}

// round 13
// speedup vs baseline: 6.4626x; 1.0964x over previous
#include <cuda_runtime.h>
#include <cuda_fp16.h>
#include <stdint.h>

#define Bc   8
#define Hh   8
#define NT   1024
#define NKT  2048
#define Cdim 512
#define Dh   64

// ---------------- scratch (no allocation allowed) ------------------------------
__device__ __half g_xh[(size_t)Bc * NT * Cdim];
__device__ __half g_ch[(size_t)Bc * NT * Cdim];
__device__ __half g_wqh[Cdim * Cdim];
__device__ __half g_wkh[Cdim * Cdim];
__device__ __half g_wvh[Cdim * Cdim];
__device__ __half g_wph[Cdim * Cdim];
__device__ __half g_qh[(size_t)Bc * Hh * NT  * Dh];
__device__ __half g_kh[(size_t)Bc * Hh * NKT * Dh];
__device__ __half g_vh[(size_t)Bc * Hh * NKT * Dh];
__device__ __half g_yh[(size_t)Bc * NT * Cdim], g_yl[(size_t)Bc * NT * Cdim];
__device__ uint32_t g_mbits[(size_t)Bc * NT * NKT / 32];   // bit-packed mask (2 MB)
__device__ int    g_maskmode;

// ---------------- helpers -------------------------------------------------------
__device__ __forceinline__ uint32_t smaddr(const void* p) {
    return (uint32_t)__cvta_generic_to_shared(p);
}
__device__ __forceinline__ void cpa16(uint32_t d, const void* s) {
    asm volatile("cp.async.ca.shared.global [%0], [%1], 16;" :: "r"(d), "l"(s));
}
__device__ __forceinline__ void cpcommit() { asm volatile("cp.async.commit_group;"); }
__device__ __forceinline__ void cpwait0()  { asm volatile("cp.async.wait_group 0;"); }

__device__ __forceinline__ void ldmx4(uint32_t a, uint32_t* r) {
    asm volatile("ldmatrix.sync.aligned.m8n8.x4.shared.b16 {%0,%1,%2,%3}, [%4];"
                 : "=r"(r[0]), "=r"(r[1]), "=r"(r[2]), "=r"(r[3]) : "r"(a));
}
__device__ __forceinline__ void ldmx2(uint32_t a, uint32_t* r) {
    asm volatile("ldmatrix.sync.aligned.m8n8.x2.shared.b16 {%0,%1}, [%2];"
                 : "=r"(r[0]), "=r"(r[1]) : "r"(a));
}
__device__ __forceinline__ void ldmx2t(uint32_t a, uint32_t* r) {
    asm volatile("ldmatrix.sync.aligned.m8n8.x2.trans.shared.b16 {%0,%1}, [%2];"
                 : "=r"(r[0]), "=r"(r[1]) : "r"(a));
}
__device__ __forceinline__ void mma16816(float* c, const uint32_t* a, const uint32_t* b) {
    asm volatile("mma.sync.aligned.m16n8k16.row.col.f32.f16.f16.f32 "
                 "{%0,%1,%2,%3},{%4,%5,%6,%7},{%8,%9},{%0,%1,%2,%3};"
                 : "+f"(c[0]), "+f"(c[1]), "+f"(c[2]), "+f"(c[3])
                 : "r"(a[0]), "r"(a[1]), "r"(a[2]), "r"(a[3]), "r"(b[0]), "r"(b[1]));
}
__device__ __forceinline__ float ex2f(float x) {
    float y; asm("ex2.approx.f32 %0, %1;" : "=f"(y) : "f"(x)); return y;
}
__device__ __forceinline__ void pairbar(int id) {
    asm volatile("bar.sync %0, 64;" :: "r"(id) : "memory");
}

// ---------------- prep kernels ---------------------------------------------------
__global__ void split_f32(const float* __restrict__ s, __half* __restrict__ h,
                          __half* __restrict__ l, int n)
{
    int i = (blockIdx.x * blockDim.x + threadIdx.x) * 4;
    if (i >= n) return;
    float4 v = *(const float4*)(s + i);
    __half hx = __float2half_rn(v.x), hy = __float2half_rn(v.y);
    __half hz = __float2half_rn(v.z), hw = __float2half_rn(v.w);
    *(__half2*)(h + i)     = __halves2half2(hx, hy);
    *(__half2*)(h + i + 2) = __halves2half2(hz, hw);
    if (l) {
        *(__half2*)(l + i)     = __halves2half2(__float2half_rn(v.x - __half2float(hx)),
                                                __float2half_rn(v.y - __half2float(hy)));
        *(__half2*)(l + i + 2) = __halves2half2(__float2half_rn(v.z - __half2float(hz)),
                                                __float2half_rn(v.w - __half2float(hw)));
    }
}

__global__ void detect_mask_mode(const unsigned char* __restrict__ m) {
    bool hi = false, f3 = false;
    for (int i = threadIdx.x; i < 8192; i += blockDim.x) {
        unsigned char v = m[i];
        int p = i & 3;
        if (p == 3 && v == 0x3f) f3 = true;
        if (p != 0 && v != 0)    hi = true;
    }
    int a3 = __syncthreads_or(f3 ? 1 : 0);
    int ah = __syncthreads_or(hi ? 1 : 0);
    if (threadIdx.x == 0) g_maskmode = a3 ? 2 : (ah ? 0 : 1);
}

// pack mask (any dtype) into 1 bit per element
__global__ void mask_to_bits(const void* __restrict__ mp, uint32_t* __restrict__ o) {
    int mode = g_maskmode;
    size_t w = (size_t)blockIdx.x * blockDim.x + threadIdx.x;
    size_t base = w * 32;
    uint32_t bits = 0;
    if (mode == 0) {
        const uchar4* p = (const uchar4*)((const unsigned char*)mp + base);
#pragma unroll
        for (int q = 0; q < 8; q++) {
            uchar4 v = p[q];
            bits |= ((uint32_t)(v.x != 0) << (q * 4))
                  | ((uint32_t)(v.y != 0) << (q * 4 + 1))
                  | ((uint32_t)(v.z != 0) << (q * 4 + 2))
                  | ((uint32_t)(v.w != 0) << (q * 4 + 3));
        }
    } else if (mode == 1) {
        const int4* p = (const int4*)((const int*)mp + base);
#pragma unroll
        for (int q = 0; q < 8; q++) {
            int4 v = p[q];
            bits |= ((uint32_t)(v.x != 0) << (q * 4))
                  | ((uint32_t)(v.y != 0) << (q * 4 + 1))
                  | ((uint32_t)(v.z != 0) << (q * 4 + 2))
                  | ((uint32_t)(v.w != 0) << (q * 4 + 3));
        }
    } else {
        const float4* p = (const float4*)((const float*)mp + base);
#pragma unroll
        for (int q = 0; q < 8; q++) {
            float4 v = p[q];
            bits |= ((uint32_t)(v.x != 0.f) << (q * 4))
                  | ((uint32_t)(v.y != 0.f) << (q * 4 + 1))
                  | ((uint32_t)(v.z != 0.f) << (q * 4 + 2))
                  | ((uint32_t)(v.w != 0.f) << (q * 4 + 3));
        }
    }
    o[w] = bits;
}

// ---------------- GEMM: Y = A @ W^T (split-fp16, TERMS mma, cp.async 2-stage) ----
#define GKT 32
#define GSH 40
#define GSZ (128 * GSH)
#define GEMM_SMEM_BYTES (2 * 4 * GSZ * 2)

template <int TERMS>
__global__ __launch_bounds__(256, 2) void gemm_mma(
    const __half* __restrict__ Ah0, const __half* __restrict__ Al0,
    const __half* __restrict__ Ah1, const __half* __restrict__ Al1,
    const __half* __restrict__ Wh,  const __half* __restrict__ Wl,
    float* __restrict__ outF, __half* __restrict__ outH, __half* __restrict__ outL,
    int MrowsPerB, int modeIn, int modeOut)
{
    extern __shared__ __half gs[];
    const int tid = threadIdx.x, lane = tid & 31, w = tid >> 5;
    const int wm = w >> 2, wn = w & 3;
    const int m0 = blockIdx.y * 128, n0 = blockIdx.x * 128;
    const int lrow = tid >> 2;
    const int lch  = (tid & 3) * 8;

    const __half *arh[2], *arl[2], *brh[2], *brl[2];
#pragma unroll
    for (int p = 0; p < 2; p++) {
        int r = lrow + p * 64, gm = m0 + r;
        int bb = gm / MrowsPerB, mm = gm - bb * MrowsPerB;
        if (modeIn == 0 || mm < NT) {
            size_t off = ((size_t)bb * NT + mm) * Cdim;
            arh[p] = Ah0 + off;
            arl[p] = (TERMS >= 2) ? (Al0 + off) : nullptr;
        } else {
            size_t off = ((size_t)bb * NT + (mm - NT)) * Cdim;
            arh[p] = Ah1 + off;
            arl[p] = (TERMS >= 2) ? (Al1 + off) : nullptr;
        }
        size_t wo = (size_t)(n0 + r) * Cdim;
        brh[p] = Wh + wo;
        brl[p] = (TERMS == 3) ? (Wl + wo) : nullptr;
    }

    float acc[4][4][4];
#pragma unroll
    for (int a = 0; a < 4; a++)
#pragma unroll
        for (int b2 = 0; b2 < 4; b2++)
#pragma unroll
            for (int q = 0; q < 4; q++) acc[a][b2][q] = 0.f;

    const int arlr = wm * 64 + (lane & 15);
    const int acs  = (lane >> 4) * 8;
    const int brlr = wn * 32 + (lane & 7);
    const int bcs  = ((lane >> 3) & 1) * 8;

    auto loadStage = [&](int st, int k0) {
        __half* b = gs + st * 4 * GSZ;
        const uint32_t d0 = (uint32_t)(lrow * GSH + lch);
#pragma unroll
        for (int p = 0; p < 2; p++) {
            uint32_t d = d0 + p * 64 * GSH;
            cpa16(smaddr(b + d),           arh[p] + k0 + lch);
            if (TERMS >= 2)
                cpa16(smaddr(b + GSZ + d), arl[p] + k0 + lch);
            cpa16(smaddr(b + 2 * GSZ + d), brh[p] + k0 + lch);
            if (TERMS == 3)
                cpa16(smaddr(b + 3 * GSZ + d), brl[p] + k0 + lch);
        }
    };

    loadStage(0, 0); cpcommit();
    const int NTILES = Cdim / GKT;
    for (int t = 0; t < NTILES; t++) {
        cpwait0(); __syncthreads();
        if (t + 1 < NTILES) { loadStage((t + 1) & 1, (t + 1) * GKT); cpcommit(); }

        __half* Ash = gs + (t & 1) * 4 * GSZ;
        __half* Asl = Ash + GSZ;
        __half* Bsh = Ash + 2 * GSZ;
        __half* Bsl = Ash + 3 * GSZ;
#pragma unroll
        for (int ks = 0; ks < 2; ks++) {
            const int kcA = ks * 16 + acs, kcB = ks * 16 + bcs;
            uint32_t ah[4][4], al[4][4];
#pragma unroll
            for (int mt = 0; mt < 4; mt++) {
                ldmx4(smaddr(&Ash[(arlr + mt * 16) * GSH + kcA]), ah[mt]);
                if (TERMS >= 2)
                    ldmx4(smaddr(&Asl[(arlr + mt * 16) * GSH + kcA]), al[mt]);
            }
#pragma unroll
            for (int nt = 0; nt < 4; nt++) {
                uint32_t bh[2], bl[2];
                ldmx2(smaddr(&Bsh[(brlr + nt * 8) * GSH + kcB]), bh);
                if (TERMS == 3)
                    ldmx2(smaddr(&Bsl[(brlr + nt * 8) * GSH + kcB]), bl);
#pragma unroll
                for (int mt = 0; mt < 4; mt++)
                    mma16816(acc[mt][nt], ah[mt], bh);
                if (TERMS >= 2)
#pragma unroll
                    for (int mt = 0; mt < 4; mt++)
                        mma16816(acc[mt][nt], al[mt], bh);
                if (TERMS == 3)
#pragma unroll
                    for (int mt = 0; mt < 4; mt++)
                        mma16816(acc[mt][nt], ah[mt], bl);
            }
        }
    }

    const int er = m0 + wm * 64 + (lane >> 2);
    const int ec = n0 + wn * 32 + 2 * (lane & 3);
#pragma unroll
    for (int mt = 0; mt < 4; mt++)
#pragma unroll
        for (int nt = 0; nt < 4; nt++) {
            int col = ec + nt * 8;
#pragma unroll
            for (int hf = 0; hf < 2; hf++) {
                int   row = er + mt * 16 + hf * 8;
                float v0 = acc[mt][nt][hf * 2], v1 = acc[mt][nt][hf * 2 + 1];
                if (modeOut == 0) {
                    int bb = row / MrowsPerB, mm = row - bb * MrowsPerB;
                    int hh = col >> 6, dd = col & 63;
                    size_t p = (((size_t)(bb * Hh + hh)) * MrowsPerB + mm) * Dh + dd;
                    __half h0 = __float2half_rn(v0), h1 = __float2half_rn(v1);
                    *(__half2*)(outH + p) = __halves2half2(h0, h1);
                    if (outL)
                        *(__half2*)(outL + p) = __halves2half2(
                            __float2half_rn(v0 - __half2float(h0)),
                            __float2half_rn(v1 - __half2float(h1)));
                } else {
                    *(float2*)(outF + (size_t)row * Cdim + col) = make_float2(v0, v1);
                }
            }
        }
}

// ---------------- Flash attention v5 (unchanged from R12) --------------------------
#define QSTR 72
#define KSTR 72
#define PSTR 136
#define QSZ  (64 * QSTR)
#define KSZ  (128 * KSTR)
#define PSZ  (64 * PSTR)
#define MBSZ (64 * 16)
#define ATT_SMEM_BYTES ((QSZ + 4 * KSZ + PSZ) * 2 + 2 * MBSZ + 2 * 128 * 4)

__global__ __launch_bounds__(256, 2) void attn_mma(
    const __half* __restrict__ qhg, const __half* __restrict__ khg,
    const __half* __restrict__ vhg, const uint32_t* __restrict__ mbits,
    __half* __restrict__ yh, __half* __restrict__ yl)
{
    extern __shared__ __half sh[];
    __half* Qh = sh;
    __half* Kb = sh + QSZ;
    __half* Vb = sh + QSZ + 2 * KSZ;
    __half* Ph = sh + QSZ + 4 * KSZ;
    unsigned char* Mb = (unsigned char*)(sh + QSZ + 4 * KSZ + PSZ);
    float*  pm = (float*)(Mb + 2 * MBSZ);
    float*  ps = pm + 128;

    const int tid = threadIdx.x, lane = tid & 31, w = tid >> 5;
    const int wq = w >> 1, wk = w & 1;
    const int pb = 1 + (w >> 1);
    const int b = blockIdx.z, h = blockIdx.y, qt = blockIdx.x;

    const size_t kvo = ((size_t)(b * Hh + h)) * NKT * Dh;
    const unsigned char* mgb =
        (const unsigned char*)mbits + ((size_t)b * NT + (size_t)qt * 64) * (NKT / 8);

    auto loadStage = [&](int kt, int st) {
        __half* Khp = Kb + st * KSZ;
        __half* Vhp = Vb + st * KSZ;
#pragma unroll
        for (int i = 0; i < 4; i++) {
            int pos = tid + i * 256;
            int r = pos >> 3, cc = (pos & 7) * 8;
            size_t go = kvo + (size_t)(kt * 128 + r) * Dh + cc;
            uint32_t so = r * KSTR + cc;
            cpa16(smaddr(Khp + so), khg + go);
            cpa16(smaddr(Vhp + so), vhg + go);
        }
        if (tid < 64)
            cpa16(smaddr(Mb + st * MBSZ + tid * 16),
                  mgb + (size_t)tid * (NKT / 8) + kt * 16);
    };

    {
        const size_t qo = (((size_t)(b * Hh + h)) * NT + qt * 64) * Dh;
#pragma unroll
        for (int i = 0; i < 2; i++) {
            int pos = tid + i * 256;
            int r = pos >> 3, cc = (pos & 7) * 8;
            cpa16(smaddr(Qh + r * QSTR + cc), qhg + qo + r * Dh + cc);
        }
        loadStage(0, 0);
        cpcommit();
    }
    cpwait0(); __syncthreads();

    uint32_t qf[4][4];
    {
        const int rl = wq * 16 + (lane & 15);
        const int cs = (lane >> 4) * 8;
#pragma unroll
        for (int kc = 0; kc < 4; kc++)
            ldmx4(smaddr(&Qh[rl * QSTR + kc * 16 + cs]), qf[kc]);
    }

    float oacc[4][4];
#pragma unroll
    for (int nt = 0; nt < 4; nt++)
#pragma unroll
        for (int q = 0; q < 4; q++) oacc[nt][q] = 0.f;
    float m_reg[2] = {-1e30f, -1e30f};
    float l_reg[2] = {0.f, 0.f};

    const int rg  = lane >> 2;
    const int mr0 = wq * 16 + rg;
    const int mr1 = mr0 + 8;
    const int ql2 = (lane & 3) * 2;
    const float SCL = 0.125f * 1.44269504f;

    for (int kt = 0; kt < NKT / 128; kt++) {
        const int st = kt & 1;
        if (kt > 0) { cpwait0(); __syncthreads(); }
        if (kt + 1 < NKT / 128) { loadStage(kt + 1, st ^ 1); cpcommit(); }

        __half* Khp = Kb + st * KSZ;
        __half* Vhp = Vb + st * KSZ;
        const uint32_t* M32 = (const uint32_t*)(Mb + st * MBSZ);

        float sacc[8][4];
#pragma unroll
        for (int nt = 0; nt < 8; nt++)
#pragma unroll
            for (int q = 0; q < 4; q++) sacc[nt][q] = 0.f;
        {
            const int brl = wk * 64 + (lane & 7);
            const int bcs = ((lane >> 3) & 1) * 8;
#pragma unroll
            for (int kc = 0; kc < 4; kc++) {
#pragma unroll
                for (int nt = 0; nt < 8; nt++) {
                    uint32_t bh[2];
                    ldmx2(smaddr(&Khp[(brl + nt * 8) * KSTR + kc * 16 + bcs]), bh);
                    mma16816(sacc[nt], qf[kc], bh);
                }
            }
        }

        uint32_t w0a = M32[mr0 * 4 + wk * 2],     w0b = M32[mr0 * 4 + wk * 2 + 1];
        uint32_t w1a = M32[mr1 * 4 + wk * 2],     w1b = M32[mr1 * 4 + wk * 2 + 1];
        float rm0 = -1e30f, rm1 = -1e30f;
#pragma unroll
        for (int nt = 0; nt < 8; nt++) {
            const int bit = (nt & 3) * 8 + ql2;
            uint32_t mw0 = (nt < 4) ? w0a : w0b;
            uint32_t mw1 = (nt < 4) ? w1a : w1b;
            sacc[nt][0] = ((mw0 >> bit) & 1)       ? -1e30f : sacc[nt][0] * SCL;
            sacc[nt][1] = ((mw0 >> (bit + 1)) & 1) ? -1e30f : sacc[nt][1] * SCL;
            sacc[nt][2] = ((mw1 >> bit) & 1)       ? -1e30f : sacc[nt][2] * SCL;
            sacc[nt][3] = ((mw1 >> (bit + 1)) & 1) ? -1e30f : sacc[nt][3] * SCL;
            rm0 = fmaxf(rm0, fmaxf(sacc[nt][0], sacc[nt][1]));
            rm1 = fmaxf(rm1, fmaxf(sacc[nt][2], sacc[nt][3]));
        }
        rm0 = fmaxf(rm0, __shfl_xor_sync(0xffffffffu, rm0, 1));
        rm0 = fmaxf(rm0, __shfl_xor_sync(0xffffffffu, rm0, 2));
        rm1 = fmaxf(rm1, __shfl_xor_sync(0xffffffffu, rm1, 1));
        rm1 = fmaxf(rm1, __shfl_xor_sync(0xffffffffu, rm1, 2));
        if ((lane & 3) == 0) { pm[w * 16 + rg] = rm0; pm[w * 16 + rg + 8] = rm1; }
        pairbar(pb);
        float mn0 = fmaxf(m_reg[0], fmaxf(rm0, pm[(w ^ 1) * 16 + rg]));
        float mn1 = fmaxf(m_reg[1], fmaxf(rm1, pm[(w ^ 1) * 16 + rg + 8]));
        float cf0 = ex2f(m_reg[0] - mn0);
        float cf1 = ex2f(m_reg[1] - mn1);

        float rs0 = 0.f, rs1 = 0.f;
#pragma unroll
        for (int nt = 0; nt < 8; nt++) {
            const int colb = wk * 64 + nt * 8 + ql2;
            float p00 = ex2f(sacc[nt][0] - mn0), p01 = ex2f(sacc[nt][1] - mn0);
            float p10 = ex2f(sacc[nt][2] - mn1), p11 = ex2f(sacc[nt][3] - mn1);
            rs0 += p00 + p01; rs1 += p10 + p11;
            *(__half2*)&Ph[mr0 * PSTR + colb] =
                __halves2half2(__float2half_rn(p00), __float2half_rn(p01));
            *(__half2*)&Ph[mr1 * PSTR + colb] =
                __halves2half2(__float2half_rn(p10), __float2half_rn(p11));
        }
        rs0 += __shfl_xor_sync(0xffffffffu, rs0, 1);
        rs0 += __shfl_xor_sync(0xffffffffu, rs0, 2);
        rs1 += __shfl_xor_sync(0xffffffffu, rs1, 1);
        rs1 += __shfl_xor_sync(0xffffffffu, rs1, 2);
        if ((lane & 3) == 0) { ps[w * 16 + rg] = rs0; ps[w * 16 + rg + 8] = rs1; }

#pragma unroll
        for (int nt = 0; nt < 4; nt++) {
            oacc[nt][0] *= cf0; oacc[nt][1] *= cf0;
            oacc[nt][2] *= cf1; oacc[nt][3] *= cf1;
        }
        pairbar(pb);
        l_reg[0] = l_reg[0] * cf0 + rs0 + ps[(w ^ 1) * 16 + rg];
        l_reg[1] = l_reg[1] * cf1 + rs1 + ps[(w ^ 1) * 16 + rg + 8];
        m_reg[0] = mn0; m_reg[1] = mn1;

        {
            const int prl = wq * 16 + (lane & 15);
            const int pcs = (lane >> 4) * 8;
            const int vrl = lane & 15;
#pragma unroll
            for (int kc = 0; kc < 8; kc++) {
                uint32_t pfh[4];
                ldmx4(smaddr(&Ph[prl * PSTR + kc * 16 + pcs]), pfh);
#pragma unroll
                for (int nt = 0; nt < 4; nt++) {
                    uint32_t vh[2];
                    ldmx2t(smaddr(&Vhp[(kc * 16 + vrl) * KSTR + wk * 32 + nt * 8]), vh);
                    mma16816(oacc[nt], pfh, vh);
                }
            }
        }
    }

    {
        float i0 = (l_reg[0] > 0.f) ? 1.f / l_reg[0] : 0.f;
        float i1 = (l_reg[1] > 0.f) ? 1.f / l_reg[1] : 0.f;
        const int c0 = h * 64 + wk * 32 + ql2;
        size_t o0 = ((size_t)b * NT + qt * 64 + mr0) * Cdim + c0;
        size_t o1 = ((size_t)b * NT + qt * 64 + mr1) * Cdim + c0;
#pragma unroll
        for (int nt = 0; nt < 4; nt++) {
            float a0 = oacc[nt][0] * i0, a1 = oacc[nt][1] * i0;
            float b0 = oacc[nt][2] * i1, b1 = oacc[nt][3] * i1;
            __half ha0 = __float2half_rn(a0), ha1 = __float2half_rn(a1);
            __half hb0 = __float2half_rn(b0), hb1 = __float2half_rn(b1);
            *(__half2*)(yh + o0 + nt * 8) = __halves2half2(ha0, ha1);
            *(__half2*)(yl + o0 + nt * 8) = __halves2half2(
                __float2half_rn(a0 - __half2float(ha0)),
                __float2half_rn(a1 - __half2float(ha1)));
            *(__half2*)(yh + o1 + nt * 8) = __halves2half2(hb0, hb1);
            *(__half2*)(yl + o1 + nt * 8) = __halves2half2(
                __float2half_rn(b0 - __half2float(hb0)),
                __float2half_rn(b1 - __half2float(hb1)));
        }
    }
}

// ---------------- launch ------------------------------------------------------------
extern "C" void kernel_launch(void* const* d_in, const int* in_sizes, int n_in,
                              void* d_out, int out_size)
{
    const float* x  = (const float*)d_in[0];
    const float* c  = (const float*)d_in[1];
    const void*  mk = d_in[2];
    const float* Wq = (const float*)d_in[3];
    const float* Wk = (const float*)d_in[4];
    const float* Wv = (const float*)d_in[5];
    const float* Wp = (const float*)d_in[6];
    float* out = (float*)d_out;

    __half *xh, *ch_, *wqh, *wkh, *wvh, *wph;
    __half *qh, *kh, *vh, *yh, *yl;
    uint32_t* mb;
    cudaGetSymbolAddress((void**)&xh,  g_xh);
    cudaGetSymbolAddress((void**)&ch_, g_ch);
    cudaGetSymbolAddress((void**)&wqh, g_wqh);
    cudaGetSymbolAddress((void**)&wkh, g_wkh);
    cudaGetSymbolAddress((void**)&wvh, g_wvh);
    cudaGetSymbolAddress((void**)&wph, g_wph);
    cudaGetSymbolAddress((void**)&qh,  g_qh);
    cudaGetSymbolAddress((void**)&kh,  g_kh);
    cudaGetSymbolAddress((void**)&vh,  g_vh);
    cudaGetSymbolAddress((void**)&yh,  g_yh);  cudaGetSymbolAddress((void**)&yl,  g_yl);
    cudaGetSymbolAddress((void**)&mb,  g_mbits);

    cudaFuncSetAttribute(gemm_mma<2>, cudaFuncAttributeMaxDynamicSharedMemorySize,
                         GEMM_SMEM_BYTES);
    cudaFuncSetAttribute(gemm_mma<1>, cudaFuncAttributeMaxDynamicSharedMemorySize,
                         GEMM_SMEM_BYTES);
    cudaFuncSetAttribute(attn_mma, cudaFuncAttributeMaxDynamicSharedMemorySize,
                         ATT_SMEM_BYTES);

    detect_mask_mode<<<1, 256>>>((const unsigned char*)mk);
    mask_to_bits<<<(Bc * NT * NKT / 32) / 256, 256>>>(mk, mb);

    const int nx = Bc * NT * Cdim;
    const int nw = Cdim * Cdim;
    split_f32<<<nx / 1024, 256>>>(x,  xh,  nullptr, nx);
    split_f32<<<nx / 1024, 256>>>(c,  ch_, nullptr, nx);
    split_f32<<<nw / 1024, 256>>>(Wq, wqh, nullptr, nw);
    split_f32<<<nw / 1024, 256>>>(Wk, wkh, nullptr, nw);
    split_f32<<<nw / 1024, 256>>>(Wv, wvh, nullptr, nw);
    split_f32<<<nw / 1024, 256>>>(Wp, wph, nullptr, nw);

    // Q/K/V projections: all 1-term (x_h * W_h), hi-only outputs
    gemm_mma<1><<<dim3(Cdim / 128, Bc * NT  / 128), 256, GEMM_SMEM_BYTES>>>(
        xh, nullptr, nullptr, nullptr, wqh, nullptr, nullptr, qh, nullptr, NT,  0, 0);
    gemm_mma<1><<<dim3(Cdim / 128, Bc * NKT / 128), 256, GEMM_SMEM_BYTES>>>(
        xh, nullptr, ch_, nullptr,    wkh, nullptr, nullptr, kh, nullptr, NKT, 1, 0);
    gemm_mma<1><<<dim3(Cdim / 128, Bc * NKT / 128), 256, GEMM_SMEM_BYTES>>>(
        xh, nullptr, ch_, nullptr,    wvh, nullptr, nullptr, vh, nullptr, NKT, 1, 0);

    attn_mma<<<dim3(NT / 64, Hh, Bc), 256, ATT_SMEM_BYTES>>>(
        qh, kh, vh, mb, yh, yl);

    // output projection: 2-term (y hi+lo, Wp fp16)
    gemm_mma<2><<<dim3(Cdim / 128, Bc * NT / 128), 256, GEMM_SMEM_BYTES>>>(
        yh, yl, nullptr, nullptr, wph, nullptr, out, nullptr, nullptr, NT, 0, 1);
}

// round 14
// speedup vs baseline: 7.0128x; 1.0851x over previous
#include <cuda_runtime.h>
#include <cuda_fp16.h>
#include <stdint.h>

#define Bc   8
#define Hh   8
#define NT   1024
#define NKT  2048
#define Cdim 512
#define Dh   64

// ---------------- scratch (no allocation allowed) ------------------------------
__device__ __half g_xh[(size_t)Bc * NT * Cdim];
__device__ __half g_ch[(size_t)Bc * NT * Cdim];
__device__ __half g_wqh[Cdim * Cdim];
__device__ __half g_wkh[Cdim * Cdim];
__device__ __half g_wvh[Cdim * Cdim];
__device__ __half g_wph[Cdim * Cdim];
__device__ __half g_qh[(size_t)Bc * Hh * NT  * Dh];
__device__ __half g_kh[(size_t)Bc * Hh * NKT * Dh];
__device__ __half g_vh[(size_t)Bc * Hh * NKT * Dh];
__device__ __half g_yh[(size_t)Bc * NT * Cdim], g_yl[(size_t)Bc * NT * Cdim];
__device__ uint32_t g_mbits[(size_t)Bc * NT * NKT / 32];   // bit-packed mask (2 MB)
__device__ int    g_maskmode;

// ---------------- helpers -------------------------------------------------------
__device__ __forceinline__ uint32_t smaddr(const void* p) {
    return (uint32_t)__cvta_generic_to_shared(p);
}
__device__ __forceinline__ void cpa16(uint32_t d, const void* s) {
    asm volatile("cp.async.ca.shared.global [%0], [%1], 16;" :: "r"(d), "l"(s));
}
__device__ __forceinline__ void cpcommit() { asm volatile("cp.async.commit_group;"); }
__device__ __forceinline__ void cpwait0()  { asm volatile("cp.async.wait_group 0;"); }

__device__ __forceinline__ void ldmx4(uint32_t a, uint32_t* r) {
    asm volatile("ldmatrix.sync.aligned.m8n8.x4.shared.b16 {%0,%1,%2,%3}, [%4];"
                 : "=r"(r[0]), "=r"(r[1]), "=r"(r[2]), "=r"(r[3]) : "r"(a));
}
__device__ __forceinline__ void ldmx2(uint32_t a, uint32_t* r) {
    asm volatile("ldmatrix.sync.aligned.m8n8.x2.shared.b16 {%0,%1}, [%2];"
                 : "=r"(r[0]), "=r"(r[1]) : "r"(a));
}
__device__ __forceinline__ void ldmx2t(uint32_t a, uint32_t* r) {
    asm volatile("ldmatrix.sync.aligned.m8n8.x2.trans.shared.b16 {%0,%1}, [%2];"
                 : "=r"(r[0]), "=r"(r[1]) : "r"(a));
}
__device__ __forceinline__ void mma16816(float* c, const uint32_t* a, const uint32_t* b) {
    asm volatile("mma.sync.aligned.m16n8k16.row.col.f32.f16.f16.f32 "
                 "{%0,%1,%2,%3},{%4,%5,%6,%7},{%8,%9},{%0,%1,%2,%3};"
                 : "+f"(c[0]), "+f"(c[1]), "+f"(c[2]), "+f"(c[3])
                 : "r"(a[0]), "r"(a[1]), "r"(a[2]), "r"(a[3]), "r"(b[0]), "r"(b[1]));
}
__device__ __forceinline__ float ex2f(float x) {
    float y; asm("ex2.approx.f32 %0, %1;" : "=f"(y) : "f"(x)); return y;
}
// packed fp16x2 exp2: one MUFU op per two values
__device__ __forceinline__ uint32_t h2ex2(float a, float b) {
    __half2 hin = __floats2half2_rn(a, b);
    uint32_t in = *(uint32_t*)&hin, out;
    asm("ex2.approx.f16x2 %0, %1;" : "=r"(out) : "r"(in));
    return out;
}
__device__ __forceinline__ void pairbar(int id) {
    asm volatile("bar.sync %0, 64;" :: "r"(id) : "memory");
}

// ---------------- prep kernels ---------------------------------------------------
__global__ void split_f32(const float* __restrict__ s, __half* __restrict__ h, int n)
{
    int i = (blockIdx.x * blockDim.x + threadIdx.x) * 4;
    if (i >= n) return;
    float4 v = *(const float4*)(s + i);
    *(__half2*)(h + i)     = __halves2half2(__float2half_rn(v.x), __float2half_rn(v.y));
    *(__half2*)(h + i + 2) = __halves2half2(__float2half_rn(v.z), __float2half_rn(v.w));
}

// all four weights in one launch: which = blockIdx.x >> 8 (each weight = 256 blocks)
__global__ void split_w4(const float* __restrict__ s0, const float* __restrict__ s1,
                         const float* __restrict__ s2, const float* __restrict__ s3,
                         __half* __restrict__ d0, __half* __restrict__ d1,
                         __half* __restrict__ d2, __half* __restrict__ d3)
{
    int which = blockIdx.x >> 8;
    int i = ((blockIdx.x & 255) * blockDim.x + threadIdx.x) * 4;
    const float* s = which == 0 ? s0 : which == 1 ? s1 : which == 2 ? s2 : s3;
    __half*      d = which == 0 ? d0 : which == 1 ? d1 : which == 2 ? d2 : d3;
    float4 v = *(const float4*)(s + i);
    *(__half2*)(d + i)     = __halves2half2(__float2half_rn(v.x), __float2half_rn(v.y));
    *(__half2*)(d + i + 2) = __halves2half2(__float2half_rn(v.z), __float2half_rn(v.w));
}

__global__ void split_f32l(const float* __restrict__ s, __half* __restrict__ h,
                           __half* __restrict__ l, int n)
{
    int i = (blockIdx.x * blockDim.x + threadIdx.x) * 4;
    if (i >= n) return;
    float4 v = *(const float4*)(s + i);
    __half hx = __float2half_rn(v.x), hy = __float2half_rn(v.y);
    __half hz = __float2half_rn(v.z), hw = __float2half_rn(v.w);
    *(__half2*)(h + i)     = __halves2half2(hx, hy);
    *(__half2*)(h + i + 2) = __halves2half2(hz, hw);
    *(__half2*)(l + i)     = __halves2half2(__float2half_rn(v.x - __half2float(hx)),
                                            __float2half_rn(v.y - __half2float(hy)));
    *(__half2*)(l + i + 2) = __halves2half2(__float2half_rn(v.z - __half2float(hz)),
                                            __float2half_rn(v.w - __half2float(hw)));
}

__global__ void detect_mask_mode(const unsigned char* __restrict__ m) {
    bool hi = false, f3 = false;
    for (int i = threadIdx.x; i < 8192; i += blockDim.x) {
        unsigned char v = m[i];
        int p = i & 3;
        if (p == 3 && v == 0x3f) f3 = true;
        if (p != 0 && v != 0)    hi = true;
    }
    int a3 = __syncthreads_or(f3 ? 1 : 0);
    int ah = __syncthreads_or(hi ? 1 : 0);
    if (threadIdx.x == 0) g_maskmode = a3 ? 2 : (ah ? 0 : 1);
}

__global__ void mask_to_bits(const void* __restrict__ mp, uint32_t* __restrict__ o) {
    int mode = g_maskmode;
    size_t w = (size_t)blockIdx.x * blockDim.x + threadIdx.x;
    size_t base = w * 32;
    uint32_t bits = 0;
    if (mode == 0) {
        const uchar4* p = (const uchar4*)((const unsigned char*)mp + base);
#pragma unroll
        for (int q = 0; q < 8; q++) {
            uchar4 v = p[q];
            bits |= ((uint32_t)(v.x != 0) << (q * 4))
                  | ((uint32_t)(v.y != 0) << (q * 4 + 1))
                  | ((uint32_t)(v.z != 0) << (q * 4 + 2))
                  | ((uint32_t)(v.w != 0) << (q * 4 + 3));
        }
    } else if (mode == 1) {
        const int4* p = (const int4*)((const int*)mp + base);
#pragma unroll
        for (int q = 0; q < 8; q++) {
            int4 v = p[q];
            bits |= ((uint32_t)(v.x != 0) << (q * 4))
                  | ((uint32_t)(v.y != 0) << (q * 4 + 1))
                  | ((uint32_t)(v.z != 0) << (q * 4 + 2))
                  | ((uint32_t)(v.w != 0) << (q * 4 + 3));
        }
    } else {
        const float4* p = (const float4*)((const float*)mp + base);
#pragma unroll
        for (int q = 0; q < 8; q++) {
            float4 v = p[q];
            bits |= ((uint32_t)(v.x != 0.f) << (q * 4))
                  | ((uint32_t)(v.y != 0.f) << (q * 4 + 1))
                  | ((uint32_t)(v.z != 0.f) << (q * 4 + 2))
                  | ((uint32_t)(v.w != 0.f) << (q * 4 + 3));
        }
    }
    o[w] = bits;
}

// ---------------- GEMM: Y = A @ W^T (split-fp16, TERMS mma, cp.async 2-stage) ----
// Optional fused second weight: blocks with n0 >= Cdim use Wh2/outH2.
#define GKT 32
#define GSH 40
#define GSZ (128 * GSH)
#define GEMM_SMEM_BYTES (2 * 4 * GSZ * 2)

template <int TERMS>
__global__ __launch_bounds__(256, 2) void gemm_mma(
    const __half* __restrict__ Ah0, const __half* __restrict__ Al0,
    const __half* __restrict__ Ah1, const __half* __restrict__ Al1,
    const __half* __restrict__ Wh,  const __half* __restrict__ Wh2,
    float* __restrict__ outF, __half* __restrict__ outH, __half* __restrict__ outH2,
    __half* __restrict__ outL,
    int MrowsPerB, int modeIn, int modeOut)
{
    extern __shared__ __half gs[];
    const int tid = threadIdx.x, lane = tid & 31, w = tid >> 5;
    const int wm = w >> 2, wn = w & 3;
    const int m0 = blockIdx.y * 128;
    int n0 = blockIdx.x * 128;
    const __half* Wsel = Wh;
    __half* outSel = outH;
    if (Wh2 != nullptr && n0 >= Cdim) { Wsel = Wh2; outSel = outH2; n0 -= Cdim; }
    const int lrow = tid >> 2;
    const int lch  = (tid & 3) * 8;

    const __half *arh[2], *arl[2], *brh[2];
#pragma unroll
    for (int p = 0; p < 2; p++) {
        int r = lrow + p * 64, gm = m0 + r;
        int bb = gm / MrowsPerB, mm = gm - bb * MrowsPerB;
        if (modeIn == 0 || mm < NT) {
            size_t off = ((size_t)bb * NT + mm) * Cdim;
            arh[p] = Ah0 + off;
            arl[p] = (TERMS >= 2) ? (Al0 + off) : nullptr;
        } else {
            size_t off = ((size_t)bb * NT + (mm - NT)) * Cdim;
            arh[p] = Ah1 + off;
            arl[p] = (TERMS >= 2) ? (Al1 + off) : nullptr;
        }
        brh[p] = Wsel + (size_t)(n0 + r) * Cdim;
    }

    float acc[4][4][4];
#pragma unroll
    for (int a = 0; a < 4; a++)
#pragma unroll
        for (int b2 = 0; b2 < 4; b2++)
#pragma unroll
            for (int q = 0; q < 4; q++) acc[a][b2][q] = 0.f;

    const int arlr = wm * 64 + (lane & 15);
    const int acs  = (lane >> 4) * 8;
    const int brlr = wn * 32 + (lane & 7);
    const int bcs  = ((lane >> 3) & 1) * 8;

    auto loadStage = [&](int st, int k0) {
        __half* b = gs + st * 4 * GSZ;
        const uint32_t d0 = (uint32_t)(lrow * GSH + lch);
#pragma unroll
        for (int p = 0; p < 2; p++) {
            uint32_t d = d0 + p * 64 * GSH;
            cpa16(smaddr(b + d),           arh[p] + k0 + lch);
            if (TERMS >= 2)
                cpa16(smaddr(b + GSZ + d), arl[p] + k0 + lch);
            cpa16(smaddr(b + 2 * GSZ + d), brh[p] + k0 + lch);
        }
    };

    loadStage(0, 0); cpcommit();
    const int NTILES = Cdim / GKT;
    for (int t = 0; t < NTILES; t++) {
        cpwait0(); __syncthreads();
        if (t + 1 < NTILES) { loadStage((t + 1) & 1, (t + 1) * GKT); cpcommit(); }

        __half* Ash = gs + (t & 1) * 4 * GSZ;
        __half* Asl = Ash + GSZ;
        __half* Bsh = Ash + 2 * GSZ;
#pragma unroll
        for (int ks = 0; ks < 2; ks++) {
            const int kcA = ks * 16 + acs, kcB = ks * 16 + bcs;
            uint32_t ah[4][4], al[4][4];
#pragma unroll
            for (int mt = 0; mt < 4; mt++) {
                ldmx4(smaddr(&Ash[(arlr + mt * 16) * GSH + kcA]), ah[mt]);
                if (TERMS >= 2)
                    ldmx4(smaddr(&Asl[(arlr + mt * 16) * GSH + kcA]), al[mt]);
            }
#pragma unroll
            for (int nt = 0; nt < 4; nt++) {
                uint32_t bh[2];
                ldmx2(smaddr(&Bsh[(brlr + nt * 8) * GSH + kcB]), bh);
#pragma unroll
                for (int mt = 0; mt < 4; mt++)
                    mma16816(acc[mt][nt], ah[mt], bh);
                if (TERMS >= 2)
#pragma unroll
                    for (int mt = 0; mt < 4; mt++)
                        mma16816(acc[mt][nt], al[mt], bh);
            }
        }
    }

    const int er = m0 + wm * 64 + (lane >> 2);
    const int ec = n0 + wn * 32 + 2 * (lane & 3);
#pragma unroll
    for (int mt = 0; mt < 4; mt++)
#pragma unroll
        for (int nt = 0; nt < 4; nt++) {
            int col = ec + nt * 8;
#pragma unroll
            for (int hf = 0; hf < 2; hf++) {
                int   row = er + mt * 16 + hf * 8;
                float v0 = acc[mt][nt][hf * 2], v1 = acc[mt][nt][hf * 2 + 1];
                if (modeOut == 0) {
                    int bb = row / MrowsPerB, mm = row - bb * MrowsPerB;
                    int hh = col >> 6, dd = col & 63;
                    size_t p = (((size_t)(bb * Hh + hh)) * MrowsPerB + mm) * Dh + dd;
                    *(__half2*)(outSel + p) =
                        __halves2half2(__float2half_rn(v0), __float2half_rn(v1));
                } else {
                    *(float2*)(outF + (size_t)row * Cdim + col) = make_float2(v0, v1);
                }
            }
        }
}

// ---------------- Flash attention v6 (f16x2 exp) ------------------------------------
#define QSTR 72
#define KSTR 72
#define PSTR 136
#define QSZ  (64 * QSTR)
#define KSZ  (128 * KSTR)
#define PSZ  (64 * PSTR)
#define MBSZ (64 * 16)
#define ATT_SMEM_BYTES ((QSZ + 4 * KSZ + PSZ) * 2 + 2 * MBSZ + 2 * 128 * 4)

__global__ __launch_bounds__(256, 2) void attn_mma(
    const __half* __restrict__ qhg, const __half* __restrict__ khg,
    const __half* __restrict__ vhg, const uint32_t* __restrict__ mbits,
    __half* __restrict__ yh, __half* __restrict__ yl)
{
    extern __shared__ __half sh[];
    __half* Qh = sh;
    __half* Kb = sh + QSZ;
    __half* Vb = sh + QSZ + 2 * KSZ;
    __half* Ph = sh + QSZ + 4 * KSZ;
    unsigned char* Mb = (unsigned char*)(sh + QSZ + 4 * KSZ + PSZ);
    float*  pm = (float*)(Mb + 2 * MBSZ);
    float*  ps = pm + 128;

    const int tid = threadIdx.x, lane = tid & 31, w = tid >> 5;
    const int wq = w >> 1, wk = w & 1;
    const int pb = 1 + (w >> 1);
    const int b = blockIdx.z, h = blockIdx.y, qt = blockIdx.x;

    const size_t kvo = ((size_t)(b * Hh + h)) * NKT * Dh;
    const unsigned char* mgb =
        (const unsigned char*)mbits + ((size_t)b * NT + (size_t)qt * 64) * (NKT / 8);

    auto loadStage = [&](int kt, int st) {
        __half* Khp = Kb + st * KSZ;
        __half* Vhp = Vb + st * KSZ;
#pragma unroll
        for (int i = 0; i < 4; i++) {
            int pos = tid + i * 256;
            int r = pos >> 3, cc = (pos & 7) * 8;
            size_t go = kvo + (size_t)(kt * 128 + r) * Dh + cc;
            uint32_t so = r * KSTR + cc;
            cpa16(smaddr(Khp + so), khg + go);
            cpa16(smaddr(Vhp + so), vhg + go);
        }
        if (tid < 64)
            cpa16(smaddr(Mb + st * MBSZ + tid * 16),
                  mgb + (size_t)tid * (NKT / 8) + kt * 16);
    };

    {
        const size_t qo = (((size_t)(b * Hh + h)) * NT + qt * 64) * Dh;
#pragma unroll
        for (int i = 0; i < 2; i++) {
            int pos = tid + i * 256;
            int r = pos >> 3, cc = (pos & 7) * 8;
            cpa16(smaddr(Qh + r * QSTR + cc), qhg + qo + r * Dh + cc);
        }
        loadStage(0, 0);
        cpcommit();
    }
    cpwait0(); __syncthreads();

    uint32_t qf[4][4];
    {
        const int rl = wq * 16 + (lane & 15);
        const int cs = (lane >> 4) * 8;
#pragma unroll
        for (int kc = 0; kc < 4; kc++)
            ldmx4(smaddr(&Qh[rl * QSTR + kc * 16 + cs]), qf[kc]);
    }

    float oacc[4][4];
#pragma unroll
    for (int nt = 0; nt < 4; nt++)
#pragma unroll
        for (int q = 0; q < 4; q++) oacc[nt][q] = 0.f;
    float m_reg[2] = {-1e30f, -1e30f};
    float l_reg[2] = {0.f, 0.f};

    const int rg  = lane >> 2;
    const int mr0 = wq * 16 + rg;
    const int mr1 = mr0 + 8;
    const int ql2 = (lane & 3) * 2;
    const float SCL = 0.125f * 1.44269504f;

    for (int kt = 0; kt < NKT / 128; kt++) {
        const int st = kt & 1;
        if (kt > 0) { cpwait0(); __syncthreads(); }
        if (kt + 1 < NKT / 128) { loadStage(kt + 1, st ^ 1); cpcommit(); }

        __half* Khp = Kb + st * KSZ;
        __half* Vhp = Vb + st * KSZ;
        const uint32_t* M32 = (const uint32_t*)(Mb + st * MBSZ);

        float sacc[8][4];
#pragma unroll
        for (int nt = 0; nt < 8; nt++)
#pragma unroll
            for (int q = 0; q < 4; q++) sacc[nt][q] = 0.f;
        {
            const int brl = wk * 64 + (lane & 7);
            const int bcs = ((lane >> 3) & 1) * 8;
#pragma unroll
            for (int kc = 0; kc < 4; kc++) {
#pragma unroll
                for (int nt = 0; nt < 8; nt++) {
                    uint32_t bh[2];
                    ldmx2(smaddr(&Khp[(brl + nt * 8) * KSTR + kc * 16 + bcs]), bh);
                    mma16816(sacc[nt], qf[kc], bh);
                }
            }
        }

        uint32_t w0a = M32[mr0 * 4 + wk * 2],     w0b = M32[mr0 * 4 + wk * 2 + 1];
        uint32_t w1a = M32[mr1 * 4 + wk * 2],     w1b = M32[mr1 * 4 + wk * 2 + 1];
        float rm0 = -1e30f, rm1 = -1e30f;
#pragma unroll
        for (int nt = 0; nt < 8; nt++) {
            const int bit = (nt & 3) * 8 + ql2;
            uint32_t mw0 = (nt < 4) ? w0a : w0b;
            uint32_t mw1 = (nt < 4) ? w1a : w1b;
            sacc[nt][0] = ((mw0 >> bit) & 1)       ? -1e30f : sacc[nt][0] * SCL;
            sacc[nt][1] = ((mw0 >> (bit + 1)) & 1) ? -1e30f : sacc[nt][1] * SCL;
            sacc[nt][2] = ((mw1 >> bit) & 1)       ? -1e30f : sacc[nt][2] * SCL;
            sacc[nt][3] = ((mw1 >> (bit + 1)) & 1) ? -1e30f : sacc[nt][3] * SCL;
            rm0 = fmaxf(rm0, fmaxf(sacc[nt][0], sacc[nt][1]));
            rm1 = fmaxf(rm1, fmaxf(sacc[nt][2], sacc[nt][3]));
        }
        rm0 = fmaxf(rm0, __shfl_xor_sync(0xffffffffu, rm0, 1));
        rm0 = fmaxf(rm0, __shfl_xor_sync(0xffffffffu, rm0, 2));
        rm1 = fmaxf(rm1, __shfl_xor_sync(0xffffffffu, rm1, 1));
        rm1 = fmaxf(rm1, __shfl_xor_sync(0xffffffffu, rm1, 2));
        if ((lane & 3) == 0) { pm[w * 16 + rg] = rm0; pm[w * 16 + rg + 8] = rm1; }
        pairbar(pb);
        float mn0 = fmaxf(m_reg[0], fmaxf(rm0, pm[(w ^ 1) * 16 + rg]));
        float mn1 = fmaxf(m_reg[1], fmaxf(rm1, pm[(w ^ 1) * 16 + rg + 8]));
        float cf0 = ex2f(m_reg[0] - mn0);
        float cf1 = ex2f(m_reg[1] - mn1);

        // --- exp (fp16x2), P store, row sum ---
        float rs0 = 0.f, rs1 = 0.f;
#pragma unroll
        for (int nt = 0; nt < 8; nt++) {
            const int colb = wk * 64 + nt * 8 + ql2;
            uint32_t p0 = h2ex2(sacc[nt][0] - mn0, sacc[nt][1] - mn0);
            uint32_t p1 = h2ex2(sacc[nt][2] - mn1, sacc[nt][3] - mn1);
            *(uint32_t*)&Ph[mr0 * PSTR + colb] = p0;
            *(uint32_t*)&Ph[mr1 * PSTR + colb] = p1;
            float2 f0 = __half22float2(*(__half2*)&p0);
            float2 f1 = __half22float2(*(__half2*)&p1);
            rs0 += f0.x + f0.y;
            rs1 += f1.x + f1.y;
        }
        rs0 += __shfl_xor_sync(0xffffffffu, rs0, 1);
        rs0 += __shfl_xor_sync(0xffffffffu, rs0, 2);
        rs1 += __shfl_xor_sync(0xffffffffu, rs1, 1);
        rs1 += __shfl_xor_sync(0xffffffffu, rs1, 2);
        if ((lane & 3) == 0) { ps[w * 16 + rg] = rs0; ps[w * 16 + rg + 8] = rs1; }

#pragma unroll
        for (int nt = 0; nt < 4; nt++) {
            oacc[nt][0] *= cf0; oacc[nt][1] *= cf0;
            oacc[nt][2] *= cf1; oacc[nt][3] *= cf1;
        }
        pairbar(pb);
        l_reg[0] = l_reg[0] * cf0 + rs0 + ps[(w ^ 1) * 16 + rg];
        l_reg[1] = l_reg[1] * cf1 + rs1 + ps[(w ^ 1) * 16 + rg + 8];
        m_reg[0] = mn0; m_reg[1] = mn1;

        {
            const int prl = wq * 16 + (lane & 15);
            const int pcs = (lane >> 4) * 8;
            const int vrl = lane & 15;
#pragma unroll
            for (int kc = 0; kc < 8; kc++) {
                uint32_t pfh[4];
                ldmx4(smaddr(&Ph[prl * PSTR + kc * 16 + pcs]), pfh);
#pragma unroll
                for (int nt = 0; nt < 4; nt++) {
                    uint32_t vh[2];
                    ldmx2t(smaddr(&Vhp[(kc * 16 + vrl) * KSTR + wk * 32 + nt * 8]), vh);
                    mma16816(oacc[nt], pfh, vh);
                }
            }
        }
    }

    {
        float i0 = (l_reg[0] > 0.f) ? 1.f / l_reg[0] : 0.f;
        float i1 = (l_reg[1] > 0.f) ? 1.f / l_reg[1] : 0.f;
        const int c0 = h * 64 + wk * 32 + ql2;
        size_t o0 = ((size_t)b * NT + qt * 64 + mr0) * Cdim + c0;
        size_t o1 = ((size_t)b * NT + qt * 64 + mr1) * Cdim + c0;
#pragma unroll
        for (int nt = 0; nt < 4; nt++) {
            float a0 = oacc[nt][0] * i0, a1 = oacc[nt][1] * i0;
            float b0 = oacc[nt][2] * i1, b1 = oacc[nt][3] * i1;
            __half ha0 = __float2half_rn(a0), ha1 = __float2half_rn(a1);
            __half hb0 = __float2half_rn(b0), hb1 = __float2half_rn(b1);
            *(__half2*)(yh + o0 + nt * 8) = __halves2half2(ha0, ha1);
            *(__half2*)(yl + o0 + nt * 8) = __halves2half2(
                __float2half_rn(a0 - __half2float(ha0)),
                __float2half_rn(a1 - __half2float(ha1)));
            *(__half2*)(yh + o1 + nt * 8) = __halves2half2(hb0, hb1);
            *(__half2*)(yl + o1 + nt * 8) = __halves2half2(
                __float2half_rn(b0 - __half2float(hb0)),
                __float2half_rn(b1 - __half2float(hb1)));
        }
    }
}

// ---------------- launch ------------------------------------------------------------
extern "C" void kernel_launch(void* const* d_in, const int* in_sizes, int n_in,
                              void* d_out, int out_size)
{
    const float* x  = (const float*)d_in[0];
    const float* c  = (const float*)d_in[1];
    const void*  mk = d_in[2];
    const float* Wq = (const float*)d_in[3];
    const float* Wk = (const float*)d_in[4];
    const float* Wv = (const float*)d_in[5];
    const float* Wp = (const float*)d_in[6];
    float* out = (float*)d_out;

    __half *xh, *ch_, *wqh, *wkh, *wvh, *wph;
    __half *qh, *kh, *vh, *yh, *yl;
    uint32_t* mb;
    cudaGetSymbolAddress((void**)&xh,  g_xh);
    cudaGetSymbolAddress((void**)&ch_, g_ch);
    cudaGetSymbolAddress((void**)&wqh, g_wqh);
    cudaGetSymbolAddress((void**)&wkh, g_wkh);
    cudaGetSymbolAddress((void**)&wvh, g_wvh);
    cudaGetSymbolAddress((void**)&wph, g_wph);
    cudaGetSymbolAddress((void**)&qh,  g_qh);
    cudaGetSymbolAddress((void**)&kh,  g_kh);
    cudaGetSymbolAddress((void**)&vh,  g_vh);
    cudaGetSymbolAddress((void**)&yh,  g_yh);  cudaGetSymbolAddress((void**)&yl,  g_yl);
    cudaGetSymbolAddress((void**)&mb,  g_mbits);

    cudaFuncSetAttribute(gemm_mma<2>, cudaFuncAttributeMaxDynamicSharedMemorySize,
                         GEMM_SMEM_BYTES);
    cudaFuncSetAttribute(gemm_mma<1>, cudaFuncAttributeMaxDynamicSharedMemorySize,
                         GEMM_SMEM_BYTES);
    cudaFuncSetAttribute(attn_mma, cudaFuncAttributeMaxDynamicSharedMemorySize,
                         ATT_SMEM_BYTES);

    detect_mask_mode<<<1, 256>>>((const unsigned char*)mk);
    mask_to_bits<<<(Bc * NT * NKT / 32) / 256, 256>>>(mk, mb);

    const int nx = Bc * NT * Cdim;
    split_f32<<<nx / 1024, 256>>>(x,  xh,  nx);
    split_f32<<<nx / 1024, 256>>>(c,  ch_, nx);
    split_w4<<<1024, 256>>>(Wq, Wk, Wv, Wp, wqh, wkh, wvh, wph);

    // Q projection: 1-term
    gemm_mma<1><<<dim3(Cdim / 128, Bc * NT / 128), 256, GEMM_SMEM_BYTES>>>(
        xh, nullptr, nullptr, nullptr, wqh, nullptr,
        nullptr, qh, nullptr, nullptr, NT, 0, 0);
    // K + V fused projection: 1-term, n0 >= Cdim selects Wv/v-out
    gemm_mma<1><<<dim3(2 * Cdim / 128, Bc * NKT / 128), 256, GEMM_SMEM_BYTES>>>(
        xh, nullptr, ch_, nullptr, wkh, wvh,
        nullptr, kh, vh, nullptr, NKT, 1, 0);

    attn_mma<<<dim3(NT / 64, Hh, Bc), 256, ATT_SMEM_BYTES>>>(
        qh, kh, vh, mb, yh, yl);

    // output projection: 2-term (y hi+lo, Wp fp16)
    gemm_mma<2><<<dim3(Cdim / 128, Bc * NT / 128), 256, GEMM_SMEM_BYTES>>>(
        yh, yl, nullptr, nullptr, wph, nullptr,
        out, nullptr, nullptr, nullptr, NT, 0, 1);
}

// round 15
// speedup vs baseline: 7.2380x; 1.0321x over previous
#include <cuda_runtime.h>
#include <cuda_fp16.h>
#include <stdint.h>

#define Bc   8
#define Hh   8
#define NT   1024
#define NKT  2048
#define Cdim 512
#define Dh   64

// ---------------- scratch (no allocation allowed) ------------------------------
__device__ __half g_xh[(size_t)Bc * NT * Cdim];
__device__ __half g_ch[(size_t)Bc * NT * Cdim];
__device__ __half g_wqh[Cdim * Cdim];
__device__ __half g_wkh[Cdim * Cdim];
__device__ __half g_wvh[Cdim * Cdim];
__device__ __half g_wph[Cdim * Cdim];
__device__ __half g_qh[(size_t)Bc * Hh * NT  * Dh];
__device__ __half g_kh[(size_t)Bc * Hh * NKT * Dh];
__device__ __half g_vh[(size_t)Bc * Hh * NKT * Dh];
__device__ __half g_yh[(size_t)Bc * NT * Cdim], g_yl[(size_t)Bc * NT * Cdim];
__device__ uint32_t g_mbits[(size_t)Bc * NT * NKT / 32];   // bit-packed mask (2 MB)
__device__ int    g_maskmode;

// ---------------- helpers -------------------------------------------------------
__device__ __forceinline__ uint32_t smaddr(const void* p) {
    return (uint32_t)__cvta_generic_to_shared(p);
}
__device__ __forceinline__ void cpa16(uint32_t d, const void* s) {
    asm volatile("cp.async.ca.shared.global [%0], [%1], 16;" :: "r"(d), "l"(s));
}
__device__ __forceinline__ void cpcommit() { asm volatile("cp.async.commit_group;"); }
__device__ __forceinline__ void cpwait0()  { asm volatile("cp.async.wait_group 0;"); }

__device__ __forceinline__ void ldmx4(uint32_t a, uint32_t* r) {
    asm volatile("ldmatrix.sync.aligned.m8n8.x4.shared.b16 {%0,%1,%2,%3}, [%4];"
                 : "=r"(r[0]), "=r"(r[1]), "=r"(r[2]), "=r"(r[3]) : "r"(a));
}
__device__ __forceinline__ void ldmx2(uint32_t a, uint32_t* r) {
    asm volatile("ldmatrix.sync.aligned.m8n8.x2.shared.b16 {%0,%1}, [%2];"
                 : "=r"(r[0]), "=r"(r[1]) : "r"(a));
}
__device__ __forceinline__ void ldmx2t(uint32_t a, uint32_t* r) {
    asm volatile("ldmatrix.sync.aligned.m8n8.x2.trans.shared.b16 {%0,%1}, [%2];"
                 : "=r"(r[0]), "=r"(r[1]) : "r"(a));
}
__device__ __forceinline__ void mma16816(float* c, const uint32_t* a, const uint32_t* b) {
    asm volatile("mma.sync.aligned.m16n8k16.row.col.f32.f16.f16.f32 "
                 "{%0,%1,%2,%3},{%4,%5,%6,%7},{%8,%9},{%0,%1,%2,%3};"
                 : "+f"(c[0]), "+f"(c[1]), "+f"(c[2]), "+f"(c[3])
                 : "r"(a[0]), "r"(a[1]), "r"(a[2]), "r"(a[3]), "r"(b[0]), "r"(b[1]));
}
__device__ __forceinline__ float ex2f(float x) {
    float y; asm("ex2.approx.f32 %0, %1;" : "=f"(y) : "f"(x)); return y;
}
__device__ __forceinline__ uint32_t h2ex2(float a, float b) {
    __half2 hin = __floats2half2_rn(a, b);
    uint32_t in = *(uint32_t*)&hin, out;
    asm("ex2.approx.f16x2 %0, %1;" : "=r"(out) : "r"(in));
    return out;
}

// ---------------- prep kernels ---------------------------------------------------
// x and c in one launch: which = blockIdx.x >> 12
__global__ void split_xc(const float* __restrict__ s0, const float* __restrict__ s1,
                         __half* __restrict__ d0, __half* __restrict__ d1)
{
    int which = blockIdx.x >> 12;
    int i = ((blockIdx.x & 4095) * blockDim.x + threadIdx.x) * 4;
    const float* s = which ? s1 : s0;
    __half*      d = which ? d1 : d0;
    float4 v = *(const float4*)(s + i);
    *(__half2*)(d + i)     = __halves2half2(__float2half_rn(v.x), __float2half_rn(v.y));
    *(__half2*)(d + i + 2) = __halves2half2(__float2half_rn(v.z), __float2half_rn(v.w));
}

__global__ void split_w4(const float* __restrict__ s0, const float* __restrict__ s1,
                         const float* __restrict__ s2, const float* __restrict__ s3,
                         __half* __restrict__ d0, __half* __restrict__ d1,
                         __half* __restrict__ d2, __half* __restrict__ d3)
{
    int which = blockIdx.x >> 8;
    int i = ((blockIdx.x & 255) * blockDim.x + threadIdx.x) * 4;
    const float* s = which == 0 ? s0 : which == 1 ? s1 : which == 2 ? s2 : s3;
    __half*      d = which == 0 ? d0 : which == 1 ? d1 : which == 2 ? d2 : d3;
    float4 v = *(const float4*)(s + i);
    *(__half2*)(d + i)     = __halves2half2(__float2half_rn(v.x), __float2half_rn(v.y));
    *(__half2*)(d + i + 2) = __halves2half2(__float2half_rn(v.z), __float2half_rn(v.w));
}

__global__ void detect_mask_mode(const unsigned char* __restrict__ m) {
    bool hi = false, f3 = false;
    for (int i = threadIdx.x; i < 8192; i += blockDim.x) {
        unsigned char v = m[i];
        int p = i & 3;
        if (p == 3 && v == 0x3f) f3 = true;
        if (p != 0 && v != 0)    hi = true;
    }
    int a3 = __syncthreads_or(f3 ? 1 : 0);
    int ah = __syncthreads_or(hi ? 1 : 0);
    if (threadIdx.x == 0) g_maskmode = a3 ? 2 : (ah ? 0 : 1);
}

__global__ void mask_to_bits(const void* __restrict__ mp, uint32_t* __restrict__ o) {
    int mode = g_maskmode;
    size_t w = (size_t)blockIdx.x * blockDim.x + threadIdx.x;
    size_t base = w * 32;
    uint32_t bits = 0;
    if (mode == 0) {
        const uchar4* p = (const uchar4*)((const unsigned char*)mp + base);
#pragma unroll
        for (int q = 0; q < 8; q++) {
            uchar4 v = p[q];
            bits |= ((uint32_t)(v.x != 0) << (q * 4))
                  | ((uint32_t)(v.y != 0) << (q * 4 + 1))
                  | ((uint32_t)(v.z != 0) << (q * 4 + 2))
                  | ((uint32_t)(v.w != 0) << (q * 4 + 3));
        }
    } else if (mode == 1) {
        const int4* p = (const int4*)((const int*)mp + base);
#pragma unroll
        for (int q = 0; q < 8; q++) {
            int4 v = p[q];
            bits |= ((uint32_t)(v.x != 0) << (q * 4))
                  | ((uint32_t)(v.y != 0) << (q * 4 + 1))
                  | ((uint32_t)(v.z != 0) << (q * 4 + 2))
                  | ((uint32_t)(v.w != 0) << (q * 4 + 3));
        }
    } else {
        const float4* p = (const float4*)((const float*)mp + base);
#pragma unroll
        for (int q = 0; q < 8; q++) {
            float4 v = p[q];
            bits |= ((uint32_t)(v.x != 0.f) << (q * 4))
                  | ((uint32_t)(v.y != 0.f) << (q * 4 + 1))
                  | ((uint32_t)(v.z != 0.f) << (q * 4 + 2))
                  | ((uint32_t)(v.w != 0.f) << (q * 4 + 3));
        }
    }
    o[w] = bits;
}

// ---------------- GEMM (unchanged from R14) ---------------------------------------
#define GKT 32
#define GSH 40
#define GSZ (128 * GSH)
#define GEMM_SMEM_BYTES (2 * 4 * GSZ * 2)

template <int TERMS>
__global__ __launch_bounds__(256, 2) void gemm_mma(
    const __half* __restrict__ Ah0, const __half* __restrict__ Al0,
    const __half* __restrict__ Ah1, const __half* __restrict__ Al1,
    const __half* __restrict__ Wh,  const __half* __restrict__ Wh2,
    float* __restrict__ outF, __half* __restrict__ outH, __half* __restrict__ outH2,
    __half* __restrict__ outL,
    int MrowsPerB, int modeIn, int modeOut)
{
    extern __shared__ __half gs[];
    const int tid = threadIdx.x, lane = tid & 31, w = tid >> 5;
    const int wm = w >> 2, wn = w & 3;
    const int m0 = blockIdx.y * 128;
    int n0 = blockIdx.x * 128;
    const __half* Wsel = Wh;
    __half* outSel = outH;
    if (Wh2 != nullptr && n0 >= Cdim) { Wsel = Wh2; outSel = outH2; n0 -= Cdim; }
    const int lrow = tid >> 2;
    const int lch  = (tid & 3) * 8;

    const __half *arh[2], *arl[2], *brh[2];
#pragma unroll
    for (int p = 0; p < 2; p++) {
        int r = lrow + p * 64, gm = m0 + r;
        int bb = gm / MrowsPerB, mm = gm - bb * MrowsPerB;
        if (modeIn == 0 || mm < NT) {
            size_t off = ((size_t)bb * NT + mm) * Cdim;
            arh[p] = Ah0 + off;
            arl[p] = (TERMS >= 2) ? (Al0 + off) : nullptr;
        } else {
            size_t off = ((size_t)bb * NT + (mm - NT)) * Cdim;
            arh[p] = Ah1 + off;
            arl[p] = (TERMS >= 2) ? (Al1 + off) : nullptr;
        }
        brh[p] = Wsel + (size_t)(n0 + r) * Cdim;
    }

    float acc[4][4][4];
#pragma unroll
    for (int a = 0; a < 4; a++)
#pragma unroll
        for (int b2 = 0; b2 < 4; b2++)
#pragma unroll
            for (int q = 0; q < 4; q++) acc[a][b2][q] = 0.f;

    const int arlr = wm * 64 + (lane & 15);
    const int acs  = (lane >> 4) * 8;
    const int brlr = wn * 32 + (lane & 7);
    const int bcs  = ((lane >> 3) & 1) * 8;

    auto loadStage = [&](int st, int k0) {
        __half* b = gs + st * 4 * GSZ;
        const uint32_t d0 = (uint32_t)(lrow * GSH + lch);
#pragma unroll
        for (int p = 0; p < 2; p++) {
            uint32_t d = d0 + p * 64 * GSH;
            cpa16(smaddr(b + d),           arh[p] + k0 + lch);
            if (TERMS >= 2)
                cpa16(smaddr(b + GSZ + d), arl[p] + k0 + lch);
            cpa16(smaddr(b + 2 * GSZ + d), brh[p] + k0 + lch);
        }
    };

    loadStage(0, 0); cpcommit();
    const int NTILES = Cdim / GKT;
    for (int t = 0; t < NTILES; t++) {
        cpwait0(); __syncthreads();
        if (t + 1 < NTILES) { loadStage((t + 1) & 1, (t + 1) * GKT); cpcommit(); }

        __half* Ash = gs + (t & 1) * 4 * GSZ;
        __half* Asl = Ash + GSZ;
        __half* Bsh = Ash + 2 * GSZ;
#pragma unroll
        for (int ks = 0; ks < 2; ks++) {
            const int kcA = ks * 16 + acs, kcB = ks * 16 + bcs;
            uint32_t ah[4][4], al[4][4];
#pragma unroll
            for (int mt = 0; mt < 4; mt++) {
                ldmx4(smaddr(&Ash[(arlr + mt * 16) * GSH + kcA]), ah[mt]);
                if (TERMS >= 2)
                    ldmx4(smaddr(&Asl[(arlr + mt * 16) * GSH + kcA]), al[mt]);
            }
#pragma unroll
            for (int nt = 0; nt < 4; nt++) {
                uint32_t bh[2];
                ldmx2(smaddr(&Bsh[(brlr + nt * 8) * GSH + kcB]), bh);
#pragma unroll
                for (int mt = 0; mt < 4; mt++)
                    mma16816(acc[mt][nt], ah[mt], bh);
                if (TERMS >= 2)
#pragma unroll
                    for (int mt = 0; mt < 4; mt++)
                        mma16816(acc[mt][nt], al[mt], bh);
            }
        }
    }

    const int er = m0 + wm * 64 + (lane >> 2);
    const int ec = n0 + wn * 32 + 2 * (lane & 3);
#pragma unroll
    for (int mt = 0; mt < 4; mt++)
#pragma unroll
        for (int nt = 0; nt < 4; nt++) {
            int col = ec + nt * 8;
#pragma unroll
            for (int hf = 0; hf < 2; hf++) {
                int   row = er + mt * 16 + hf * 8;
                float v0 = acc[mt][nt][hf * 2], v1 = acc[mt][nt][hf * 2 + 1];
                if (modeOut == 0) {
                    int bb = row / MrowsPerB, mm = row - bb * MrowsPerB;
                    int hh = col >> 6, dd = col & 63;
                    size_t p = (((size_t)(bb * Hh + hh)) * MrowsPerB + mm) * Dh + dd;
                    *(__half2*)(outSel + p) =
                        __halves2half2(__float2half_rn(v0), __float2half_rn(v1));
                } else {
                    *(float2*)(outF + (size_t)row * Cdim + col) = make_float2(v0, v1);
                }
            }
        }
}

// ---------------- Flash attention v7: 4 warps, full row per warp -------------------
// 128 threads, warp = 16q x 128kv. Register-only softmax (quad shfl). One
// __syncthreads per tile. P is same-warp produce/consume -> no sync needed.
#define QSTR 72
#define KSTR 72
#define PSTR 136
#define QSZ  (64 * QSTR)
#define KSZ  (128 * KSTR)
#define PSZ  (64 * PSTR)
#define MBSZ (64 * 16)
#define ATT_SMEM_BYTES ((QSZ + 4 * KSZ + PSZ) * 2 + 2 * MBSZ)

__global__ __launch_bounds__(128, 2) void attn_mma(
    const __half* __restrict__ qhg, const __half* __restrict__ khg,
    const __half* __restrict__ vhg, const uint32_t* __restrict__ mbits,
    __half* __restrict__ yh, __half* __restrict__ yl)
{
    extern __shared__ __half sh[];
    __half* Qh = sh;
    __half* Kb = sh + QSZ;
    __half* Vb = sh + QSZ + 2 * KSZ;
    __half* Ph = sh + QSZ + 4 * KSZ;
    unsigned char* Mb = (unsigned char*)(sh + QSZ + 4 * KSZ + PSZ);

    const int tid = threadIdx.x, lane = tid & 31, w = tid >> 5;
    const int b = blockIdx.z, h = blockIdx.y, qt = blockIdx.x;

    const size_t kvo = ((size_t)(b * Hh + h)) * NKT * Dh;
    const unsigned char* mgb =
        (const unsigned char*)mbits + ((size_t)b * NT + (size_t)qt * 64) * (NKT / 8);

    auto loadStage = [&](int kt, int st) {
        __half* Khp = Kb + st * KSZ;
        __half* Vhp = Vb + st * KSZ;
#pragma unroll
        for (int i = 0; i < 8; i++) {
            int pos = tid + i * 128;
            int r = pos >> 3, cc = (pos & 7) * 8;
            size_t go = kvo + (size_t)(kt * 128 + r) * Dh + cc;
            uint32_t so = r * KSTR + cc;
            cpa16(smaddr(Khp + so), khg + go);
            cpa16(smaddr(Vhp + so), vhg + go);
        }
        if (tid < 64)
            cpa16(smaddr(Mb + st * MBSZ + tid * 16),
                  mgb + (size_t)tid * (NKT / 8) + kt * 16);
    };

    // prologue: Q + stage 0
    {
        const size_t qo = (((size_t)(b * Hh + h)) * NT + qt * 64) * Dh;
#pragma unroll
        for (int i = 0; i < 4; i++) {
            int pos = tid + i * 128;
            int r = pos >> 3, cc = (pos & 7) * 8;
            cpa16(smaddr(Qh + r * QSTR + cc), qhg + qo + r * Dh + cc);
        }
        loadStage(0, 0);
        cpcommit();
    }
    cpwait0(); __syncthreads();

    uint32_t qf[4][4];
    {
        const int rl = w * 16 + (lane & 15);
        const int cs = (lane >> 4) * 8;
#pragma unroll
        for (int kc = 0; kc < 4; kc++)
            ldmx4(smaddr(&Qh[rl * QSTR + kc * 16 + cs]), qf[kc]);
    }

    float oacc[8][4];
#pragma unroll
    for (int nt = 0; nt < 8; nt++)
#pragma unroll
        for (int q = 0; q < 4; q++) oacc[nt][q] = 0.f;
    float m_reg[2] = {-1e30f, -1e30f};
    float l_reg[2] = {0.f, 0.f};

    const int rg  = lane >> 2;
    const int mr0 = w * 16 + rg;
    const int mr1 = mr0 + 8;
    const int ql2 = (lane & 3) * 2;
    const float SCL = 0.125f * 1.44269504f;

    for (int kt = 0; kt < NKT / 128; kt++) {
        const int st = kt & 1;
        if (kt > 0) { cpwait0(); __syncthreads(); }
        if (kt + 1 < NKT / 128) { loadStage(kt + 1, st ^ 1); cpcommit(); }

        __half* Khp = Kb + st * KSZ;
        __half* Vhp = Vb + st * KSZ;
        const uint32_t* M32 = (const uint32_t*)(Mb + st * MBSZ);

        // --- S = Qh Kh^T : warp covers all 128 kv cols (16 n-tiles) ---
        float sacc[16][4];
#pragma unroll
        for (int nt = 0; nt < 16; nt++)
#pragma unroll
            for (int q = 0; q < 4; q++) sacc[nt][q] = 0.f;
        {
            const int brl = lane & 7;
            const int bcs = ((lane >> 3) & 1) * 8;
#pragma unroll
            for (int kc = 0; kc < 4; kc++) {
#pragma unroll
                for (int nt = 0; nt < 16; nt++) {
                    uint32_t bh[2];
                    ldmx2(smaddr(&Khp[(brl + nt * 8) * KSTR + kc * 16 + bcs]), bh);
                    mma16816(sacc[nt], qf[kc], bh);
                }
            }
        }

        // --- mask + scale, register row max (full row in quad) ---
        uint32_t mw0[4], mw1[4];
#pragma unroll
        for (int q = 0; q < 4; q++) {
            mw0[q] = M32[mr0 * 4 + q];
            mw1[q] = M32[mr1 * 4 + q];
        }
        float rm0 = -1e30f, rm1 = -1e30f;
#pragma unroll
        for (int nt = 0; nt < 16; nt++) {
            const int bit = (nt & 3) * 8 + ql2;
            uint32_t w0 = mw0[nt >> 2], w1 = mw1[nt >> 2];
            sacc[nt][0] = ((w0 >> bit) & 1)       ? -1e30f : sacc[nt][0] * SCL;
            sacc[nt][1] = ((w0 >> (bit + 1)) & 1) ? -1e30f : sacc[nt][1] * SCL;
            sacc[nt][2] = ((w1 >> bit) & 1)       ? -1e30f : sacc[nt][2] * SCL;
            sacc[nt][3] = ((w1 >> (bit + 1)) & 1) ? -1e30f : sacc[nt][3] * SCL;
            rm0 = fmaxf(rm0, fmaxf(sacc[nt][0], sacc[nt][1]));
            rm1 = fmaxf(rm1, fmaxf(sacc[nt][2], sacc[nt][3]));
        }
        rm0 = fmaxf(rm0, __shfl_xor_sync(0xffffffffu, rm0, 1));
        rm0 = fmaxf(rm0, __shfl_xor_sync(0xffffffffu, rm0, 2));
        rm1 = fmaxf(rm1, __shfl_xor_sync(0xffffffffu, rm1, 1));
        rm1 = fmaxf(rm1, __shfl_xor_sync(0xffffffffu, rm1, 2));
        float mn0 = fmaxf(m_reg[0], rm0);
        float mn1 = fmaxf(m_reg[1], rm1);
        float cf0 = ex2f(m_reg[0] - mn0);
        float cf1 = ex2f(m_reg[1] - mn1);

        // --- exp (fp16x2), P store, row sum (register-only) ---
        float rs0 = 0.f, rs1 = 0.f;
#pragma unroll
        for (int nt = 0; nt < 16; nt++) {
            const int colb = nt * 8 + ql2;
            uint32_t p0 = h2ex2(sacc[nt][0] - mn0, sacc[nt][1] - mn0);
            uint32_t p1 = h2ex2(sacc[nt][2] - mn1, sacc[nt][3] - mn1);
            *(uint32_t*)&Ph[mr0 * PSTR + colb] = p0;
            *(uint32_t*)&Ph[mr1 * PSTR + colb] = p1;
            float2 f0 = __half22float2(*(__half2*)&p0);
            float2 f1 = __half22float2(*(__half2*)&p1);
            rs0 += f0.x + f0.y;
            rs1 += f1.x + f1.y;
        }
        rs0 += __shfl_xor_sync(0xffffffffu, rs0, 1);
        rs0 += __shfl_xor_sync(0xffffffffu, rs0, 2);
        rs1 += __shfl_xor_sync(0xffffffffu, rs1, 1);
        rs1 += __shfl_xor_sync(0xffffffffu, rs1, 2);
        l_reg[0] = l_reg[0] * cf0 + rs0;
        l_reg[1] = l_reg[1] * cf1 + rs1;
        m_reg[0] = mn0; m_reg[1] = mn1;

        // rescale O
#pragma unroll
        for (int nt = 0; nt < 8; nt++) {
            oacc[nt][0] *= cf0; oacc[nt][1] *= cf0;
            oacc[nt][2] *= cf1; oacc[nt][3] *= cf1;
        }

        // --- O += P Vh (same-warp P, no sync) ---
        {
            const int prl = w * 16 + (lane & 15);
            const int pcs = (lane >> 4) * 8;
            const int vrl = lane & 15;
#pragma unroll
            for (int kc = 0; kc < 8; kc++) {
                uint32_t pfh[4];
                ldmx4(smaddr(&Ph[prl * PSTR + kc * 16 + pcs]), pfh);
#pragma unroll
                for (int nt = 0; nt < 8; nt++) {
                    uint32_t vh[2];
                    ldmx2t(smaddr(&Vhp[(kc * 16 + vrl) * KSTR + nt * 8]), vh);
                    mma16816(oacc[nt], pfh, vh);
                }
            }
        }
    }

    // --- epilogue: warp owns 16 rows x full 64 Dh ---
    {
        float i0 = (l_reg[0] > 0.f) ? 1.f / l_reg[0] : 0.f;
        float i1 = (l_reg[1] > 0.f) ? 1.f / l_reg[1] : 0.f;
        const int c0 = h * 64 + ql2;
        size_t o0 = ((size_t)b * NT + qt * 64 + mr0) * Cdim + c0;
        size_t o1 = ((size_t)b * NT + qt * 64 + mr1) * Cdim + c0;
#pragma unroll
        for (int nt = 0; nt < 8; nt++) {
            float a0 = oacc[nt][0] * i0, a1 = oacc[nt][1] * i0;
            float b0 = oacc[nt][2] * i1, b1 = oacc[nt][3] * i1;
            __half ha0 = __float2half_rn(a0), ha1 = __float2half_rn(a1);
            __half hb0 = __float2half_rn(b0), hb1 = __float2half_rn(b1);
            *(__half2*)(yh + o0 + nt * 8) = __halves2half2(ha0, ha1);
            *(__half2*)(yl + o0 + nt * 8) = __halves2half2(
                __float2half_rn(a0 - __half2float(ha0)),
                __float2half_rn(a1 - __half2float(ha1)));
            *(__half2*)(yh + o1 + nt * 8) = __halves2half2(hb0, hb1);
            *(__half2*)(yl + o1 + nt * 8) = __halves2half2(
                __float2half_rn(b0 - __half2float(hb0)),
                __float2half_rn(b1 - __half2float(hb1)));
        }
    }
}

// ---------------- launch ------------------------------------------------------------
extern "C" void kernel_launch(void* const* d_in, const int* in_sizes, int n_in,
                              void* d_out, int out_size)
{
    const float* x  = (const float*)d_in[0];
    const float* c  = (const float*)d_in[1];
    const void*  mk = d_in[2];
    const float* Wq = (const float*)d_in[3];
    const float* Wk = (const float*)d_in[4];
    const float* Wv = (const float*)d_in[5];
    const float* Wp = (const float*)d_in[6];
    float* out = (float*)d_out;

    __half *xh, *ch_, *wqh, *wkh, *wvh, *wph;
    __half *qh, *kh, *vh, *yh, *yl;
    uint32_t* mb;
    cudaGetSymbolAddress((void**)&xh,  g_xh);
    cudaGetSymbolAddress((void**)&ch_, g_ch);
    cudaGetSymbolAddress((void**)&wqh, g_wqh);
    cudaGetSymbolAddress((void**)&wkh, g_wkh);
    cudaGetSymbolAddress((void**)&wvh, g_wvh);
    cudaGetSymbolAddress((void**)&wph, g_wph);
    cudaGetSymbolAddress((void**)&qh,  g_qh);
    cudaGetSymbolAddress((void**)&kh,  g_kh);
    cudaGetSymbolAddress((void**)&vh,  g_vh);
    cudaGetSymbolAddress((void**)&yh,  g_yh);  cudaGetSymbolAddress((void**)&yl,  g_yl);
    cudaGetSymbolAddress((void**)&mb,  g_mbits);

    cudaFuncSetAttribute(gemm_mma<2>, cudaFuncAttributeMaxDynamicSharedMemorySize,
                         GEMM_SMEM_BYTES);
    cudaFuncSetAttribute(gemm_mma<1>, cudaFuncAttributeMaxDynamicSharedMemorySize,
                         GEMM_SMEM_BYTES);
    cudaFuncSetAttribute(attn_mma, cudaFuncAttributeMaxDynamicSharedMemorySize,
                         ATT_SMEM_BYTES);

    detect_mask_mode<<<1, 256>>>((const unsigned char*)mk);
    mask_to_bits<<<(Bc * NT * NKT / 32) / 256, 256>>>(mk, mb);

    split_xc<<<8192, 256>>>(x, c, xh, ch_);
    split_w4<<<1024, 256>>>(Wq, Wk, Wv, Wp, wqh, wkh, wvh, wph);

    // Q projection: 1-term
    gemm_mma<1><<<dim3(Cdim / 128, Bc * NT / 128), 256, GEMM_SMEM_BYTES>>>(
        xh, nullptr, nullptr, nullptr, wqh, nullptr,
        nullptr, qh, nullptr, nullptr, NT, 0, 0);
    // K + V fused projection: 1-term
    gemm_mma<1><<<dim3(2 * Cdim / 128, Bc * NKT / 128), 256, GEMM_SMEM_BYTES>>>(
        xh, nullptr, ch_, nullptr, wkh, wvh,
        nullptr, kh, vh, nullptr, NKT, 1, 0);

    attn_mma<<<dim3(NT / 64, Hh, Bc), 128, ATT_SMEM_BYTES>>>(
        qh, kh, vh, mb, yh, yl);

    // output projection: 2-term (y hi+lo, Wp fp16)
    gemm_mma<2><<<dim3(Cdim / 128, Bc * NT / 128), 256, GEMM_SMEM_BYTES>>>(
        yh, yl, nullptr, nullptr, wph, nullptr,
        out, nullptr, nullptr, nullptr, NT, 0, 1);
}

// round 16
// speedup vs baseline: 7.4179x; 1.0249x over previous
#include <cuda_runtime.h>
#include <cuda_fp16.h>
#include <stdint.h>

#define Bc   8
#define Hh   8
#define NT   1024
#define NKT  2048
#define Cdim 512
#define Dh   64

// ---------------- scratch (no allocation allowed) ------------------------------
__device__ __half g_xh[(size_t)Bc * NT * Cdim];
__device__ __half g_ch[(size_t)Bc * NT * Cdim];
__device__ __half g_wqh[Cdim * Cdim];
__device__ __half g_wkh[Cdim * Cdim];
__device__ __half g_wvh[Cdim * Cdim];
__device__ __half g_wph[Cdim * Cdim];
__device__ __half g_qh[(size_t)Bc * Hh * NT  * Dh];
__device__ __half g_kh[(size_t)Bc * Hh * NKT * Dh];
__device__ __half g_vh[(size_t)Bc * Hh * NKT * Dh];
__device__ __half g_yh[(size_t)Bc * NT * Cdim], g_yl[(size_t)Bc * NT * Cdim];
__device__ uint32_t g_mbits[(size_t)Bc * NT * NKT / 32];
__device__ int    g_maskmode;

// ---------------- helpers -------------------------------------------------------
__device__ __forceinline__ uint32_t smaddr(const void* p) {
    return (uint32_t)__cvta_generic_to_shared(p);
}
__device__ __forceinline__ void cpa16(uint32_t d, const void* s) {
    asm volatile("cp.async.ca.shared.global [%0], [%1], 16;" :: "r"(d), "l"(s));
}
__device__ __forceinline__ void cpcommit() { asm volatile("cp.async.commit_group;"); }
__device__ __forceinline__ void cpwait0()  { asm volatile("cp.async.wait_group 0;"); }

__device__ __forceinline__ void ldmx4(uint32_t a, uint32_t* r) {
    asm volatile("ldmatrix.sync.aligned.m8n8.x4.shared.b16 {%0,%1,%2,%3}, [%4];"
                 : "=r"(r[0]), "=r"(r[1]), "=r"(r[2]), "=r"(r[3]) : "r"(a));
}
__device__ __forceinline__ void ldmx4t(uint32_t a, uint32_t* r) {
    asm volatile("ldmatrix.sync.aligned.m8n8.x4.trans.shared.b16 {%0,%1,%2,%3}, [%4];"
                 : "=r"(r[0]), "=r"(r[1]), "=r"(r[2]), "=r"(r[3]) : "r"(a));
}
__device__ __forceinline__ void mma16816(float* c, const uint32_t* a, const uint32_t* b) {
    asm volatile("mma.sync.aligned.m16n8k16.row.col.f32.f16.f16.f32 "
                 "{%0,%1,%2,%3},{%4,%5,%6,%7},{%8,%9},{%0,%1,%2,%3};"
                 : "+f"(c[0]), "+f"(c[1]), "+f"(c[2]), "+f"(c[3])
                 : "r"(a[0]), "r"(a[1]), "r"(a[2]), "r"(a[3]), "r"(b[0]), "r"(b[1]));
}
__device__ __forceinline__ float ex2f(float x) {
    float y; asm("ex2.approx.f32 %0, %1;" : "=f"(y) : "f"(x)); return y;
}
__device__ __forceinline__ uint32_t h2ex2(float a, float b) {
    __half2 hin = __floats2half2_rn(a, b);
    uint32_t in = *(uint32_t*)&hin, out;
    asm("ex2.approx.f16x2 %0, %1;" : "=r"(out) : "r"(in));
    return out;
}

// ---------------- prep kernels ---------------------------------------------------
__global__ void split_xc(const float* __restrict__ s0, const float* __restrict__ s1,
                         __half* __restrict__ d0, __half* __restrict__ d1)
{
    int which = blockIdx.x >> 12;
    int i = ((blockIdx.x & 4095) * blockDim.x + threadIdx.x) * 4;
    const float* s = which ? s1 : s0;
    __half*      d = which ? d1 : d0;
    float4 v = *(const float4*)(s + i);
    *(__half2*)(d + i)     = __halves2half2(__float2half_rn(v.x), __float2half_rn(v.y));
    *(__half2*)(d + i + 2) = __halves2half2(__float2half_rn(v.z), __float2half_rn(v.w));
}

__global__ void split_w4(const float* __restrict__ s0, const float* __restrict__ s1,
                         const float* __restrict__ s2, const float* __restrict__ s3,
                         __half* __restrict__ d0, __half* __restrict__ d1,
                         __half* __restrict__ d2, __half* __restrict__ d3)
{
    int which = blockIdx.x >> 8;
    int i = ((blockIdx.x & 255) * blockDim.x + threadIdx.x) * 4;
    const float* s = which == 0 ? s0 : which == 1 ? s1 : which == 2 ? s2 : s3;
    __half*      d = which == 0 ? d0 : which == 1 ? d1 : which == 2 ? d2 : d3;
    float4 v = *(const float4*)(s + i);
    *(__half2*)(d + i)     = __halves2half2(__float2half_rn(v.x), __float2half_rn(v.y));
    *(__half2*)(d + i + 2) = __halves2half2(__float2half_rn(v.z), __float2half_rn(v.w));
}

__global__ void detect_mask_mode(const unsigned char* __restrict__ m) {
    bool hi = false, f3 = false;
    for (int i = threadIdx.x; i < 8192; i += blockDim.x) {
        unsigned char v = m[i];
        int p = i & 3;
        if (p == 3 && v == 0x3f) f3 = true;
        if (p != 0 && v != 0)    hi = true;
    }
    int a3 = __syncthreads_or(f3 ? 1 : 0);
    int ah = __syncthreads_or(hi ? 1 : 0);
    if (threadIdx.x == 0) g_maskmode = a3 ? 2 : (ah ? 0 : 1);
}

__global__ void mask_to_bits(const void* __restrict__ mp, uint32_t* __restrict__ o) {
    int mode = g_maskmode;
    size_t w = (size_t)blockIdx.x * blockDim.x + threadIdx.x;
    size_t base = w * 32;
    uint32_t bits = 0;
    if (mode == 0) {
        const uchar4* p = (const uchar4*)((const unsigned char*)mp + base);
#pragma unroll
        for (int q = 0; q < 8; q++) {
            uchar4 v = p[q];
            bits |= ((uint32_t)(v.x != 0) << (q * 4))
                  | ((uint32_t)(v.y != 0) << (q * 4 + 1))
                  | ((uint32_t)(v.z != 0) << (q * 4 + 2))
                  | ((uint32_t)(v.w != 0) << (q * 4 + 3));
        }
    } else if (mode == 1) {
        const int4* p = (const int4*)((const int*)mp + base);
#pragma unroll
        for (int q = 0; q < 8; q++) {
            int4 v = p[q];
            bits |= ((uint32_t)(v.x != 0) << (q * 4))
                  | ((uint32_t)(v.y != 0) << (q * 4 + 1))
                  | ((uint32_t)(v.z != 0) << (q * 4 + 2))
                  | ((uint32_t)(v.w != 0) << (q * 4 + 3));
        }
    } else {
        const float4* p = (const float4*)((const float*)mp + base);
#pragma unroll
        for (int q = 0; q < 8; q++) {
            float4 v = p[q];
            bits |= ((uint32_t)(v.x != 0.f) << (q * 4))
                  | ((uint32_t)(v.y != 0.f) << (q * 4 + 1))
                  | ((uint32_t)(v.z != 0.f) << (q * 4 + 2))
                  | ((uint32_t)(v.w != 0.f) << (q * 4 + 3));
        }
    }
    o[w] = bits;
}

// ---------------- GEMM: Y = A @ W^T ------------------------------------------------
// Segments on blockIdx.x: [0,4) -> Wh/outH, [4,8) -> Wh2/outH2, [8,12) -> Wh3/outH3
// (Q segment: MrowsPerB=NT, modeIn=0, early-exit when m-block out of range).
#define GKT 32
#define GSH 40
#define GSZ (128 * GSH)
#define GEMM_SMEM_BYTES (2 * 4 * GSZ * 2)

template <int TERMS>
__global__ __launch_bounds__(256, 2) void gemm_mma(
    const __half* __restrict__ Ah0, const __half* __restrict__ Al0,
    const __half* __restrict__ Ah1,
    const __half* __restrict__ Wh,  const __half* __restrict__ Wh2,
    const __half* __restrict__ Wh3,
    float* __restrict__ outF, __half* __restrict__ outH, __half* __restrict__ outH2,
    __half* __restrict__ outH3,
    int MrowsPerB, int modeIn, int modeOut)
{
    extern __shared__ __half gs[];
    const int tid = threadIdx.x, lane = tid & 31, w = tid >> 5;
    const int wm = w >> 2, wn = w & 3;
    const int m0 = blockIdx.y * 128;
    const int seg = blockIdx.x >> 2;
    const int n0 = (blockIdx.x & 3) * 128;
    const __half* Wsel = seg == 0 ? Wh : seg == 1 ? Wh2 : Wh3;
    __half* outSel = seg == 0 ? outH : seg == 1 ? outH2 : outH3;
    if (seg == 2) {                       // Q segment
        MrowsPerB = NT; modeIn = 0;
        if (m0 >= Bc * NT) return;
    }
    const int lrow = tid >> 2;
    const int lch  = (tid & 3) * 8;

    const __half *arh[2], *arl[2], *brh[2];
#pragma unroll
    for (int p = 0; p < 2; p++) {
        int r = lrow + p * 64, gm = m0 + r;
        int bb = gm / MrowsPerB, mm = gm - bb * MrowsPerB;
        if (modeIn == 0 || mm < NT) {
            size_t off = ((size_t)bb * NT + mm) * Cdim;
            arh[p] = Ah0 + off;
            arl[p] = (TERMS >= 2) ? (Al0 + off) : nullptr;
        } else {
            size_t off = ((size_t)bb * NT + (mm - NT)) * Cdim;
            arh[p] = Ah1 + off;
            arl[p] = nullptr;
        }
        brh[p] = Wsel + (size_t)(n0 + r) * Cdim;
    }

    float acc[4][4][4];
#pragma unroll
    for (int a = 0; a < 4; a++)
#pragma unroll
        for (int b2 = 0; b2 < 4; b2++)
#pragma unroll
            for (int q = 0; q < 4; q++) acc[a][b2][q] = 0.f;

    const int arlr = wm * 64 + (lane & 15);
    const int acs  = (lane >> 4) * 8;
    const int bq    = wn * 32 + (lane & 7);         // B base row
    const int bksel = ((lane >> 3) & 1) * 8;        // k-half select
    const int bnsel = ((lane >> 4) & 1) * 8;        // n-tile select (x4)

    auto loadStage = [&](int st, int k0) {
        __half* b = gs + st * 4 * GSZ;
        const uint32_t d0 = (uint32_t)(lrow * GSH + lch);
#pragma unroll
        for (int p = 0; p < 2; p++) {
            uint32_t d = d0 + p * 64 * GSH;
            cpa16(smaddr(b + d),           arh[p] + k0 + lch);
            if (TERMS >= 2)
                cpa16(smaddr(b + GSZ + d), arl[p] + k0 + lch);
            cpa16(smaddr(b + 2 * GSZ + d), brh[p] + k0 + lch);
        }
    };

    loadStage(0, 0); cpcommit();
    const int NTILES = Cdim / GKT;
    for (int t = 0; t < NTILES; t++) {
        cpwait0(); __syncthreads();
        if (t + 1 < NTILES) { loadStage((t + 1) & 1, (t + 1) * GKT); cpcommit(); }

        __half* Ash = gs + (t & 1) * 4 * GSZ;
        __half* Asl = Ash + GSZ;
        __half* Bsh = Ash + 2 * GSZ;
#pragma unroll
        for (int ks = 0; ks < 2; ks++) {
            const int kcA = ks * 16 + acs, kcB = ks * 16 + bksel;
            uint32_t ah[4][4], al[4][4];
#pragma unroll
            for (int mt = 0; mt < 4; mt++) {
                ldmx4(smaddr(&Ash[(arlr + mt * 16) * GSH + kcA]), ah[mt]);
                if (TERMS >= 2)
                    ldmx4(smaddr(&Asl[(arlr + mt * 16) * GSH + kcA]), al[mt]);
            }
#pragma unroll
            for (int nt = 0; nt < 4; nt += 2) {
                uint32_t bh[4];
                ldmx4(smaddr(&Bsh[(bq + nt * 8 + bnsel) * GSH + kcB]), bh);
#pragma unroll
                for (int mt = 0; mt < 4; mt++)
                    mma16816(acc[mt][nt], ah[mt], bh);
#pragma unroll
                for (int mt = 0; mt < 4; mt++)
                    mma16816(acc[mt][nt + 1], ah[mt], bh + 2);
                if (TERMS >= 2) {
#pragma unroll
                    for (int mt = 0; mt < 4; mt++)
                        mma16816(acc[mt][nt], al[mt], bh);
#pragma unroll
                    for (int mt = 0; mt < 4; mt++)
                        mma16816(acc[mt][nt + 1], al[mt], bh + 2);
                }
            }
        }
    }

    const int er = m0 + wm * 64 + (lane >> 2);
    const int ec = n0 + wn * 32 + 2 * (lane & 3);
#pragma unroll
    for (int mt = 0; mt < 4; mt++)
#pragma unroll
        for (int nt = 0; nt < 4; nt++) {
            int col = ec + nt * 8;
#pragma unroll
            for (int hf = 0; hf < 2; hf++) {
                int   row = er + mt * 16 + hf * 8;
                float v0 = acc[mt][nt][hf * 2], v1 = acc[mt][nt][hf * 2 + 1];
                if (modeOut == 0) {
                    int bb = row / MrowsPerB, mm = row - bb * MrowsPerB;
                    int hh = col >> 6, dd = col & 63;
                    size_t p = (((size_t)(bb * Hh + hh)) * MrowsPerB + mm) * Dh + dd;
                    *(__half2*)(outSel + p) =
                        __halves2half2(__float2half_rn(v0), __float2half_rn(v1));
                } else {
                    *(float2*)(outF + (size_t)row * Cdim + col) = make_float2(v0, v1);
                }
            }
        }
}

// ---------------- Flash attention v8: ldmatrix.x4 fragment loads --------------------
#define QSTR 72
#define KSTR 72
#define PSTR 136
#define QSZ  (64 * QSTR)
#define KSZ  (128 * KSTR)
#define PSZ  (64 * PSTR)
#define MBSZ (64 * 16)
#define ATT_SMEM_BYTES ((QSZ + 4 * KSZ + PSZ) * 2 + 2 * MBSZ)

__global__ __launch_bounds__(128, 2) void attn_mma(
    const __half* __restrict__ qhg, const __half* __restrict__ khg,
    const __half* __restrict__ vhg, const uint32_t* __restrict__ mbits,
    __half* __restrict__ yh, __half* __restrict__ yl)
{
    extern __shared__ __half sh[];
    __half* Qh = sh;
    __half* Kb = sh + QSZ;
    __half* Vb = sh + QSZ + 2 * KSZ;
    __half* Ph = sh + QSZ + 4 * KSZ;
    unsigned char* Mb = (unsigned char*)(sh + QSZ + 4 * KSZ + PSZ);

    const int tid = threadIdx.x, lane = tid & 31, w = tid >> 5;
    const int b = blockIdx.z, h = blockIdx.y, qt = blockIdx.x;

    const size_t kvo = ((size_t)(b * Hh + h)) * NKT * Dh;
    const unsigned char* mgb =
        (const unsigned char*)mbits + ((size_t)b * NT + (size_t)qt * 64) * (NKT / 8);

    auto loadStage = [&](int kt, int st) {
        __half* Khp = Kb + st * KSZ;
        __half* Vhp = Vb + st * KSZ;
#pragma unroll
        for (int i = 0; i < 8; i++) {
            int pos = tid + i * 128;
            int r = pos >> 3, cc = (pos & 7) * 8;
            size_t go = kvo + (size_t)(kt * 128 + r) * Dh + cc;
            uint32_t so = r * KSTR + cc;
            cpa16(smaddr(Khp + so), khg + go);
            cpa16(smaddr(Vhp + so), vhg + go);
        }
        if (tid < 64)
            cpa16(smaddr(Mb + st * MBSZ + tid * 16),
                  mgb + (size_t)tid * (NKT / 8) + kt * 16);
    };

    {
        const size_t qo = (((size_t)(b * Hh + h)) * NT + qt * 64) * Dh;
#pragma unroll
        for (int i = 0; i < 4; i++) {
            int pos = tid + i * 128;
            int r = pos >> 3, cc = (pos & 7) * 8;
            cpa16(smaddr(Qh + r * QSTR + cc), qhg + qo + r * Dh + cc);
        }
        loadStage(0, 0);
        cpcommit();
    }
    cpwait0(); __syncthreads();

    uint32_t qf[4][4];
    {
        const int rl = w * 16 + (lane & 15);
        const int cs = (lane >> 4) * 8;
#pragma unroll
        for (int kc = 0; kc < 4; kc++)
            ldmx4(smaddr(&Qh[rl * QSTR + kc * 16 + cs]), qf[kc]);
    }

    float oacc[8][4];
#pragma unroll
    for (int nt = 0; nt < 8; nt++)
#pragma unroll
        for (int q = 0; q < 4; q++) oacc[nt][q] = 0.f;
    float m_reg[2] = {-1e30f, -1e30f};
    float l_reg[2] = {0.f, 0.f};

    const int rg  = lane >> 2;
    const int mr0 = w * 16 + rg;
    const int mr1 = mr0 + 8;
    const int ql2 = (lane & 3) * 2;
    const float SCL = 0.125f * 1.44269504f;

    // x4 fragment-load lane mappings
    const int kq    = lane & 7;                 // K row base
    const int kksel = ((lane >> 3) & 1) * 8;    // K k-half select
    const int knsel = ((lane >> 4) & 1) * 8;    // K n-tile select
    const int vr    = lane & 15;                // V row (trans)
    const int vnsel = ((lane >> 4) & 1) * 8;    // V n-tile select

    for (int kt = 0; kt < NKT / 128; kt++) {
        const int st = kt & 1;
        if (kt > 0) { cpwait0(); __syncthreads(); }
        if (kt + 1 < NKT / 128) { loadStage(kt + 1, st ^ 1); cpcommit(); }

        __half* Khp = Kb + st * KSZ;
        __half* Vhp = Vb + st * KSZ;
        const uint32_t* M32 = (const uint32_t*)(Mb + st * MBSZ);

        // --- S = Qh Kh^T : ldmx4 serves 2 n-tiles per load ---
        float sacc[16][4];
#pragma unroll
        for (int nt = 0; nt < 16; nt++)
#pragma unroll
            for (int q = 0; q < 4; q++) sacc[nt][q] = 0.f;
#pragma unroll
        for (int kc = 0; kc < 4; kc++) {
#pragma unroll
            for (int nt = 0; nt < 16; nt += 2) {
                uint32_t bh[4];
                ldmx4(smaddr(&Khp[(kq + nt * 8 + knsel) * KSTR + kc * 16 + kksel]), bh);
                mma16816(sacc[nt],     qf[kc], bh);
                mma16816(sacc[nt + 1], qf[kc], bh + 2);
            }
        }

        // --- mask + scale, register row max ---
        uint32_t mw0[4], mw1[4];
#pragma unroll
        for (int q = 0; q < 4; q++) {
            mw0[q] = M32[mr0 * 4 + q];
            mw1[q] = M32[mr1 * 4 + q];
        }
        float rm0 = -1e30f, rm1 = -1e30f;
#pragma unroll
        for (int nt = 0; nt < 16; nt++) {
            const int bit = (nt & 3) * 8 + ql2;
            uint32_t w0 = mw0[nt >> 2], w1 = mw1[nt >> 2];
            sacc[nt][0] = ((w0 >> bit) & 1)       ? -1e30f : sacc[nt][0] * SCL;
            sacc[nt][1] = ((w0 >> (bit + 1)) & 1) ? -1e30f : sacc[nt][1] * SCL;
            sacc[nt][2] = ((w1 >> bit) & 1)       ? -1e30f : sacc[nt][2] * SCL;
            sacc[nt][3] = ((w1 >> (bit + 1)) & 1) ? -1e30f : sacc[nt][3] * SCL;
            rm0 = fmaxf(rm0, fmaxf(sacc[nt][0], sacc[nt][1]));
            rm1 = fmaxf(rm1, fmaxf(sacc[nt][2], sacc[nt][3]));
        }
        rm0 = fmaxf(rm0, __shfl_xor_sync(0xffffffffu, rm0, 1));
        rm0 = fmaxf(rm0, __shfl_xor_sync(0xffffffffu, rm0, 2));
        rm1 = fmaxf(rm1, __shfl_xor_sync(0xffffffffu, rm1, 1));
        rm1 = fmaxf(rm1, __shfl_xor_sync(0xffffffffu, rm1, 2));
        float mn0 = fmaxf(m_reg[0], rm0);
        float mn1 = fmaxf(m_reg[1], rm1);
        float cf0 = ex2f(m_reg[0] - mn0);
        float cf1 = ex2f(m_reg[1] - mn1);

        // --- exp (fp16x2), P store, row sum ---
        float rs0 = 0.f, rs1 = 0.f;
#pragma unroll
        for (int nt = 0; nt < 16; nt++) {
            const int colb = nt * 8 + ql2;
            uint32_t p0 = h2ex2(sacc[nt][0] - mn0, sacc[nt][1] - mn0);
            uint32_t p1 = h2ex2(sacc[nt][2] - mn1, sacc[nt][3] - mn1);
            *(uint32_t*)&Ph[mr0 * PSTR + colb] = p0;
            *(uint32_t*)&Ph[mr1 * PSTR + colb] = p1;
            float2 f0 = __half22float2(*(__half2*)&p0);
            float2 f1 = __half22float2(*(__half2*)&p1);
            rs0 += f0.x + f0.y;
            rs1 += f1.x + f1.y;
        }
        rs0 += __shfl_xor_sync(0xffffffffu, rs0, 1);
        rs0 += __shfl_xor_sync(0xffffffffu, rs0, 2);
        rs1 += __shfl_xor_sync(0xffffffffu, rs1, 1);
        rs1 += __shfl_xor_sync(0xffffffffu, rs1, 2);
        l_reg[0] = l_reg[0] * cf0 + rs0;
        l_reg[1] = l_reg[1] * cf1 + rs1;
        m_reg[0] = mn0; m_reg[1] = mn1;

#pragma unroll
        for (int nt = 0; nt < 8; nt++) {
            oacc[nt][0] *= cf0; oacc[nt][1] *= cf0;
            oacc[nt][2] *= cf1; oacc[nt][3] *= cf1;
        }

        // --- O += P Vh : ldmx4t serves 2 n-tiles per load ---
        {
            const int prl = w * 16 + (lane & 15);
            const int pcs = (lane >> 4) * 8;
#pragma unroll
            for (int kc = 0; kc < 8; kc++) {
                uint32_t pfh[4];
                ldmx4(smaddr(&Ph[prl * PSTR + kc * 16 + pcs]), pfh);
#pragma unroll
                for (int nt = 0; nt < 8; nt += 2) {
                    uint32_t vh[4];
                    ldmx4t(smaddr(&Vhp[(kc * 16 + vr) * KSTR + nt * 8 + vnsel]), vh);
                    mma16816(oacc[nt],     pfh, vh);
                    mma16816(oacc[nt + 1], pfh, vh + 2);
                }
            }
        }
    }

    // --- epilogue ---
    {
        float i0 = (l_reg[0] > 0.f) ? 1.f / l_reg[0] : 0.f;
        float i1 = (l_reg[1] > 0.f) ? 1.f / l_reg[1] : 0.f;
        const int c0 = h * 64 + ql2;
        size_t o0 = ((size_t)b * NT + qt * 64 + mr0) * Cdim + c0;
        size_t o1 = ((size_t)b * NT + qt * 64 + mr1) * Cdim + c0;
#pragma unroll
        for (int nt = 0; nt < 8; nt++) {
            float a0 = oacc[nt][0] * i0, a1 = oacc[nt][1] * i0;
            float b0 = oacc[nt][2] * i1, b1 = oacc[nt][3] * i1;
            __half ha0 = __float2half_rn(a0), ha1 = __float2half_rn(a1);
            __half hb0 = __float2half_rn(b0), hb1 = __float2half_rn(b1);
            *(__half2*)(yh + o0 + nt * 8) = __halves2half2(ha0, ha1);
            *(__half2*)(yl + o0 + nt * 8) = __halves2half2(
                __float2half_rn(a0 - __half2float(ha0)),
                __float2half_rn(a1 - __half2float(ha1)));
            *(__half2*)(yh + o1 + nt * 8) = __halves2half2(hb0, hb1);
            *(__half2*)(yl + o1 + nt * 8) = __halves2half2(
                __float2half_rn(b0 - __half2float(hb0)),
                __float2half_rn(b1 - __half2float(hb1)));
        }
    }
}

// ---------------- launch ------------------------------------------------------------
extern "C" void kernel_launch(void* const* d_in, const int* in_sizes, int n_in,
                              void* d_out, int out_size)
{
    const float* x  = (const float*)d_in[0];
    const float* c  = (const float*)d_in[1];
    const void*  mk = d_in[2];
    const float* Wq = (const float*)d_in[3];
    const float* Wk = (const float*)d_in[4];
    const float* Wv = (const float*)d_in[5];
    const float* Wp = (const float*)d_in[6];
    float* out = (float*)d_out;

    __half *xh, *ch_, *wqh, *wkh, *wvh, *wph;
    __half *qh, *kh, *vh, *yh, *yl;
    uint32_t* mb;
    cudaGetSymbolAddress((void**)&xh,  g_xh);
    cudaGetSymbolAddress((void**)&ch_, g_ch);
    cudaGetSymbolAddress((void**)&wqh, g_wqh);
    cudaGetSymbolAddress((void**)&wkh, g_wkh);
    cudaGetSymbolAddress((void**)&wvh, g_wvh);
    cudaGetSymbolAddress((void**)&wph, g_wph);
    cudaGetSymbolAddress((void**)&qh,  g_qh);
    cudaGetSymbolAddress((void**)&kh,  g_kh);
    cudaGetSymbolAddress((void**)&vh,  g_vh);
    cudaGetSymbolAddress((void**)&yh,  g_yh);  cudaGetSymbolAddress((void**)&yl,  g_yl);
    cudaGetSymbolAddress((void**)&mb,  g_mbits);

    cudaFuncSetAttribute(gemm_mma<2>, cudaFuncAttributeMaxDynamicSharedMemorySize,
                         GEMM_SMEM_BYTES);
    cudaFuncSetAttribute(gemm_mma<1>, cudaFuncAttributeMaxDynamicSharedMemorySize,
                         GEMM_SMEM_BYTES);
    cudaFuncSetAttribute(attn_mma, cudaFuncAttributeMaxDynamicSharedMemorySize,
                         ATT_SMEM_BYTES);

    detect_mask_mode<<<1, 256>>>((const unsigned char*)mk);
    mask_to_bits<<<(Bc * NT * NKT / 32) / 256, 256>>>(mk, mb);

    split_xc<<<8192, 256>>>(x, c, xh, ch_);
    split_w4<<<1024, 256>>>(Wq, Wk, Wv, Wp, wqh, wkh, wvh, wph);

    // Fused K + V + Q projection: segments on blockIdx.x (K, V, Q)
    gemm_mma<1><<<dim3(3 * Cdim / 128, Bc * NKT / 128), 256, GEMM_SMEM_BYTES>>>(
        xh, nullptr, ch_, wkh, wvh, wqh,
        nullptr, kh, vh, qh, NKT, 1, 0);

    attn_mma<<<dim3(NT / 64, Hh, Bc), 128, ATT_SMEM_BYTES>>>(
        qh, kh, vh, mb, yh, yl);

    // output projection: 2-term (y hi+lo, Wp fp16)
    gemm_mma<2><<<dim3(Cdim / 128, Bc * NT / 128), 256, GEMM_SMEM_BYTES>>>(
        yh, yl, nullptr, wph, nullptr, nullptr,
        out, nullptr, nullptr, nullptr, NT, 0, 1);
}

// round 17
// speedup vs baseline: 7.7843x; 1.0494x over previous
#include <cuda_runtime.h>
#include <cuda_fp16.h>
#include <stdint.h>

#define Bc   8
#define Hh   8
#define NT   1024
#define NKT  2048
#define Cdim 512
#define Dh   64

// ---------------- scratch (no allocation allowed) ------------------------------
__device__ __half g_xh[(size_t)Bc * NT * Cdim];
__device__ __half g_ch[(size_t)Bc * NT * Cdim];
__device__ __half g_wqh[Cdim * Cdim];
__device__ __half g_wkh[Cdim * Cdim];
__device__ __half g_wvh[Cdim * Cdim];
__device__ __half g_wph[Cdim * Cdim];
__device__ __half g_qh[(size_t)Bc * Hh * NT  * Dh];
__device__ __half g_kh[(size_t)Bc * Hh * NKT * Dh];
__device__ __half g_vh[(size_t)Bc * Hh * NKT * Dh];
__device__ __half g_yh[(size_t)Bc * NT * Cdim], g_yl[(size_t)Bc * NT * Cdim];
__device__ uint32_t g_mbits[(size_t)Bc * NT * NKT / 32];

// ---------------- helpers -------------------------------------------------------
__device__ __forceinline__ uint32_t smaddr(const void* p) {
    return (uint32_t)__cvta_generic_to_shared(p);
}
__device__ __forceinline__ void cpa16(uint32_t d, const void* s) {
    asm volatile("cp.async.ca.shared.global [%0], [%1], 16;" :: "r"(d), "l"(s));
}
__device__ __forceinline__ void cpcommit() { asm volatile("cp.async.commit_group;"); }
__device__ __forceinline__ void cpwait0()  { asm volatile("cp.async.wait_group 0;"); }

__device__ __forceinline__ void ldmx4(uint32_t a, uint32_t* r) {
    asm volatile("ldmatrix.sync.aligned.m8n8.x4.shared.b16 {%0,%1,%2,%3}, [%4];"
                 : "=r"(r[0]), "=r"(r[1]), "=r"(r[2]), "=r"(r[3]) : "r"(a));
}
__device__ __forceinline__ void ldmx4t(uint32_t a, uint32_t* r) {
    asm volatile("ldmatrix.sync.aligned.m8n8.x4.trans.shared.b16 {%0,%1,%2,%3}, [%4];"
                 : "=r"(r[0]), "=r"(r[1]), "=r"(r[2]), "=r"(r[3]) : "r"(a));
}
__device__ __forceinline__ void mma16816(float* c, const uint32_t* a, const uint32_t* b) {
    asm volatile("mma.sync.aligned.m16n8k16.row.col.f32.f16.f16.f32 "
                 "{%0,%1,%2,%3},{%4,%5,%6,%7},{%8,%9},{%0,%1,%2,%3};"
                 : "+f"(c[0]), "+f"(c[1]), "+f"(c[2]), "+f"(c[3])
                 : "r"(a[0]), "r"(a[1]), "r"(a[2]), "r"(a[3]), "r"(b[0]), "r"(b[1]));
}
__device__ __forceinline__ float ex2f(float x) {
    float y; asm("ex2.approx.f32 %0, %1;" : "=f"(y) : "f"(x)); return y;
}
__device__ __forceinline__ uint32_t h2ex2(float a, float b) {
    __half2 hin = __floats2half2_rn(a, b);
    uint32_t in = *(uint32_t*)&hin, out;
    asm("ex2.approx.f16x2 %0, %1;" : "=r"(out) : "r"(in));
    return out;
}

// ---------------- prep kernels ---------------------------------------------------
// one launch for x, c, and the 4 weights (grid segments)
__global__ void prep_split(
    const float* __restrict__ x,  const float* __restrict__ c,
    const float* __restrict__ w0, const float* __restrict__ w1,
    const float* __restrict__ w2, const float* __restrict__ w3,
    __half* __restrict__ xh, __half* __restrict__ ch,
    __half* __restrict__ d0, __half* __restrict__ d1,
    __half* __restrict__ d2, __half* __restrict__ d3)
{
    const float* s; __half* d; int i;
    int blk = blockIdx.x;
    if (blk < 4096)      { s = x;  d = xh; i = (blk * 256 + threadIdx.x) * 4; }
    else if (blk < 8192) { s = c;  d = ch; i = ((blk - 4096) * 256 + threadIdx.x) * 4; }
    else {
        int wb = blk - 8192;
        int which = wb >> 8;
        s = which == 0 ? w0 : which == 1 ? w1 : which == 2 ? w2 : w3;
        d = which == 0 ? d0 : which == 1 ? d1 : which == 2 ? d2 : d3;
        i = ((wb & 255) * 256 + threadIdx.x) * 4;
    }
    float4 v = *(const float4*)(s + i);
    *(__half2*)(d + i)     = __halves2half2(__float2half_rn(v.x), __float2half_rn(v.y));
    *(__half2*)(d + i + 2) = __halves2half2(__float2half_rn(v.z), __float2half_rn(v.w));
}

// pack mask to bits; dtype detected per-block from its own 8 KB of raw bytes
__global__ void mask_to_bits(const void* __restrict__ mp, uint32_t* __restrict__ o) {
    // local dtype detection (random 0/1 data -> certain within 8 KB)
    bool hi = false, f3 = false;
    const unsigned char* mb8 = (const unsigned char*)mp + (size_t)blockIdx.x * 8192;
    for (int i = threadIdx.x; i < 8192; i += 256) {
        unsigned char v = mb8[i];
        int p = i & 3;
        if (p == 3 && v == 0x3f) f3 = true;
        if (p != 0 && v != 0)    hi = true;
    }
    int a3 = __syncthreads_or(f3 ? 1 : 0);
    int ah = __syncthreads_or(hi ? 1 : 0);
    int mode = a3 ? 2 : (ah ? 0 : 1);

    size_t w = (size_t)blockIdx.x * blockDim.x + threadIdx.x;
    size_t base = w * 32;
    uint32_t bits = 0;
    if (mode == 0) {
        const uchar4* p = (const uchar4*)((const unsigned char*)mp + base);
#pragma unroll
        for (int q = 0; q < 8; q++) {
            uchar4 v = p[q];
            bits |= ((uint32_t)(v.x != 0) << (q * 4))
                  | ((uint32_t)(v.y != 0) << (q * 4 + 1))
                  | ((uint32_t)(v.z != 0) << (q * 4 + 2))
                  | ((uint32_t)(v.w != 0) << (q * 4 + 3));
        }
    } else if (mode == 1) {
        const int4* p = (const int4*)((const int*)mp + base);
#pragma unroll
        for (int q = 0; q < 8; q++) {
            int4 v = p[q];
            bits |= ((uint32_t)(v.x != 0) << (q * 4))
                  | ((uint32_t)(v.y != 0) << (q * 4 + 1))
                  | ((uint32_t)(v.z != 0) << (q * 4 + 2))
                  | ((uint32_t)(v.w != 0) << (q * 4 + 3));
        }
    } else {
        const float4* p = (const float4*)((const float*)mp + base);
#pragma unroll
        for (int q = 0; q < 8; q++) {
            float4 v = p[q];
            bits |= ((uint32_t)(v.x != 0.f) << (q * 4))
                  | ((uint32_t)(v.y != 0.f) << (q * 4 + 1))
                  | ((uint32_t)(v.z != 0.f) << (q * 4 + 2))
                  | ((uint32_t)(v.w != 0.f) << (q * 4 + 3));
        }
    }
    o[w] = bits;
}

// ---------------- GEMM: Y = A @ W^T (unchanged from R16) ---------------------------
#define GKT 32
#define GSH 40
#define GSZ (128 * GSH)
#define GEMM_SMEM_BYTES (2 * 4 * GSZ * 2)

template <int TERMS>
__global__ __launch_bounds__(256, 2) void gemm_mma(
    const __half* __restrict__ Ah0, const __half* __restrict__ Al0,
    const __half* __restrict__ Ah1,
    const __half* __restrict__ Wh,  const __half* __restrict__ Wh2,
    const __half* __restrict__ Wh3,
    float* __restrict__ outF, __half* __restrict__ outH, __half* __restrict__ outH2,
    __half* __restrict__ outH3,
    int MrowsPerB, int modeIn, int modeOut)
{
    extern __shared__ __half gs[];
    const int tid = threadIdx.x, lane = tid & 31, w = tid >> 5;
    const int wm = w >> 2, wn = w & 3;
    const int m0 = blockIdx.y * 128;
    const int seg = blockIdx.x >> 2;
    const int n0 = (blockIdx.x & 3) * 128;
    const __half* Wsel = seg == 0 ? Wh : seg == 1 ? Wh2 : Wh3;
    __half* outSel = seg == 0 ? outH : seg == 1 ? outH2 : outH3;
    if (seg == 2) {
        MrowsPerB = NT; modeIn = 0;
        if (m0 >= Bc * NT) return;
    }
    const int lrow = tid >> 2;
    const int lch  = (tid & 3) * 8;

    const __half *arh[2], *arl[2], *brh[2];
#pragma unroll
    for (int p = 0; p < 2; p++) {
        int r = lrow + p * 64, gm = m0 + r;
        int bb = gm / MrowsPerB, mm = gm - bb * MrowsPerB;
        if (modeIn == 0 || mm < NT) {
            size_t off = ((size_t)bb * NT + mm) * Cdim;
            arh[p] = Ah0 + off;
            arl[p] = (TERMS >= 2) ? (Al0 + off) : nullptr;
        } else {
            size_t off = ((size_t)bb * NT + (mm - NT)) * Cdim;
            arh[p] = Ah1 + off;
            arl[p] = nullptr;
        }
        brh[p] = Wsel + (size_t)(n0 + r) * Cdim;
    }

    float acc[4][4][4];
#pragma unroll
    for (int a = 0; a < 4; a++)
#pragma unroll
        for (int b2 = 0; b2 < 4; b2++)
#pragma unroll
            for (int q = 0; q < 4; q++) acc[a][b2][q] = 0.f;

    const int arlr = wm * 64 + (lane & 15);
    const int acs  = (lane >> 4) * 8;
    const int bq    = wn * 32 + (lane & 7);
    const int bksel = ((lane >> 3) & 1) * 8;
    const int bnsel = ((lane >> 4) & 1) * 8;

    auto loadStage = [&](int st, int k0) {
        __half* b = gs + st * 4 * GSZ;
        const uint32_t d0 = (uint32_t)(lrow * GSH + lch);
#pragma unroll
        for (int p = 0; p < 2; p++) {
            uint32_t d = d0 + p * 64 * GSH;
            cpa16(smaddr(b + d),           arh[p] + k0 + lch);
            if (TERMS >= 2)
                cpa16(smaddr(b + GSZ + d), arl[p] + k0 + lch);
            cpa16(smaddr(b + 2 * GSZ + d), brh[p] + k0 + lch);
        }
    };

    loadStage(0, 0); cpcommit();
    const int NTILES = Cdim / GKT;
    for (int t = 0; t < NTILES; t++) {
        cpwait0(); __syncthreads();
        if (t + 1 < NTILES) { loadStage((t + 1) & 1, (t + 1) * GKT); cpcommit(); }

        __half* Ash = gs + (t & 1) * 4 * GSZ;
        __half* Asl = Ash + GSZ;
        __half* Bsh = Ash + 2 * GSZ;
#pragma unroll
        for (int ks = 0; ks < 2; ks++) {
            const int kcA = ks * 16 + acs, kcB = ks * 16 + bksel;
            uint32_t ah[4][4], al[4][4];
#pragma unroll
            for (int mt = 0; mt < 4; mt++) {
                ldmx4(smaddr(&Ash[(arlr + mt * 16) * GSH + kcA]), ah[mt]);
                if (TERMS >= 2)
                    ldmx4(smaddr(&Asl[(arlr + mt * 16) * GSH + kcA]), al[mt]);
            }
#pragma unroll
            for (int nt = 0; nt < 4; nt += 2) {
                uint32_t bh[4];
                ldmx4(smaddr(&Bsh[(bq + nt * 8 + bnsel) * GSH + kcB]), bh);
#pragma unroll
                for (int mt = 0; mt < 4; mt++)
                    mma16816(acc[mt][nt], ah[mt], bh);
#pragma unroll
                for (int mt = 0; mt < 4; mt++)
                    mma16816(acc[mt][nt + 1], ah[mt], bh + 2);
                if (TERMS >= 2) {
#pragma unroll
                    for (int mt = 0; mt < 4; mt++)
                        mma16816(acc[mt][nt], al[mt], bh);
#pragma unroll
                    for (int mt = 0; mt < 4; mt++)
                        mma16816(acc[mt][nt + 1], al[mt], bh + 2);
                }
            }
        }
    }

    const int er = m0 + wm * 64 + (lane >> 2);
    const int ec = n0 + wn * 32 + 2 * (lane & 3);
#pragma unroll
    for (int mt = 0; mt < 4; mt++)
#pragma unroll
        for (int nt = 0; nt < 4; nt++) {
            int col = ec + nt * 8;
#pragma unroll
            for (int hf = 0; hf < 2; hf++) {
                int   row = er + mt * 16 + hf * 8;
                float v0 = acc[mt][nt][hf * 2], v1 = acc[mt][nt][hf * 2 + 1];
                if (modeOut == 0) {
                    int bb = row / MrowsPerB, mm = row - bb * MrowsPerB;
                    int hh = col >> 6, dd = col & 63;
                    size_t p = (((size_t)(bb * Hh + hh)) * MrowsPerB + mm) * Dh + dd;
                    *(__half2*)(outSel + p) =
                        __halves2half2(__float2half_rn(v0), __float2half_rn(v1));
                } else {
                    *(float2*)(outF + (size_t)row * Cdim + col) = make_float2(v0, v1);
                }
            }
        }
}

// ---------------- Flash attention v9: register-resident P --------------------------
// The exp'd half2 pairs ARE the PV A-fragments (C-frag layout of the S-mma matches
// the A-frag layout of the PV-mma) -> P never touches smem.
#define QSTR 72
#define KSTR 72
#define QSZ  (64 * QSTR)
#define KSZ  (128 * KSTR)
#define MBSZ (64 * 16)
#define ATT_SMEM_BYTES ((QSZ + 4 * KSZ) * 2 + 2 * MBSZ)

__global__ __launch_bounds__(128, 2) void attn_mma(
    const __half* __restrict__ qhg, const __half* __restrict__ khg,
    const __half* __restrict__ vhg, const uint32_t* __restrict__ mbits,
    __half* __restrict__ yh, __half* __restrict__ yl)
{
    extern __shared__ __half sh[];
    __half* Qh = sh;
    __half* Kb = sh + QSZ;
    __half* Vb = sh + QSZ + 2 * KSZ;
    unsigned char* Mb = (unsigned char*)(sh + QSZ + 4 * KSZ);

    const int tid = threadIdx.x, lane = tid & 31, w = tid >> 5;
    const int b = blockIdx.z, h = blockIdx.y, qt = blockIdx.x;

    const size_t kvo = ((size_t)(b * Hh + h)) * NKT * Dh;
    const unsigned char* mgb =
        (const unsigned char*)mbits + ((size_t)b * NT + (size_t)qt * 64) * (NKT / 8);

    auto loadStage = [&](int kt, int st) {
        __half* Khp = Kb + st * KSZ;
        __half* Vhp = Vb + st * KSZ;
#pragma unroll
        for (int i = 0; i < 8; i++) {
            int pos = tid + i * 128;
            int r = pos >> 3, cc = (pos & 7) * 8;
            size_t go = kvo + (size_t)(kt * 128 + r) * Dh + cc;
            uint32_t so = r * KSTR + cc;
            cpa16(smaddr(Khp + so), khg + go);
            cpa16(smaddr(Vhp + so), vhg + go);
        }
        if (tid < 64)
            cpa16(smaddr(Mb + st * MBSZ + tid * 16),
                  mgb + (size_t)tid * (NKT / 8) + kt * 16);
    };

    {
        const size_t qo = (((size_t)(b * Hh + h)) * NT + qt * 64) * Dh;
#pragma unroll
        for (int i = 0; i < 4; i++) {
            int pos = tid + i * 128;
            int r = pos >> 3, cc = (pos & 7) * 8;
            cpa16(smaddr(Qh + r * QSTR + cc), qhg + qo + r * Dh + cc);
        }
        loadStage(0, 0);
        cpcommit();
    }
    cpwait0(); __syncthreads();

    uint32_t qf[4][4];
    {
        const int rl = w * 16 + (lane & 15);
        const int cs = (lane >> 4) * 8;
#pragma unroll
        for (int kc = 0; kc < 4; kc++)
            ldmx4(smaddr(&Qh[rl * QSTR + kc * 16 + cs]), qf[kc]);
    }

    float oacc[8][4];
#pragma unroll
    for (int nt = 0; nt < 8; nt++)
#pragma unroll
        for (int q = 0; q < 4; q++) oacc[nt][q] = 0.f;
    float m_reg[2] = {-1e30f, -1e30f};
    float l_reg[2] = {0.f, 0.f};

    const int rg  = lane >> 2;
    const int mr0 = w * 16 + rg;
    const int mr1 = mr0 + 8;
    const int ql2 = (lane & 3) * 2;
    const float SCL = 0.125f * 1.44269504f;

    const int kq    = lane & 7;
    const int kksel = ((lane >> 3) & 1) * 8;
    const int knsel = ((lane >> 4) & 1) * 8;
    const int vr    = lane & 15;
    const int vnsel = ((lane >> 4) & 1) * 8;

    for (int kt = 0; kt < NKT / 128; kt++) {
        const int st = kt & 1;
        if (kt > 0) { cpwait0(); __syncthreads(); }
        if (kt + 1 < NKT / 128) { loadStage(kt + 1, st ^ 1); cpcommit(); }

        __half* Khp = Kb + st * KSZ;
        __half* Vhp = Vb + st * KSZ;
        const uint32_t* M32 = (const uint32_t*)(Mb + st * MBSZ);

        // --- S = Qh Kh^T ---
        float sacc[16][4];
#pragma unroll
        for (int nt = 0; nt < 16; nt++)
#pragma unroll
            for (int q = 0; q < 4; q++) sacc[nt][q] = 0.f;
#pragma unroll
        for (int kc = 0; kc < 4; kc++) {
#pragma unroll
            for (int nt = 0; nt < 16; nt += 2) {
                uint32_t bh[4];
                ldmx4(smaddr(&Khp[(kq + nt * 8 + knsel) * KSTR + kc * 16 + kksel]), bh);
                mma16816(sacc[nt],     qf[kc], bh);
                mma16816(sacc[nt + 1], qf[kc], bh + 2);
            }
        }

        // --- mask + scale, register row max ---
        uint32_t mw0[4], mw1[4];
#pragma unroll
        for (int q = 0; q < 4; q++) {
            mw0[q] = M32[mr0 * 4 + q];
            mw1[q] = M32[mr1 * 4 + q];
        }
        float rm0 = -1e30f, rm1 = -1e30f;
#pragma unroll
        for (int nt = 0; nt < 16; nt++) {
            const int bit = (nt & 3) * 8 + ql2;
            uint32_t w0 = mw0[nt >> 2], w1 = mw1[nt >> 2];
            sacc[nt][0] = ((w0 >> bit) & 1)       ? -1e30f : sacc[nt][0] * SCL;
            sacc[nt][1] = ((w0 >> (bit + 1)) & 1) ? -1e30f : sacc[nt][1] * SCL;
            sacc[nt][2] = ((w1 >> bit) & 1)       ? -1e30f : sacc[nt][2] * SCL;
            sacc[nt][3] = ((w1 >> (bit + 1)) & 1) ? -1e30f : sacc[nt][3] * SCL;
            rm0 = fmaxf(rm0, fmaxf(sacc[nt][0], sacc[nt][1]));
            rm1 = fmaxf(rm1, fmaxf(sacc[nt][2], sacc[nt][3]));
        }
        rm0 = fmaxf(rm0, __shfl_xor_sync(0xffffffffu, rm0, 1));
        rm0 = fmaxf(rm0, __shfl_xor_sync(0xffffffffu, rm0, 2));
        rm1 = fmaxf(rm1, __shfl_xor_sync(0xffffffffu, rm1, 1));
        rm1 = fmaxf(rm1, __shfl_xor_sync(0xffffffffu, rm1, 2));
        float mn0 = fmaxf(m_reg[0], rm0);
        float mn1 = fmaxf(m_reg[1], rm1);
        float cf0 = ex2f(m_reg[0] - mn0);
        float cf1 = ex2f(m_reg[1] - mn1);

        // --- exp (fp16x2) directly into PV A-fragments (registers), row sum ---
        uint32_t pf[8][4];
        float rs0 = 0.f, rs1 = 0.f;
#pragma unroll
        for (int nt = 0; nt < 16; nt++) {
            uint32_t p0 = h2ex2(sacc[nt][0] - mn0, sacc[nt][1] - mn0);
            uint32_t p1 = h2ex2(sacc[nt][2] - mn1, sacc[nt][3] - mn1);
            pf[nt >> 1][(nt & 1) * 2]     = p0;
            pf[nt >> 1][(nt & 1) * 2 + 1] = p1;
            float2 f0 = __half22float2(*(__half2*)&p0);
            float2 f1 = __half22float2(*(__half2*)&p1);
            rs0 += f0.x + f0.y;
            rs1 += f1.x + f1.y;
        }
        rs0 += __shfl_xor_sync(0xffffffffu, rs0, 1);
        rs0 += __shfl_xor_sync(0xffffffffu, rs0, 2);
        rs1 += __shfl_xor_sync(0xffffffffu, rs1, 1);
        rs1 += __shfl_xor_sync(0xffffffffu, rs1, 2);
        l_reg[0] = l_reg[0] * cf0 + rs0;
        l_reg[1] = l_reg[1] * cf1 + rs1;
        m_reg[0] = mn0; m_reg[1] = mn1;

#pragma unroll
        for (int nt = 0; nt < 8; nt++) {
            oacc[nt][0] *= cf0; oacc[nt][1] *= cf0;
            oacc[nt][2] *= cf1; oacc[nt][3] *= cf1;
        }

        // --- O += P Vh : P from registers, V via ldmx4t (2 n-tiles/load) ---
#pragma unroll
        for (int kc = 0; kc < 8; kc++) {
#pragma unroll
            for (int nt = 0; nt < 8; nt += 2) {
                uint32_t vh[4];
                ldmx4t(smaddr(&Vhp[(kc * 16 + vr) * KSTR + nt * 8 + vnsel]), vh);
                mma16816(oacc[nt],     pf[kc], vh);
                mma16816(oacc[nt + 1], pf[kc], vh + 2);
            }
        }
    }

    // --- epilogue ---
    {
        float i0 = (l_reg[0] > 0.f) ? 1.f / l_reg[0] : 0.f;
        float i1 = (l_reg[1] > 0.f) ? 1.f / l_reg[1] : 0.f;
        const int c0 = h * 64 + ql2;
        size_t o0 = ((size_t)b * NT + qt * 64 + mr0) * Cdim + c0;
        size_t o1 = ((size_t)b * NT + qt * 64 + mr1) * Cdim + c0;
#pragma unroll
        for (int nt = 0; nt < 8; nt++) {
            float a0 = oacc[nt][0] * i0, a1 = oacc[nt][1] * i0;
            float b0 = oacc[nt][2] * i1, b1 = oacc[nt][3] * i1;
            __half ha0 = __float2half_rn(a0), ha1 = __float2half_rn(a1);
            __half hb0 = __float2half_rn(b0), hb1 = __float2half_rn(b1);
            *(__half2*)(yh + o0 + nt * 8) = __halves2half2(ha0, ha1);
            *(__half2*)(yl + o0 + nt * 8) = __halves2half2(
                __float2half_rn(a0 - __half2float(ha0)),
                __float2half_rn(a1 - __half2float(ha1)));
            *(__half2*)(yh + o1 + nt * 8) = __halves2half2(hb0, hb1);
            *(__half2*)(yl + o1 + nt * 8) = __halves2half2(
                __float2half_rn(b0 - __half2float(hb0)),
                __float2half_rn(b1 - __half2float(hb1)));
        }
    }
}

// ---------------- launch ------------------------------------------------------------
extern "C" void kernel_launch(void* const* d_in, const int* in_sizes, int n_in,
                              void* d_out, int out_size)
{
    const float* x  = (const float*)d_in[0];
    const float* c  = (const float*)d_in[1];
    const void*  mk = d_in[2];
    const float* Wq = (const float*)d_in[3];
    const float* Wk = (const float*)d_in[4];
    const float* Wv = (const float*)d_in[5];
    const float* Wp = (const float*)d_in[6];
    float* out = (float*)d_out;

    __half *xh, *ch_, *wqh, *wkh, *wvh, *wph;
    __half *qh, *kh, *vh, *yh, *yl;
    uint32_t* mb;
    cudaGetSymbolAddress((void**)&xh,  g_xh);
    cudaGetSymbolAddress((void**)&ch_, g_ch);
    cudaGetSymbolAddress((void**)&wqh, g_wqh);
    cudaGetSymbolAddress((void**)&wkh, g_wkh);
    cudaGetSymbolAddress((void**)&wvh, g_wvh);
    cudaGetSymbolAddress((void**)&wph, g_wph);
    cudaGetSymbolAddress((void**)&qh,  g_qh);
    cudaGetSymbolAddress((void**)&kh,  g_kh);
    cudaGetSymbolAddress((void**)&vh,  g_vh);
    cudaGetSymbolAddress((void**)&yh,  g_yh);  cudaGetSymbolAddress((void**)&yl,  g_yl);
    cudaGetSymbolAddress((void**)&mb,  g_mbits);

    cudaFuncSetAttribute(gemm_mma<2>, cudaFuncAttributeMaxDynamicSharedMemorySize,
                         GEMM_SMEM_BYTES);
    cudaFuncSetAttribute(gemm_mma<1>, cudaFuncAttributeMaxDynamicSharedMemorySize,
                         GEMM_SMEM_BYTES);
    cudaFuncSetAttribute(attn_mma, cudaFuncAttributeMaxDynamicSharedMemorySize,
                         ATT_SMEM_BYTES);

    mask_to_bits<<<(Bc * NT * NKT / 32) / 256, 256>>>(mk, mb);
    prep_split<<<8192 + 1024, 256>>>(x, c, Wq, Wk, Wv, Wp,
                                     xh, ch_, wqh, wkh, wvh, wph);

    // Fused K + V + Q projection (segments on blockIdx.x)
    gemm_mma<1><<<dim3(3 * Cdim / 128, Bc * NKT / 128), 256, GEMM_SMEM_BYTES>>>(
        xh, nullptr, ch_, wkh, wvh, wqh,
        nullptr, kh, vh, qh, NKT, 1, 0);

    attn_mma<<<dim3(NT / 64, Hh, Bc), 128, ATT_SMEM_BYTES>>>(
        qh, kh, vh, mb, yh, yl);

    // output projection: 2-term (y hi+lo, Wp fp16)
    gemm_mma<2><<<dim3(Cdim / 128, Bc * NT / 128), 256, GEMM_SMEM_BYTES>>>(
        yh, yl, nullptr, wph, nullptr, nullptr,
        out, nullptr, nullptr, nullptr, NT, 0, 1);
}